// round 1
// baseline (speedup 1.0000x reference)
#include <cuda_runtime.h>
#include <math.h>

constexpr int B = 4, S = 2048, D = 1024, H = 16, HD = 64;
constexpr int NR = B * S;  // 8192 rows

// ---------------- scratch (static device globals; no allocation) -------------
__device__ float g_Q[(size_t)NR * D];
__device__ float g_K[(size_t)NR * D];
__device__ float g_V[(size_t)NR * D];
__device__ float g_C[(size_t)NR * D];
__device__ float g_Y[(size_t)NR * D];

// ---------------- GEMM: C[n,m] = sum_k A[n,k] * W[m,k] + bias[m] (+R[n,m]) ---
// 128x128 tile, BK=8, 256 threads, 8x8 microtile.
__global__ __launch_bounds__(256) void gemm_kernel(
    const float* __restrict__ A, const float* __restrict__ W,
    const float* __restrict__ bias, const float* __restrict__ R,
    float* __restrict__ C, int N, int M, int K)
{
    __shared__ float As[8][128];
    __shared__ float Bs[8][128];

    const int m0 = blockIdx.x * 128;
    const int n0 = blockIdx.y * 128;
    const int tid = threadIdx.x;
    const int tx = tid & 15;        // M microtile index
    const int ty = tid >> 4;        // N microtile index
    const int lrow = tid >> 1;      // 0..127 row within tile for loads
    const int lk = (tid & 1) * 4;   // 0 or 4 within BK

    const float* Ag = A + (size_t)(n0 + lrow) * K + lk;
    const float* Wg = W + (size_t)(m0 + lrow) * K + lk;

    float acc[8][8];
#pragma unroll
    for (int i = 0; i < 8; i++)
#pragma unroll
        for (int j = 0; j < 8; j++) acc[i][j] = 0.f;

    for (int k0 = 0; k0 < K; k0 += 8) {
        float4 av = *(const float4*)(Ag + k0);
        float4 wv = *(const float4*)(Wg + k0);
        __syncthreads();
        As[lk + 0][lrow] = av.x; As[lk + 1][lrow] = av.y;
        As[lk + 2][lrow] = av.z; As[lk + 3][lrow] = av.w;
        Bs[lk + 0][lrow] = wv.x; Bs[lk + 1][lrow] = wv.y;
        Bs[lk + 2][lrow] = wv.z; Bs[lk + 3][lrow] = wv.w;
        __syncthreads();
#pragma unroll
        for (int kk = 0; kk < 8; kk++) {
            float a[8], b[8];
            *(float4*)(a)     = *(const float4*)&As[kk][ty * 8];
            *(float4*)(a + 4) = *(const float4*)&As[kk][ty * 8 + 4];
            *(float4*)(b)     = *(const float4*)&Bs[kk][tx * 8];
            *(float4*)(b + 4) = *(const float4*)&Bs[kk][tx * 8 + 4];
#pragma unroll
            for (int i = 0; i < 8; i++)
#pragma unroll
                for (int j = 0; j < 8; j++)
                    acc[i][j] = fmaf(a[i], b[j], acc[i][j]);
        }
    }

#pragma unroll
    for (int i = 0; i < 8; i++) {
        const int n = n0 + ty * 8 + i;
#pragma unroll
        for (int j = 0; j < 8; j++) {
            const int m = m0 + tx * 8 + j;
            float v = acc[i][j] + bias[m];
            if (R) v += R[(size_t)n * M + m];
            C[(size_t)n * M + m] = v;
        }
    }
}

// ---------------- Flash attention (fp32, online softmax) --------------------
// grid (S/64, H, B), 256 threads. 64-row Q tile, 64-row K/V tiles.
// SMEM (dynamic): Qs/Ks/Vs/Ps each 64x65 floats + 64 ints of mask.
constexpr int AT_STRIDE = 65;
constexpr int AT_SMEM_BYTES = (4 * 64 * AT_STRIDE) * 4 + 64 * 4;

__global__ __launch_bounds__(256) void attn_kernel(
    const float* __restrict__ Q, const float* __restrict__ K,
    const float* __restrict__ V, const int* __restrict__ mask,
    float* __restrict__ O)
{
    extern __shared__ float sm[];
    float* Qs = sm;
    float* Ks = Qs + 64 * AT_STRIDE;
    float* Vs = Ks + 64 * AT_STRIDE;
    float* Ps = Vs + 64 * AT_STRIDE;
    int*   ms = (int*)(Ps + 64 * AT_STRIDE);

    const int b = blockIdx.z, h = blockIdx.y, q0 = blockIdx.x * 64;
    const int tid = threadIdx.x;
    const int tx = tid & 15, ty = tid >> 4;

    // Load Q tile
    {
        const int r = tid >> 2, c0 = (tid & 3) * 16;
        const float* qg = Q + ((size_t)(b * S + q0 + r)) * D + h * HD + c0;
#pragma unroll
        for (int j = 0; j < 16; j += 4) {
            float4 v = *(const float4*)(qg + j);
            Qs[r * AT_STRIDE + c0 + j + 0] = v.x;
            Qs[r * AT_STRIDE + c0 + j + 1] = v.y;
            Qs[r * AT_STRIDE + c0 + j + 2] = v.z;
            Qs[r * AT_STRIDE + c0 + j + 3] = v.w;
        }
    }

    float acc[4][4];
    float mr[4], lr[4];
#pragma unroll
    for (int i = 0; i < 4; i++) {
        mr[i] = -1e30f; lr[i] = 0.f;
#pragma unroll
        for (int j = 0; j < 4; j++) acc[i][j] = 0.f;
    }
    const float scale = 0.125f;  // 1/sqrt(64)

    for (int k0 = 0; k0 < S; k0 += 64) {
        __syncthreads();  // prior-tile Ps/Vs reads done before overwrite
        {
            const int r = tid >> 2, c0 = (tid & 3) * 16;
            const float* kg = K + ((size_t)(b * S + k0 + r)) * D + h * HD + c0;
            const float* vg = V + ((size_t)(b * S + k0 + r)) * D + h * HD + c0;
#pragma unroll
            for (int j = 0; j < 16; j += 4) {
                float4 kv = *(const float4*)(kg + j);
                float4 vv = *(const float4*)(vg + j);
                Ks[r * AT_STRIDE + c0 + j + 0] = kv.x;
                Ks[r * AT_STRIDE + c0 + j + 1] = kv.y;
                Ks[r * AT_STRIDE + c0 + j + 2] = kv.z;
                Ks[r * AT_STRIDE + c0 + j + 3] = kv.w;
                Vs[r * AT_STRIDE + c0 + j + 0] = vv.x;
                Vs[r * AT_STRIDE + c0 + j + 1] = vv.y;
                Vs[r * AT_STRIDE + c0 + j + 2] = vv.z;
                Vs[r * AT_STRIDE + c0 + j + 3] = vv.w;
            }
            if (tid < 64) ms[tid] = mask[b * S + k0 + tid];
        }
        __syncthreads();

        // S = Q K^T for the 4x4 microtile
        float sv[4][4];
#pragma unroll
        for (int i = 0; i < 4; i++)
#pragma unroll
            for (int j = 0; j < 4; j++) sv[i][j] = 0.f;

#pragma unroll 4
        for (int d = 0; d < HD; d++) {
            float qv[4], kv[4];
#pragma unroll
            for (int i = 0; i < 4; i++) qv[i] = Qs[(ty * 4 + i) * AT_STRIDE + d];
#pragma unroll
            for (int j = 0; j < 4; j++) kv[j] = Ks[(tx * 4 + j) * AT_STRIDE + d];
#pragma unroll
            for (int i = 0; i < 4; i++)
#pragma unroll
                for (int j = 0; j < 4; j++)
                    sv[i][j] = fmaf(qv[i], kv[j], sv[i][j]);
        }

        // scale + mask
        int mk[4];
#pragma unroll
        for (int j = 0; j < 4; j++) mk[j] = ms[tx * 4 + j];
#pragma unroll
        for (int i = 0; i < 4; i++)
#pragma unroll
            for (int j = 0; j < 4; j++)
                sv[i][j] = (mk[j] == 0) ? -1e9f : sv[i][j] * scale;

        // online softmax update
        float p[4][4];
#pragma unroll
        for (int i = 0; i < 4; i++) {
            float tm = fmaxf(fmaxf(sv[i][0], sv[i][1]), fmaxf(sv[i][2], sv[i][3]));
#pragma unroll
            for (int o = 1; o < 16; o <<= 1)
                tm = fmaxf(tm, __shfl_xor_sync(0xffffffffu, tm, o));
            const float mn = fmaxf(mr[i], tm);
            const float cf = __expf(mr[i] - mn);
            mr[i] = mn;
            float rs = 0.f;
#pragma unroll
            for (int j = 0; j < 4; j++) {
                p[i][j] = __expf(sv[i][j] - mn);
                rs += p[i][j];
            }
#pragma unroll
            for (int o = 1; o < 16; o <<= 1)
                rs += __shfl_xor_sync(0xffffffffu, rs, o);
            lr[i] = lr[i] * cf + rs;
#pragma unroll
            for (int j = 0; j < 4; j++) acc[i][j] *= cf;
        }

        // stage P
#pragma unroll
        for (int i = 0; i < 4; i++)
#pragma unroll
            for (int j = 0; j < 4; j++)
                Ps[(ty * 4 + i) * AT_STRIDE + tx * 4 + j] = p[i][j];
        __syncthreads();

        // acc += P V
#pragma unroll 4
        for (int c = 0; c < 64; c++) {
            float pv[4], vv[4];
#pragma unroll
            for (int i = 0; i < 4; i++) pv[i] = Ps[(ty * 4 + i) * AT_STRIDE + c];
#pragma unroll
            for (int j = 0; j < 4; j++) vv[j] = Vs[c * AT_STRIDE + tx * 4 + j];
#pragma unroll
            for (int i = 0; i < 4; i++)
#pragma unroll
                for (int j = 0; j < 4; j++)
                    acc[i][j] = fmaf(pv[i], vv[j], acc[i][j]);
        }
    }

    // epilogue: O = acc / l
#pragma unroll
    for (int i = 0; i < 4; i++) {
        const float inv = 1.0f / lr[i];
        float* og = O + ((size_t)(b * S + q0 + ty * 4 + i)) * D + h * HD;
#pragma unroll
        for (int j = 0; j < 4; j++)
            og[tx * 4 + j] = acc[i][j] * inv;
    }
}

// ---------------- LayerNorm over D, one block per row ------------------------
__global__ __launch_bounds__(256) void ln_kernel(
    const float* __restrict__ Y, const float* __restrict__ gamma,
    const float* __restrict__ beta, float* __restrict__ out)
{
    __shared__ float r1[256], r2[256];
    const int row = blockIdx.x;
    const int tid = threadIdx.x;
    const float* y = Y + (size_t)row * D;

    float s = 0.f, s2 = 0.f;
    for (int i = tid; i < D; i += 256) {
        const float v = y[i];
        s += v;
        s2 = fmaf(v, v, s2);
    }
    r1[tid] = s; r2[tid] = s2;
    __syncthreads();
    for (int o = 128; o > 0; o >>= 1) {
        if (tid < o) { r1[tid] += r1[tid + o]; r2[tid] += r2[tid + o]; }
        __syncthreads();
    }
    const float mu = r1[0] * (1.0f / D);
    const float var = r2[0] * (1.0f / D) - mu * mu;
    const float inv = rsqrtf(var + 1e-5f);

    float* o = out + (size_t)row * D;
    for (int i = tid; i < D; i += 256)
        o[i] = (y[i] - mu) * inv * gamma[i] + beta[i];
}

// ---------------- launch ------------------------------------------------------
extern "C" void kernel_launch(void* const* d_in, const int* in_sizes, int n_in,
                              void* d_out, int out_size)
{
    const float* x     = (const float*)d_in[0];
    const int*   mask  = (const int*)d_in[1];
    const float* Wq    = (const float*)d_in[2];
    const float* bq    = (const float*)d_in[3];
    const float* Wk    = (const float*)d_in[4];
    const float* bk    = (const float*)d_in[5];
    const float* Wv    = (const float*)d_in[6];
    const float* bv    = (const float*)d_in[7];
    const float* Wo    = (const float*)d_in[8];
    const float* bo    = (const float*)d_in[9];
    const float* gamma = (const float*)d_in[10];
    const float* beta  = (const float*)d_in[11];

    float *Qp, *Kp, *Vp, *Cp, *Yp;
    cudaGetSymbolAddress((void**)&Qp, g_Q);
    cudaGetSymbolAddress((void**)&Kp, g_K);
    cudaGetSymbolAddress((void**)&Vp, g_V);
    cudaGetSymbolAddress((void**)&Cp, g_C);
    cudaGetSymbolAddress((void**)&Yp, g_Y);

    dim3 gg(D / 128, NR / 128);  // (8, 64)
    gemm_kernel<<<gg, 256>>>(x, Wq, bq, nullptr, Qp, NR, D, D);
    gemm_kernel<<<gg, 256>>>(x, Wk, bk, nullptr, Kp, NR, D, D);
    gemm_kernel<<<gg, 256>>>(x, Wv, bv, nullptr, Vp, NR, D, D);

    cudaFuncSetAttribute(attn_kernel,
                         cudaFuncAttributeMaxDynamicSharedMemorySize,
                         AT_SMEM_BYTES);
    attn_kernel<<<dim3(S / 64, H, B), 256, AT_SMEM_BYTES>>>(Qp, Kp, Vp, mask, Cp);

    gemm_kernel<<<gg, 256>>>(Cp, Wo, bo, x, Yp, NR, D, D);
    ln_kernel<<<NR, 256>>>(Yp, gamma, beta, (float*)d_out);
}

// round 3
// speedup vs baseline: 3.1452x; 3.1452x over previous
#include <cuda_runtime.h>
#include <cstdint>
#include <math.h>

constexpr int B = 4, S = 2048, D = 1024, H = 16, HD = 64;
constexpr int NR = B * S;  // 8192 rows

// ---------------- scratch (static device globals; no allocation) -------------
__device__ float g_Q[(size_t)NR * D];
__device__ float g_K[(size_t)NR * D];
__device__ float g_V[(size_t)NR * D];
__device__ float g_C[(size_t)NR * D];
__device__ float g_Y[(size_t)NR * D];

// ======================= helpers ============================================
__device__ __forceinline__ uint32_t smem_u32(const void* p) {
    uint32_t a;
    asm("{ .reg .u64 t; cvta.to.shared.u64 t, %1; cvt.u32.u64 %0, t; }"
        : "=r"(a) : "l"(p));
    return a;
}
__device__ __forceinline__ uint32_t f2tf32(float f) {
    uint32_t u;
    asm("cvt.rna.tf32.f32 %0, %1;" : "=r"(u) : "f"(f));
    return u;
}
__device__ __forceinline__ void ldsm4(uint32_t& r0, uint32_t& r1, uint32_t& r2,
                                      uint32_t& r3, uint32_t addr) {
    asm volatile("ldmatrix.sync.aligned.m8n8.x4.shared.b16 {%0,%1,%2,%3}, [%4];"
                 : "=r"(r0), "=r"(r1), "=r"(r2), "=r"(r3) : "r"(addr));
}
__device__ __forceinline__ void mma8(float (&c)[4], const uint32_t (&a)[4],
                                     uint32_t b0, uint32_t b1) {
    asm volatile(
        "mma.sync.aligned.m16n8k8.row.col.f32.tf32.tf32.f32 "
        "{%0,%1,%2,%3}, {%4,%5,%6,%7}, {%8,%9}, {%0,%1,%2,%3};"
        : "+f"(c[0]), "+f"(c[1]), "+f"(c[2]), "+f"(c[3])
        : "r"(a[0]), "r"(a[1]), "r"(a[2]), "r"(a[3]), "r"(b0), "r"(b1));
}

// ======================= tf32 mma GEMM ======================================
// C[n, m] = sum_k A[n, k] * W[m, k] + bias[m] (+ R[n, m])
// Block tile 128(n) x 128(m), K chunks of 32. 8 warps, warp tile 64x32.
constexpr int GST = 36;                 // smem row stride (floats)
constexpr int G_STAGE = 256 * GST;      // uints per stage (A rows 0..127, B 128..255)
constexpr int GEMM_SMEM = 2 * G_STAGE * 4;  // 73728 B

__global__ __launch_bounds__(256) void gemm_mma(
    const float* __restrict__ A, const float* __restrict__ W,
    const float* __restrict__ bias, const float* __restrict__ R,
    float* __restrict__ C)
{
    extern __shared__ uint32_t gsm[];
    const int tid = threadIdx.x;
    const int lane = tid & 31, wid = tid >> 5;
    const int m0 = blockIdx.x * 128, n0 = blockIdx.y * 128;
    const int wr = wid >> 2, wc = wid & 3;   // warp row (0..1), warp col (0..3)
    const int lrow = lane & 15;
    const int lcol = (lane >> 4) * 4;
    const uint32_t sbase = smem_u32(gsm);

    float4 rv[8];
    float acc[4][4][4];
#pragma unroll
    for (int mt = 0; mt < 4; mt++)
#pragma unroll
        for (int nt = 0; nt < 4; nt++)
#pragma unroll
            for (int q = 0; q < 4; q++) acc[mt][nt][q] = 0.f;

    auto ldg_chunk = [&](int c) {
        const int k0 = c * 32;
#pragma unroll
        for (int i = 0; i < 8; i++) {
            const int idx = tid + i * 256;
            const int t = idx & 1023;
            const int row = t >> 3, c4 = (t & 7) * 4;
            const float* g = (idx < 1024 ? A + (size_t)(n0 + row) * D
                                         : W + (size_t)(m0 + row) * D) + k0 + c4;
            rv[i] = *(const float4*)g;
        }
    };
    auto sts_chunk = [&](int stage) {
        uint32_t* base = gsm + stage * G_STAGE;
#pragma unroll
        for (int i = 0; i < 8; i++) {
            const int idx = tid + i * 256;
            const int t = idx & 1023;
            const int row = (t >> 3) + (idx < 1024 ? 0 : 128);
            const int c4 = (t & 7) * 4;
            uint4 u;
            u.x = f2tf32(rv[i].x); u.y = f2tf32(rv[i].y);
            u.z = f2tf32(rv[i].z); u.w = f2tf32(rv[i].w);
            *(uint4*)(base + row * GST + c4) = u;
        }
    };

    ldg_chunk(0);
    for (int c = 0; c < 32; c++) {
        const int stage = c & 1;
        sts_chunk(stage);
        __syncthreads();
        if (c < 31) ldg_chunk(c + 1);

        const uint32_t stb = sbase + stage * G_STAGE * 4;
#pragma unroll
        for (int k = 0; k < 4; k++) {
            uint32_t a[4][4];
            uint32_t bfr[4][2];
#pragma unroll
            for (int mt = 0; mt < 4; mt++) {
                const uint32_t addr =
                    stb + ((wr * 64 + mt * 16 + lrow) * GST + k * 8 + lcol) * 4;
                ldsm4(a[mt][0], a[mt][1], a[mt][2], a[mt][3], addr);
            }
#pragma unroll
            for (int np = 0; np < 2; np++) {
                const uint32_t addr =
                    stb + ((128 + wc * 32 + np * 16 + lrow) * GST + k * 8 + lcol) * 4;
                uint32_t b0, b1, b2, b3;
                ldsm4(b0, b1, b2, b3, addr);
                bfr[np * 2 + 0][0] = b0; bfr[np * 2 + 1][0] = b1;
                bfr[np * 2 + 0][1] = b2; bfr[np * 2 + 1][1] = b3;
            }
#pragma unroll
            for (int mt = 0; mt < 4; mt++)
#pragma unroll
                for (int nt = 0; nt < 4; nt++)
                    mma8(acc[mt][nt], a[mt], bfr[nt][0], bfr[nt][1]);
        }
        __syncthreads();
    }

    // epilogue
    const int g = lane >> 2, cc = lane & 3;
#pragma unroll
    for (int mt = 0; mt < 4; mt++) {
#pragma unroll
        for (int hf = 0; hf < 2; hf++) {
            const int row = n0 + wr * 64 + mt * 16 + g + hf * 8;
#pragma unroll
            for (int nt = 0; nt < 4; nt++) {
                const int col = m0 + wc * 32 + nt * 8 + cc * 2;
                float2 bv = *(const float2*)(bias + col);
                float2 o;
                o.x = acc[mt][nt][hf * 2 + 0] + bv.x;
                o.y = acc[mt][nt][hf * 2 + 1] + bv.y;
                if (R) {
                    float2 rvv = *(const float2*)(R + (size_t)row * D + col);
                    o.x += rvv.x; o.y += rvv.y;
                }
                *(float2*)(C + (size_t)row * D + col) = o;
            }
        }
    }
}

// ======================= tf32 mma flash attention ===========================
// Block: 256 q rows, 8 warps x 32 rows. 64-key tiles. HD = 64.
constexpr int AST = 68;
constexpr int AQ_OFF = 0;
constexpr int AK_OFF = 256 * AST;                 // 17408
constexpr int AV_OFF = AK_OFF + 64 * AST;         // Vt[d][tok]
constexpr int AP_OFF = AV_OFF + 64 * AST;
constexpr int AM_OFF = AP_OFF + 256 * AST;        // 64 mask ints
constexpr int ATT_SMEM = (AM_OFF + 64) * 4;       // 174336 B

__global__ __launch_bounds__(256) void attn_mma(
    const float* __restrict__ Q, const float* __restrict__ K,
    const float* __restrict__ V, const int* __restrict__ mask,
    float* __restrict__ O)
{
    extern __shared__ uint32_t smx[];
    const int tid = threadIdx.x, lane = tid & 31, wid = tid >> 5;
    const int b = blockIdx.z, h = blockIdx.y, q0 = blockIdx.x * 256;
    const uint32_t sb = smem_u32(smx);
    const int lrow = lane & 15;
    const int lcol = (lane >> 4) * 4;
    const int g = lane >> 2, cc = lane & 3;
    const int qb = wid * 32;
    const float scale = 0.125f;  // 1/sqrt(64)

    // load Q tile (256 x 64), cvt to tf32
#pragma unroll
    for (int i = 0; i < 16; i++) {
        const int idx = tid + i * 256;
        const int row = idx >> 4, c4 = (idx & 15) * 4;
        float4 v = *(const float4*)(Q + (size_t)(b * S + q0 + row) * D + h * HD + c4);
        uint4 u;
        u.x = f2tf32(v.x); u.y = f2tf32(v.y); u.z = f2tf32(v.z); u.w = f2tf32(v.w);
        *(uint4*)(smx + AQ_OFF + row * AST + c4) = u;
    }

    float ob[2][8][4];
#pragma unroll
    for (int mt = 0; mt < 2; mt++)
#pragma unroll
        for (int nt = 0; nt < 8; nt++)
#pragma unroll
            for (int q = 0; q < 4; q++) ob[mt][nt][q] = 0.f;
    float mst[4], lst[4];
#pragma unroll
    for (int i = 0; i < 4; i++) { mst[i] = -1e30f; lst[i] = 0.f; }

    for (int t = 0; t < S / 64; t++) {
        const int k0 = t * 64;
        __syncthreads();  // prior PV reads of Ks/Vt/Ps complete

        // K tile (64 x 64)
#pragma unroll
        for (int i = 0; i < 4; i++) {
            const int idx = tid + i * 256;
            const int row = idx >> 4, c4 = (idx & 15) * 4;
            float4 v = *(const float4*)(K + (size_t)(b * S + k0 + row) * D + h * HD + c4);
            uint4 u;
            u.x = f2tf32(v.x); u.y = f2tf32(v.y); u.z = f2tf32(v.z); u.w = f2tf32(v.w);
            *(uint4*)(smx + AK_OFF + row * AST + c4) = u;
        }
        // V tile transposed: Vt[d][tok]
        {
            const int tok_l = tid & 15;
            const int d0 = (tid >> 4) * 4;
#pragma unroll
            for (int p = 0; p < 4; p++) {
                const int tok = tok_l + p * 16;
                float4 v = *(const float4*)(V + (size_t)(b * S + k0 + tok) * D + h * HD + d0);
                smx[AV_OFF + (d0 + 0) * AST + tok] = f2tf32(v.x);
                smx[AV_OFF + (d0 + 1) * AST + tok] = f2tf32(v.y);
                smx[AV_OFF + (d0 + 2) * AST + tok] = f2tf32(v.z);
                smx[AV_OFF + (d0 + 3) * AST + tok] = f2tf32(v.w);
            }
        }
        if (tid < 64) smx[AM_OFF + tid] = (uint32_t)mask[b * S + k0 + tid];
        __syncthreads();

        // ---- S = Q K^T ----
        float sc[2][8][4];
#pragma unroll
        for (int mt = 0; mt < 2; mt++)
#pragma unroll
            for (int nt = 0; nt < 8; nt++)
#pragma unroll
                for (int q = 0; q < 4; q++) sc[mt][nt][q] = 0.f;

#pragma unroll
        for (int k = 0; k < 8; k++) {
            uint32_t a[2][4], bfr[8][2];
#pragma unroll
            for (int mt = 0; mt < 2; mt++) {
                const uint32_t addr =
                    sb + (AQ_OFF + (qb + mt * 16 + lrow) * AST + k * 8 + lcol) * 4;
                ldsm4(a[mt][0], a[mt][1], a[mt][2], a[mt][3], addr);
            }
#pragma unroll
            for (int np = 0; np < 4; np++) {
                const uint32_t addr =
                    sb + (AK_OFF + (np * 16 + lrow) * AST + k * 8 + lcol) * 4;
                uint32_t b0, b1, b2, b3;
                ldsm4(b0, b1, b2, b3, addr);
                bfr[np * 2 + 0][0] = b0; bfr[np * 2 + 1][0] = b1;
                bfr[np * 2 + 0][1] = b2; bfr[np * 2 + 1][1] = b3;
            }
#pragma unroll
            for (int mt = 0; mt < 2; mt++)
#pragma unroll
                for (int nt = 0; nt < 8; nt++)
                    mma8(sc[mt][nt], a[mt], bfr[nt][0], bfr[nt][1]);
        }

        // mask addends (same cols for both mt / both row halves)
        float madd[8][2];
#pragma unroll
        for (int nt = 0; nt < 8; nt++) {
            const int c0 = nt * 8 + cc * 2;
            madd[nt][0] = smx[AM_OFF + c0] ? 0.f : -1e9f;
            madd[nt][1] = smx[AM_OFF + c0 + 1] ? 0.f : -1e9f;
        }

        // ---- online softmax ----
#pragma unroll
        for (int mt = 0; mt < 2; mt++) {
#pragma unroll
            for (int hf = 0; hf < 2; hf++) {
                const int si = mt * 2 + hf;
                float rm = -1e30f;
#pragma unroll
                for (int nt = 0; nt < 8; nt++) {
                    float v0 = fmaf(sc[mt][nt][hf * 2 + 0], scale, madd[nt][0]);
                    float v1 = fmaf(sc[mt][nt][hf * 2 + 1], scale, madd[nt][1]);
                    sc[mt][nt][hf * 2 + 0] = v0;
                    sc[mt][nt][hf * 2 + 1] = v1;
                    rm = fmaxf(rm, fmaxf(v0, v1));
                }
                rm = fmaxf(rm, __shfl_xor_sync(0xffffffffu, rm, 1));
                rm = fmaxf(rm, __shfl_xor_sync(0xffffffffu, rm, 2));
                const float mnew = fmaxf(mst[si], rm);
                const float cf = __expf(mst[si] - mnew);
                mst[si] = mnew;
                float rs = 0.f;
#pragma unroll
                for (int nt = 0; nt < 8; nt++) {
                    float p0 = __expf(sc[mt][nt][hf * 2 + 0] - mnew);
                    float p1 = __expf(sc[mt][nt][hf * 2 + 1] - mnew);
                    sc[mt][nt][hf * 2 + 0] = p0;
                    sc[mt][nt][hf * 2 + 1] = p1;
                    rs += p0 + p1;
                }
                rs += __shfl_xor_sync(0xffffffffu, rs, 1);
                rs += __shfl_xor_sync(0xffffffffu, rs, 2);
                lst[si] = lst[si] * cf + rs;
#pragma unroll
                for (int nt = 0; nt < 8; nt++) {
                    ob[mt][nt][hf * 2 + 0] *= cf;
                    ob[mt][nt][hf * 2 + 1] *= cf;
                }
            }
        }

        // stage P (tf32)
#pragma unroll
        for (int mt = 0; mt < 2; mt++)
#pragma unroll
            for (int nt = 0; nt < 8; nt++) {
                const int r0 = qb + mt * 16 + g;
                const int cp = nt * 8 + cc * 2;
                uint2 u0, u1;
                u0.x = f2tf32(sc[mt][nt][0]); u0.y = f2tf32(sc[mt][nt][1]);
                u1.x = f2tf32(sc[mt][nt][2]); u1.y = f2tf32(sc[mt][nt][3]);
                *(uint2*)(smx + AP_OFF + r0 * AST + cp) = u0;
                *(uint2*)(smx + AP_OFF + (r0 + 8) * AST + cp) = u1;
            }
        __syncthreads();

        // ---- O += P V ----
#pragma unroll
        for (int k = 0; k < 8; k++) {
            uint32_t a[2][4], bfr[8][2];
#pragma unroll
            for (int mt = 0; mt < 2; mt++) {
                const uint32_t addr =
                    sb + (AP_OFF + (qb + mt * 16 + lrow) * AST + k * 8 + lcol) * 4;
                ldsm4(a[mt][0], a[mt][1], a[mt][2], a[mt][3], addr);
            }
#pragma unroll
            for (int np = 0; np < 4; np++) {
                const uint32_t addr =
                    sb + (AV_OFF + (np * 16 + lrow) * AST + k * 8 + lcol) * 4;
                uint32_t b0, b1, b2, b3;
                ldsm4(b0, b1, b2, b3, addr);
                bfr[np * 2 + 0][0] = b0; bfr[np * 2 + 1][0] = b1;
                bfr[np * 2 + 0][1] = b2; bfr[np * 2 + 1][1] = b3;
            }
#pragma unroll
            for (int mt = 0; mt < 2; mt++)
#pragma unroll
                for (int nt = 0; nt < 8; nt++)
                    mma8(ob[mt][nt], a[mt], bfr[nt][0], bfr[nt][1]);
        }
    }

    // epilogue: O = ob / l
#pragma unroll
    for (int mt = 0; mt < 2; mt++)
#pragma unroll
        for (int hf = 0; hf < 2; hf++) {
            const float inv = 1.0f / lst[mt * 2 + hf];
            const int row = q0 + qb + mt * 16 + g + hf * 8;
#pragma unroll
            for (int nt = 0; nt < 8; nt++) {
                const int col = h * HD + nt * 8 + cc * 2;
                float2 o;
                o.x = ob[mt][nt][hf * 2 + 0] * inv;
                o.y = ob[mt][nt][hf * 2 + 1] * inv;
                *(float2*)(O + (size_t)(b * S + row) * D + col) = o;
            }
        }
}

// ---------------- LayerNorm over D, one block per row ------------------------
__global__ __launch_bounds__(256) void ln_kernel(
    const float* __restrict__ Y, const float* __restrict__ gamma,
    const float* __restrict__ beta, float* __restrict__ out)
{
    __shared__ float r1[256], r2[256];
    const int row = blockIdx.x;
    const int tid = threadIdx.x;
    const float* y = Y + (size_t)row * D;

    float s = 0.f, s2 = 0.f;
    for (int i = tid; i < D; i += 256) {
        const float v = y[i];
        s += v;
        s2 = fmaf(v, v, s2);
    }
    r1[tid] = s; r2[tid] = s2;
    __syncthreads();
    for (int o = 128; o > 0; o >>= 1) {
        if (tid < o) { r1[tid] += r1[tid + o]; r2[tid] += r2[tid + o]; }
        __syncthreads();
    }
    const float mu = r1[0] * (1.0f / D);
    const float var = r2[0] * (1.0f / D) - mu * mu;
    const float inv = rsqrtf(var + 1e-5f);

    float* o = out + (size_t)row * D;
    for (int i = tid; i < D; i += 256)
        o[i] = (y[i] - mu) * inv * gamma[i] + beta[i];
}

// ---------------- launch ------------------------------------------------------
extern "C" void kernel_launch(void* const* d_in, const int* in_sizes, int n_in,
                              void* d_out, int out_size)
{
    const float* x     = (const float*)d_in[0];
    const int*   mask  = (const int*)d_in[1];
    const float* Wq    = (const float*)d_in[2];
    const float* bq    = (const float*)d_in[3];
    const float* Wk    = (const float*)d_in[4];
    const float* bk    = (const float*)d_in[5];
    const float* Wv    = (const float*)d_in[6];
    const float* bv    = (const float*)d_in[7];
    const float* Wo    = (const float*)d_in[8];
    const float* bo    = (const float*)d_in[9];
    const float* gamma = (const float*)d_in[10];
    const float* beta  = (const float*)d_in[11];

    float *Qp, *Kp, *Vp, *Cp, *Yp;
    cudaGetSymbolAddress((void**)&Qp, g_Q);
    cudaGetSymbolAddress((void**)&Kp, g_K);
    cudaGetSymbolAddress((void**)&Vp, g_V);
    cudaGetSymbolAddress((void**)&Cp, g_C);
    cudaGetSymbolAddress((void**)&Yp, g_Y);

    cudaFuncSetAttribute(gemm_mma, cudaFuncAttributeMaxDynamicSharedMemorySize,
                         GEMM_SMEM);
    cudaFuncSetAttribute(attn_mma, cudaFuncAttributeMaxDynamicSharedMemorySize,
                         ATT_SMEM);

    dim3 gg(D / 128, NR / 128);  // (8, 64)
    gemm_mma<<<gg, 256, GEMM_SMEM>>>(x, Wq, bq, nullptr, Qp);
    gemm_mma<<<gg, 256, GEMM_SMEM>>>(x, Wk, bk, nullptr, Kp);
    gemm_mma<<<gg, 256, GEMM_SMEM>>>(x, Wv, bv, nullptr, Vp);

    attn_mma<<<dim3(S / 256, H, B), 256, ATT_SMEM>>>(Qp, Kp, Vp, mask, Cp);

    gemm_mma<<<gg, 256, GEMM_SMEM>>>(Cp, Wo, bo, x, Yp);
    ln_kernel<<<NR, 256>>>(Yp, gamma, beta, (float*)d_out);
}

// round 4
// speedup vs baseline: 3.5600x; 1.1319x over previous
#include <cuda_runtime.h>
#include <cstdint>
#include <math.h>

constexpr int B = 4, S = 2048, D = 1024, H = 16, HD = 64;
constexpr int NR = B * S;  // 8192 rows

// ---------------- scratch (static device globals; no allocation) -------------
__device__ float    g_Q[(size_t)NR * D];
__device__ float    g_K[(size_t)NR * D];
__device__ float    g_V[(size_t)NR * D];
__device__ float    g_C[(size_t)NR * D];
__device__ float    g_Y[(size_t)NR * D];
__device__ uint32_t g_Xc[(size_t)NR * D];       // x in tf32 bits
__device__ uint32_t g_Wc[(size_t)4 * D * D];    // Wq,Wk,Wv,Wo in tf32 bits
__device__ uint32_t g_Cc[(size_t)NR * D];       // attention output in tf32 bits

// ======================= helpers ============================================
__device__ __forceinline__ uint32_t smem_u32(const void* p) {
    uint32_t a;
    asm("{ .reg .u64 t; cvta.to.shared.u64 t, %1; cvt.u32.u64 %0, t; }"
        : "=r"(a) : "l"(p));
    return a;
}
__device__ __forceinline__ uint32_t f2tf32(float f) {
    uint32_t u;
    asm("cvt.rna.tf32.f32 %0, %1;" : "=r"(u) : "f"(f));
    return u;
}
__device__ __forceinline__ void ldsm4(uint32_t& r0, uint32_t& r1, uint32_t& r2,
                                      uint32_t& r3, uint32_t addr) {
    asm volatile("ldmatrix.sync.aligned.m8n8.x4.shared.b16 {%0,%1,%2,%3}, [%4];"
                 : "=r"(r0), "=r"(r1), "=r"(r2), "=r"(r3) : "r"(addr));
}
__device__ __forceinline__ void mma8(float (&c)[4], const uint32_t (&a)[4],
                                     uint32_t b0, uint32_t b1) {
    asm volatile(
        "mma.sync.aligned.m16n8k8.row.col.f32.tf32.tf32.f32 "
        "{%0,%1,%2,%3}, {%4,%5,%6,%7}, {%8,%9}, {%0,%1,%2,%3};"
        : "+f"(c[0]), "+f"(c[1]), "+f"(c[2]), "+f"(c[3])
        : "r"(a[0]), "r"(a[1]), "r"(a[2]), "r"(a[3]), "r"(b0), "r"(b1));
}
__device__ __forceinline__ void cp_async16(uint32_t s, const void* g) {
    asm volatile("cp.async.cg.shared.global [%0], [%1], 16;" :: "r"(s), "l"(g));
}
__device__ __forceinline__ void cp_commit() {
    asm volatile("cp.async.commit_group;" ::: "memory");
}
template <int N>
__device__ __forceinline__ void cp_wait() {
    asm volatile("cp.async.wait_group %0;" :: "n"(N) : "memory");
}

// ======================= tf32 prep (fp32 -> tf32 bits) =======================
__global__ __launch_bounds__(256) void cvt_tf32(const float* __restrict__ in,
                                                uint32_t* __restrict__ out,
                                                int n4)
{
    const int i = (blockIdx.x * 256 + threadIdx.x) * 4;
    if (i < n4 * 4) {
        float4 v = *(const float4*)(in + i);
        uint4 u;
        u.x = f2tf32(v.x); u.y = f2tf32(v.y); u.z = f2tf32(v.z); u.w = f2tf32(v.w);
        *(uint4*)(out + i) = u;
    }
}

// ======================= tf32 mma GEMM (operands pre-converted) ==============
// C[n, m] = sum_k A[n, k] * W[m, k] + bias[m] (+ R[n, m])
// Block tile 128(n) x 128(m), K chunks of 32. 8 warps, warp tile 64x32.
constexpr int GST = 36;                 // smem row stride (uints)
constexpr int G_STAGE = 256 * GST;      // uints per stage
constexpr int GEMM_SMEM = 2 * G_STAGE * 4;  // 73728 B

__global__ __launch_bounds__(256, 2) void gemm_mma(
    const uint32_t* __restrict__ A, const uint32_t* __restrict__ W,
    const float* __restrict__ bias, const float* __restrict__ R,
    float* __restrict__ C)
{
    extern __shared__ uint32_t gsm[];
    const int tid = threadIdx.x;
    const int lane = tid & 31, wid = tid >> 5;
    const int m0 = blockIdx.x * 128, n0 = blockIdx.y * 128;
    const int wr = wid >> 2, wc = wid & 3;
    const int lrow = lane & 15;
    const int lcol = (lane >> 4) * 4;
    const uint32_t sbase = smem_u32(gsm);

    float acc[4][4][4];
#pragma unroll
    for (int mt = 0; mt < 4; mt++)
#pragma unroll
        for (int nt = 0; nt < 4; nt++)
#pragma unroll
            for (int q = 0; q < 4; q++) acc[mt][nt][q] = 0.f;

    auto issue_chunk = [&](int c) {
        const int k0 = c * 32;
        const uint32_t stb = sbase + (c & 1) * G_STAGE * 4;
#pragma unroll
        for (int i = 0; i < 8; i++) {
            const int idx = tid + i * 256;
            const int t = idx & 1023;
            const int row = t >> 3, c4 = (t & 7) * 4;
            const uint32_t* g =
                (idx < 1024 ? A + (size_t)(n0 + row) * D
                            : W + (size_t)(m0 + row) * D) + k0 + c4;
            const int srow = row + (idx < 1024 ? 0 : 128);
            cp_async16(stb + (srow * GST + c4) * 4, g);
        }
        cp_commit();
    };

    issue_chunk(0);
    for (int c = 0; c < 32; c++) {
        if (c < 31) issue_chunk(c + 1);
        if (c < 31) cp_wait<1>(); else cp_wait<0>();
        __syncthreads();

        const uint32_t stb = sbase + (c & 1) * G_STAGE * 4;
#pragma unroll
        for (int k = 0; k < 4; k++) {
            uint32_t a[4][4];
            uint32_t bfr[4][2];
#pragma unroll
            for (int mt = 0; mt < 4; mt++) {
                const uint32_t addr =
                    stb + ((wr * 64 + mt * 16 + lrow) * GST + k * 8 + lcol) * 4;
                ldsm4(a[mt][0], a[mt][1], a[mt][2], a[mt][3], addr);
            }
#pragma unroll
            for (int np = 0; np < 2; np++) {
                const uint32_t addr =
                    stb + ((128 + wc * 32 + np * 16 + lrow) * GST + k * 8 + lcol) * 4;
                uint32_t b0, b1, b2, b3;
                ldsm4(b0, b1, b2, b3, addr);
                bfr[np * 2 + 0][0] = b0; bfr[np * 2 + 1][0] = b1;
                bfr[np * 2 + 0][1] = b2; bfr[np * 2 + 1][1] = b3;
            }
#pragma unroll
            for (int mt = 0; mt < 4; mt++)
#pragma unroll
                for (int nt = 0; nt < 4; nt++)
                    mma8(acc[mt][nt], a[mt], bfr[nt][0], bfr[nt][1]);
        }
        __syncthreads();
    }

    // epilogue
    const int g = lane >> 2, cc = lane & 3;
#pragma unroll
    for (int mt = 0; mt < 4; mt++) {
#pragma unroll
        for (int hf = 0; hf < 2; hf++) {
            const int row = n0 + wr * 64 + mt * 16 + g + hf * 8;
#pragma unroll
            for (int nt = 0; nt < 4; nt++) {
                const int col = m0 + wc * 32 + nt * 8 + cc * 2;
                float2 bv = *(const float2*)(bias + col);
                float2 o;
                o.x = acc[mt][nt][hf * 2 + 0] + bv.x;
                o.y = acc[mt][nt][hf * 2 + 1] + bv.y;
                if (R) {
                    float2 rvv = *(const float2*)(R + (size_t)row * D + col);
                    o.x += rvv.x; o.y += rvv.y;
                }
                *(float2*)(C + (size_t)row * D + col) = o;
            }
        }
    }
}

// ======================= tf32 mma flash attention ===========================
// Block: 256 q rows, 16 warps x 16 rows. 64-key tiles. HD = 64.
constexpr int AST = 68;
constexpr int AQ_OFF = 0;
constexpr int AK_OFF = 256 * AST;
constexpr int AV_OFF = AK_OFF + 64 * AST;          // Vt[d][tok]
constexpr int AP_OFF = AV_OFF + 64 * AST;
constexpr int AM_OFF = AP_OFF + 256 * AST;         // 64 mask ints
constexpr int ATT_SMEM = (AM_OFF + 64) * 4;        // 174336 B

__global__ __launch_bounds__(512) void attn_mma(
    const float* __restrict__ Q, const float* __restrict__ K,
    const float* __restrict__ V, const int* __restrict__ mask,
    float* __restrict__ O)
{
    extern __shared__ uint32_t smx[];
    const int tid = threadIdx.x, lane = tid & 31, wid = tid >> 5;
    const int b = blockIdx.z, h = blockIdx.y, q0 = blockIdx.x * 256;
    const uint32_t sb = smem_u32(smx);
    const int lrow = lane & 15;
    const int lcol = (lane >> 4) * 4;
    const int g = lane >> 2, cc = lane & 3;
    const int qb = wid * 16;
    const float scale = 0.125f;  // 1/sqrt(64)

    // load Q tile (256 x 64), cvt to tf32
#pragma unroll
    for (int i = 0; i < 8; i++) {
        const int idx = tid + i * 512;
        const int row = idx >> 4, c4 = (idx & 15) * 4;
        float4 v = *(const float4*)(Q + (size_t)(b * S + q0 + row) * D + h * HD + c4);
        uint4 u;
        u.x = f2tf32(v.x); u.y = f2tf32(v.y); u.z = f2tf32(v.z); u.w = f2tf32(v.w);
        *(uint4*)(smx + AQ_OFF + row * AST + c4) = u;
    }

    float ob[8][4];
#pragma unroll
    for (int nt = 0; nt < 8; nt++)
#pragma unroll
        for (int q = 0; q < 4; q++) ob[nt][q] = 0.f;
    float mst[2], lst[2];
    mst[0] = mst[1] = -1e30f;
    lst[0] = lst[1] = 0.f;

    for (int t = 0; t < S / 64; t++) {
        const int k0 = t * 64;
        __syncthreads();  // prior PV reads of Ks/Vt/Ps complete

        // K tile (64 x 64)
#pragma unroll
        for (int i = 0; i < 2; i++) {
            const int idx = tid + i * 512;
            const int row = idx >> 4, c4 = (idx & 15) * 4;
            float4 v = *(const float4*)(K + (size_t)(b * S + k0 + row) * D + h * HD + c4);
            uint4 u;
            u.x = f2tf32(v.x); u.y = f2tf32(v.y); u.z = f2tf32(v.z); u.w = f2tf32(v.w);
            *(uint4*)(smx + AK_OFF + row * AST + c4) = u;
        }
        // V tile transposed: Vt[d][tok]
        {
            const int tok = tid & 63;
            const int d0 = (tid >> 6) * 4;
#pragma unroll
            for (int p = 0; p < 2; p++) {
                const int d = d0 + p * 32;
                float4 v = *(const float4*)(V + (size_t)(b * S + k0 + tok) * D + h * HD + d);
                smx[AV_OFF + (d + 0) * AST + tok] = f2tf32(v.x);
                smx[AV_OFF + (d + 1) * AST + tok] = f2tf32(v.y);
                smx[AV_OFF + (d + 2) * AST + tok] = f2tf32(v.z);
                smx[AV_OFF + (d + 3) * AST + tok] = f2tf32(v.w);
            }
        }
        if (tid < 64) smx[AM_OFF + tid] = (uint32_t)mask[b * S + k0 + tid];
        __syncthreads();

        // ---- S = Q K^T ----
        float sc[8][4];
#pragma unroll
        for (int nt = 0; nt < 8; nt++)
#pragma unroll
            for (int q = 0; q < 4; q++) sc[nt][q] = 0.f;

#pragma unroll
        for (int k = 0; k < 8; k++) {
            uint32_t a[4], bfr[8][2];
            {
                const uint32_t addr =
                    sb + (AQ_OFF + (qb + lrow) * AST + k * 8 + lcol) * 4;
                ldsm4(a[0], a[1], a[2], a[3], addr);
            }
#pragma unroll
            for (int np = 0; np < 4; np++) {
                const uint32_t addr =
                    sb + (AK_OFF + (np * 16 + lrow) * AST + k * 8 + lcol) * 4;
                uint32_t b0, b1, b2, b3;
                ldsm4(b0, b1, b2, b3, addr);
                bfr[np * 2 + 0][0] = b0; bfr[np * 2 + 1][0] = b1;
                bfr[np * 2 + 0][1] = b2; bfr[np * 2 + 1][1] = b3;
            }
#pragma unroll
            for (int nt = 0; nt < 8; nt++)
                mma8(sc[nt], a, bfr[nt][0], bfr[nt][1]);
        }

        // ---- online softmax (per row-half) ----
#pragma unroll
        for (int hf = 0; hf < 2; hf++) {
            float rm = -1e30f;
#pragma unroll
            for (int nt = 0; nt < 8; nt++) {
                const int c0 = nt * 8 + cc * 2;
                const float m0v = smx[AM_OFF + c0] ? 0.f : -1e9f;
                const float m1v = smx[AM_OFF + c0 + 1] ? 0.f : -1e9f;
                float v0 = fmaf(sc[nt][hf * 2 + 0], scale, m0v);
                float v1 = fmaf(sc[nt][hf * 2 + 1], scale, m1v);
                sc[nt][hf * 2 + 0] = v0;
                sc[nt][hf * 2 + 1] = v1;
                rm = fmaxf(rm, fmaxf(v0, v1));
            }
            rm = fmaxf(rm, __shfl_xor_sync(0xffffffffu, rm, 1));
            rm = fmaxf(rm, __shfl_xor_sync(0xffffffffu, rm, 2));
            const float mnew = fmaxf(mst[hf], rm);
            const float cf = __expf(mst[hf] - mnew);
            mst[hf] = mnew;
            float rs = 0.f;
#pragma unroll
            for (int nt = 0; nt < 8; nt++) {
                float p0 = __expf(sc[nt][hf * 2 + 0] - mnew);
                float p1 = __expf(sc[nt][hf * 2 + 1] - mnew);
                sc[nt][hf * 2 + 0] = p0;
                sc[nt][hf * 2 + 1] = p1;
                rs += p0 + p1;
            }
            rs += __shfl_xor_sync(0xffffffffu, rs, 1);
            rs += __shfl_xor_sync(0xffffffffu, rs, 2);
            lst[hf] = lst[hf] * cf + rs;
#pragma unroll
            for (int nt = 0; nt < 8; nt++) {
                ob[nt][hf * 2 + 0] *= cf;
                ob[nt][hf * 2 + 1] *= cf;
            }
        }

        // stage P (tf32) — warp-local rows
#pragma unroll
        for (int nt = 0; nt < 8; nt++) {
            const int r0 = qb + g;
            const int cp = nt * 8 + cc * 2;
            uint2 u0, u1;
            u0.x = f2tf32(sc[nt][0]); u0.y = f2tf32(sc[nt][1]);
            u1.x = f2tf32(sc[nt][2]); u1.y = f2tf32(sc[nt][3]);
            *(uint2*)(smx + AP_OFF + r0 * AST + cp) = u0;
            *(uint2*)(smx + AP_OFF + (r0 + 8) * AST + cp) = u1;
        }
        __syncwarp();

        // ---- O += P V ----
#pragma unroll
        for (int k = 0; k < 8; k++) {
            uint32_t a[4], bfr[8][2];
            {
                const uint32_t addr =
                    sb + (AP_OFF + (qb + lrow) * AST + k * 8 + lcol) * 4;
                ldsm4(a[0], a[1], a[2], a[3], addr);
            }
#pragma unroll
            for (int np = 0; np < 4; np++) {
                const uint32_t addr =
                    sb + (AV_OFF + (np * 16 + lrow) * AST + k * 8 + lcol) * 4;
                uint32_t b0, b1, b2, b3;
                ldsm4(b0, b1, b2, b3, addr);
                bfr[np * 2 + 0][0] = b0; bfr[np * 2 + 1][0] = b1;
                bfr[np * 2 + 0][1] = b2; bfr[np * 2 + 1][1] = b3;
            }
#pragma unroll
            for (int nt = 0; nt < 8; nt++)
                mma8(ob[nt], a, bfr[nt][0], bfr[nt][1]);
        }
    }

    // epilogue: O = ob / l
#pragma unroll
    for (int hf = 0; hf < 2; hf++) {
        const float inv = 1.0f / lst[hf];
        const int row = q0 + qb + g + hf * 8;
#pragma unroll
        for (int nt = 0; nt < 8; nt++) {
            const int col = h * HD + nt * 8 + cc * 2;
            float2 o;
            o.x = ob[nt][hf * 2 + 0] * inv;
            o.y = ob[nt][hf * 2 + 1] * inv;
            *(float2*)(O + (size_t)(b * S + row) * D + col) = o;
        }
    }
}

// ---------------- LayerNorm over D, one block per row ------------------------
__global__ __launch_bounds__(256) void ln_kernel(
    const float* __restrict__ Y, const float* __restrict__ gamma,
    const float* __restrict__ beta, float* __restrict__ out)
{
    __shared__ float r1[256], r2[256];
    const int row = blockIdx.x;
    const int tid = threadIdx.x;
    const float* y = Y + (size_t)row * D;

    float s = 0.f, s2 = 0.f;
    for (int i = tid; i < D; i += 256) {
        const float v = y[i];
        s += v;
        s2 = fmaf(v, v, s2);
    }
    r1[tid] = s; r2[tid] = s2;
    __syncthreads();
    for (int o = 128; o > 0; o >>= 1) {
        if (tid < o) { r1[tid] += r1[tid + o]; r2[tid] += r2[tid + o]; }
        __syncthreads();
    }
    const float mu = r1[0] * (1.0f / D);
    const float var = r2[0] * (1.0f / D) - mu * mu;
    const float inv = rsqrtf(var + 1e-5f);

    float* o = out + (size_t)row * D;
    for (int i = tid; i < D; i += 256)
        o[i] = (y[i] - mu) * inv * gamma[i] + beta[i];
}

// ---------------- launch ------------------------------------------------------
extern "C" void kernel_launch(void* const* d_in, const int* in_sizes, int n_in,
                              void* d_out, int out_size)
{
    const float* x     = (const float*)d_in[0];
    const int*   mask  = (const int*)d_in[1];
    const float* Wq    = (const float*)d_in[2];
    const float* bq    = (const float*)d_in[3];
    const float* Wk    = (const float*)d_in[4];
    const float* bk    = (const float*)d_in[5];
    const float* Wv    = (const float*)d_in[6];
    const float* bv    = (const float*)d_in[7];
    const float* Wo    = (const float*)d_in[8];
    const float* bo    = (const float*)d_in[9];
    const float* gamma = (const float*)d_in[10];
    const float* beta  = (const float*)d_in[11];

    float *Qp, *Kp, *Vp, *Cp, *Yp;
    uint32_t *Xc, *Wc, *Cc;
    cudaGetSymbolAddress((void**)&Qp, g_Q);
    cudaGetSymbolAddress((void**)&Kp, g_K);
    cudaGetSymbolAddress((void**)&Vp, g_V);
    cudaGetSymbolAddress((void**)&Cp, g_C);
    cudaGetSymbolAddress((void**)&Yp, g_Y);
    cudaGetSymbolAddress((void**)&Xc, g_Xc);
    cudaGetSymbolAddress((void**)&Wc, g_Wc);
    cudaGetSymbolAddress((void**)&Cc, g_Cc);

    cudaFuncSetAttribute(gemm_mma, cudaFuncAttributeMaxDynamicSharedMemorySize,
                         GEMM_SMEM);
    cudaFuncSetAttribute(attn_mma, cudaFuncAttributeMaxDynamicSharedMemorySize,
                         ATT_SMEM);

    const int nX4 = NR * D / 4, nW4 = D * D / 4;
    cvt_tf32<<<nX4 / 256, 256>>>(x, Xc, nX4);
    cvt_tf32<<<nW4 / 256, 256>>>(Wq, Wc + (size_t)0 * D * D, nW4);
    cvt_tf32<<<nW4 / 256, 256>>>(Wk, Wc + (size_t)1 * D * D, nW4);
    cvt_tf32<<<nW4 / 256, 256>>>(Wv, Wc + (size_t)2 * D * D, nW4);
    cvt_tf32<<<nW4 / 256, 256>>>(Wo, Wc + (size_t)3 * D * D, nW4);

    dim3 gg(D / 128, NR / 128);  // (8, 64)
    gemm_mma<<<gg, 256, GEMM_SMEM>>>(Xc, Wc + (size_t)0 * D * D, bq, nullptr, Qp);
    gemm_mma<<<gg, 256, GEMM_SMEM>>>(Xc, Wc + (size_t)1 * D * D, bk, nullptr, Kp);
    gemm_mma<<<gg, 256, GEMM_SMEM>>>(Xc, Wc + (size_t)2 * D * D, bv, nullptr, Vp);

    attn_mma<<<dim3(S / 256, H, B), 512, ATT_SMEM>>>(Qp, Kp, Vp, mask, Cp);

    cvt_tf32<<<nX4 / 256, 256>>>(Cp, Cc, nX4);
    gemm_mma<<<gg, 256, GEMM_SMEM>>>(Cc, Wc + (size_t)3 * D * D, bo, x, Yp);
    ln_kernel<<<NR, 256>>>(Yp, gamma, beta, (float*)d_out);
}

// round 5
// speedup vs baseline: 5.9488x; 1.6710x over previous
#include <cuda_runtime.h>
#include <cuda_bf16.h>
#include <cstdint>
#include <math.h>

constexpr int B = 4, S = 2048, D = 1024, H = 16, HD = 64;
constexpr int NR = B * S;  // 8192 rows

// ---------------- scratch (static device globals; no allocation) -------------
__device__ __nv_bfloat16 g_Xb[(size_t)NR * D];      // x bf16
__device__ __nv_bfloat16 g_Wb[(size_t)4 * D * D];   // Wq,Wk,Wv,Wo bf16
__device__ __nv_bfloat16 g_Qb[(size_t)NR * D];
__device__ __nv_bfloat16 g_Kb[(size_t)NR * D];
__device__ __nv_bfloat16 g_Vb[(size_t)NR * D];
__device__ __nv_bfloat16 g_Cb[(size_t)NR * D];      // attention out bf16
__device__ float         g_Y[(size_t)NR * D];

// ======================= helpers ============================================
__device__ __forceinline__ uint32_t smem_u32(const void* p) {
    uint32_t a;
    asm("{ .reg .u64 t; cvta.to.shared.u64 t, %1; cvt.u32.u64 %0, t; }"
        : "=r"(a) : "l"(p));
    return a;
}
__device__ __forceinline__ void ldsm4(uint32_t& r0, uint32_t& r1, uint32_t& r2,
                                      uint32_t& r3, uint32_t addr) {
    asm volatile("ldmatrix.sync.aligned.m8n8.x4.shared.b16 {%0,%1,%2,%3}, [%4];"
                 : "=r"(r0), "=r"(r1), "=r"(r2), "=r"(r3) : "r"(addr));
}
__device__ __forceinline__ void mma16(float (&c)[4], const uint32_t (&a)[4],
                                      uint32_t b0, uint32_t b1) {
    asm volatile(
        "mma.sync.aligned.m16n8k16.row.col.f32.bf16.bf16.f32 "
        "{%0,%1,%2,%3}, {%4,%5,%6,%7}, {%8,%9}, {%0,%1,%2,%3};"
        : "+f"(c[0]), "+f"(c[1]), "+f"(c[2]), "+f"(c[3])
        : "r"(a[0]), "r"(a[1]), "r"(a[2]), "r"(a[3]), "r"(b0), "r"(b1));
}
__device__ __forceinline__ void cp_async16(uint32_t s, const void* g) {
    asm volatile("cp.async.cg.shared.global [%0], [%1], 16;" :: "r"(s), "l"(g));
}
__device__ __forceinline__ void cp_commit() {
    asm volatile("cp.async.commit_group;" ::: "memory");
}
template <int N>
__device__ __forceinline__ void cp_wait() {
    asm volatile("cp.async.wait_group %0;" :: "n"(N) : "memory");
}

// ======================= fp32 -> bf16 prep ===================================
__global__ __launch_bounds__(256) void cvt_bf16(const float* __restrict__ in,
                                                __nv_bfloat16* __restrict__ out,
                                                int n4)
{
    const int i = (blockIdx.x * 256 + threadIdx.x) * 4;
    if (i < n4 * 4) {
        float4 v = *(const float4*)(in + i);
        __nv_bfloat162 p0 = __floats2bfloat162_rn(v.x, v.y);
        __nv_bfloat162 p1 = __floats2bfloat162_rn(v.z, v.w);
        uint2 u;
        u.x = *(uint32_t*)&p0;
        u.y = *(uint32_t*)&p1;
        *(uint2*)(out + i) = u;
    }
}

// ======================= bf16 mma GEMM ======================================
// C[n, m] = sum_k A[n, k] * W[m, k] + bias[m] (+ R[n, m])
// Block tile 128(n) x 128(m), K chunks of 64 bf16. 8 warps, warp tile 64x32.
constexpr int GST = 72;                 // smem row stride (bf16 elems)
constexpr int G_STAGE = 256 * GST;      // bf16 elems per stage
constexpr int GEMM_SMEM = 2 * G_STAGE * 2;  // 73728 B

template <bool OUT_BF16>
__global__ __launch_bounds__(256, 2) void gemm_bf(
    const __nv_bfloat16* __restrict__ A, const __nv_bfloat16* __restrict__ W,
    const float* __restrict__ bias, const float* __restrict__ R,
    void* __restrict__ Cout)
{
    extern __shared__ __nv_bfloat16 gsm[];
    const int tid = threadIdx.x;
    const int lane = tid & 31, wid = tid >> 5;
    const int m0 = blockIdx.x * 128, n0 = blockIdx.y * 128;
    const int wr = wid >> 2, wc = wid & 3;
    const int lrow = lane & 15;
    const int lcol8 = (lane >> 4) * 8;
    const uint32_t sbase = smem_u32(gsm);

    float acc[4][4][4];
#pragma unroll
    for (int mt = 0; mt < 4; mt++)
#pragma unroll
        for (int nt = 0; nt < 4; nt++)
#pragma unroll
            for (int q = 0; q < 4; q++) acc[mt][nt][q] = 0.f;

    auto issue_chunk = [&](int c) {
        const int k0 = c * 64;
        const uint32_t stb = sbase + (c & 1) * G_STAGE * 2;
#pragma unroll
        for (int i = 0; i < 8; i++) {
            const int idx = tid + i * 256;
            const int t = idx & 1023;
            const int row = t >> 3, c8 = (t & 7) * 8;
            const __nv_bfloat16* g =
                (idx < 1024 ? A + (size_t)(n0 + row) * D
                            : W + (size_t)(m0 + row) * D) + k0 + c8;
            const int srow = row + (idx < 1024 ? 0 : 128);
            cp_async16(stb + (srow * GST + c8) * 2, g);
        }
        cp_commit();
    };

    issue_chunk(0);
    for (int c = 0; c < 16; c++) {
        if (c < 15) issue_chunk(c + 1);
        if (c < 15) cp_wait<1>(); else cp_wait<0>();
        __syncthreads();

        const uint32_t stb = sbase + (c & 1) * G_STAGE * 2;
#pragma unroll
        for (int k = 0; k < 4; k++) {
            uint32_t a[4][4];
            uint32_t bfr[4][2];
#pragma unroll
            for (int mt = 0; mt < 4; mt++) {
                const uint32_t addr =
                    stb + ((wr * 64 + mt * 16 + lrow) * GST + k * 16 + lcol8) * 2;
                ldsm4(a[mt][0], a[mt][1], a[mt][2], a[mt][3], addr);
            }
#pragma unroll
            for (int np = 0; np < 2; np++) {
                const uint32_t addr =
                    stb + ((128 + wc * 32 + np * 16 + lrow) * GST + k * 16 + lcol8) * 2;
                uint32_t b0, b1, b2, b3;
                ldsm4(b0, b1, b2, b3, addr);
                bfr[np * 2 + 0][0] = b0; bfr[np * 2 + 1][0] = b1;
                bfr[np * 2 + 0][1] = b2; bfr[np * 2 + 1][1] = b3;
            }
#pragma unroll
            for (int mt = 0; mt < 4; mt++)
#pragma unroll
                for (int nt = 0; nt < 4; nt++)
                    mma16(acc[mt][nt], a[mt], bfr[nt][0], bfr[nt][1]);
        }
        __syncthreads();
    }

    // epilogue
    const int g = lane >> 2, cc = lane & 3;
#pragma unroll
    for (int mt = 0; mt < 4; mt++) {
#pragma unroll
        for (int hf = 0; hf < 2; hf++) {
            const int row = n0 + wr * 64 + mt * 16 + g + hf * 8;
#pragma unroll
            for (int nt = 0; nt < 4; nt++) {
                const int col = m0 + wc * 32 + nt * 8 + cc * 2;
                float2 bv = *(const float2*)(bias + col);
                float ox = acc[mt][nt][hf * 2 + 0] + bv.x;
                float oy = acc[mt][nt][hf * 2 + 1] + bv.y;
                if (OUT_BF16) {
                    __nv_bfloat162 p = __floats2bfloat162_rn(ox, oy);
                    *(uint32_t*)((__nv_bfloat16*)Cout + (size_t)row * D + col) =
                        *(uint32_t*)&p;
                } else {
                    if (R) {
                        float2 rvv = *(const float2*)(R + (size_t)row * D + col);
                        ox += rvv.x; oy += rvv.y;
                    }
                    float2 o; o.x = ox; o.y = oy;
                    *(float2*)((float*)Cout + (size_t)row * D + col) = o;
                }
            }
        }
    }
}

// ======================= bf16 mma flash attention ===========================
// Block: 256 q rows, 16 warps x 16 rows. 64-key tiles. HD = 64.
constexpr int AST = 72;                     // bf16 elems per smem row
constexpr int AQ_OFF = 0;
constexpr int AK_OFF = 256 * AST;           // 18432
constexpr int AV_OFF = AK_OFF + 64 * AST;   // Vt[d][tok]
constexpr int AP_OFF = AV_OFF + 64 * AST;
constexpr int AEND   = AP_OFF + 256 * AST;  // 46080 bf16 elems
constexpr int AM_BYTE = AEND * 2;           // mask ints start (92160, 4B aligned)
constexpr int ATT_SMEM = AM_BYTE + 64 * 4;  // 92416 B

__global__ __launch_bounds__(512) void attn_mma(
    const __nv_bfloat16* __restrict__ Q, const __nv_bfloat16* __restrict__ K,
    const __nv_bfloat16* __restrict__ V, const int* __restrict__ mask,
    __nv_bfloat16* __restrict__ O)
{
    extern __shared__ __nv_bfloat16 smb[];
    int* ms = (int*)((char*)smb + AM_BYTE);
    const int tid = threadIdx.x, lane = tid & 31, wid = tid >> 5;
    const int b = blockIdx.z, h = blockIdx.y, q0 = blockIdx.x * 256;
    const uint32_t sb = smem_u32(smb);
    const int lrow = lane & 15;
    const int lcol8 = (lane >> 4) * 8;
    const int g = lane >> 2, cc = lane & 3;
    const int qb = wid * 16;
    const float scale = 0.125f;  // 1/sqrt(64)

    // load Q tile (256 x 64 bf16)
#pragma unroll
    for (int i = 0; i < 4; i++) {
        const int idx = tid + i * 512;
        const int row = idx >> 3, c8 = (idx & 7) * 8;
        uint4 v = *(const uint4*)(Q + (size_t)(b * S + q0 + row) * D + h * HD + c8);
        *(uint4*)(smb + AQ_OFF + row * AST + c8) = v;
    }

    float ob[8][4];
#pragma unroll
    for (int nt = 0; nt < 8; nt++)
#pragma unroll
        for (int q = 0; q < 4; q++) ob[nt][q] = 0.f;
    float mst[2], lst[2];
    mst[0] = mst[1] = -1e30f;
    lst[0] = lst[1] = 0.f;

    for (int t = 0; t < S / 64; t++) {
        const int k0 = t * 64;
        __syncthreads();  // prior-tile reads complete

        // K tile (64 x 64)
        {
            const int row = tid >> 3, c8 = (tid & 7) * 8;
            uint4 v = *(const uint4*)(K + (size_t)(b * S + k0 + row) * D + h * HD + c8);
            *(uint4*)(smb + AK_OFF + row * AST + c8) = v;
        }
        // V tile transposed: Vt[d][tok]
        {
            const int tok = tid & 63;
            const int d8 = (tid >> 6) * 8;
            union { uint4 u; __nv_bfloat16 e[8]; } v;
            v.u = *(const uint4*)(V + (size_t)(b * S + k0 + tok) * D + h * HD + d8);
#pragma unroll
            for (int j = 0; j < 8; j++)
                smb[AV_OFF + (d8 + j) * AST + tok] = v.e[j];
        }
        if (tid < 64) ms[tid] = mask[b * S + k0 + tid];
        __syncthreads();

        // ---- S = Q K^T ----
        float sc[8][4];
#pragma unroll
        for (int nt = 0; nt < 8; nt++)
#pragma unroll
            for (int q = 0; q < 4; q++) sc[nt][q] = 0.f;

#pragma unroll
        for (int k = 0; k < 4; k++) {
            uint32_t a[4], bfr[8][2];
            {
                const uint32_t addr =
                    sb + ((AQ_OFF + (qb + lrow) * AST) + k * 16 + lcol8) * 2;
                ldsm4(a[0], a[1], a[2], a[3], addr);
            }
#pragma unroll
            for (int np = 0; np < 4; np++) {
                const uint32_t addr =
                    sb + ((AK_OFF + (np * 16 + lrow) * AST) + k * 16 + lcol8) * 2;
                uint32_t b0, b1, b2, b3;
                ldsm4(b0, b1, b2, b3, addr);
                bfr[np * 2 + 0][0] = b0; bfr[np * 2 + 1][0] = b1;
                bfr[np * 2 + 0][1] = b2; bfr[np * 2 + 1][1] = b3;
            }
#pragma unroll
            for (int nt = 0; nt < 8; nt++)
                mma16(sc[nt], a, bfr[nt][0], bfr[nt][1]);
        }

        // ---- online softmax (per row-half) ----
#pragma unroll
        for (int hf = 0; hf < 2; hf++) {
            float rm = -1e30f;
#pragma unroll
            for (int nt = 0; nt < 8; nt++) {
                const int c0 = nt * 8 + cc * 2;
                const float m0v = ms[c0] ? 0.f : -1e9f;
                const float m1v = ms[c0 + 1] ? 0.f : -1e9f;
                float v0 = fmaf(sc[nt][hf * 2 + 0], scale, m0v);
                float v1 = fmaf(sc[nt][hf * 2 + 1], scale, m1v);
                sc[nt][hf * 2 + 0] = v0;
                sc[nt][hf * 2 + 1] = v1;
                rm = fmaxf(rm, fmaxf(v0, v1));
            }
            rm = fmaxf(rm, __shfl_xor_sync(0xffffffffu, rm, 1));
            rm = fmaxf(rm, __shfl_xor_sync(0xffffffffu, rm, 2));
            const float mnew = fmaxf(mst[hf], rm);
            const float cf = __expf(mst[hf] - mnew);
            mst[hf] = mnew;
            float rs = 0.f;
#pragma unroll
            for (int nt = 0; nt < 8; nt++) {
                float p0 = __expf(sc[nt][hf * 2 + 0] - mnew);
                float p1 = __expf(sc[nt][hf * 2 + 1] - mnew);
                sc[nt][hf * 2 + 0] = p0;
                sc[nt][hf * 2 + 1] = p1;
                rs += p0 + p1;
            }
            rs += __shfl_xor_sync(0xffffffffu, rs, 1);
            rs += __shfl_xor_sync(0xffffffffu, rs, 2);
            lst[hf] = lst[hf] * cf + rs;
#pragma unroll
            for (int nt = 0; nt < 8; nt++) {
                ob[nt][hf * 2 + 0] *= cf;
                ob[nt][hf * 2 + 1] *= cf;
            }
        }

        // stage P (bf16) — warp-local rows
#pragma unroll
        for (int nt = 0; nt < 8; nt++) {
            const int cp = nt * 8 + cc * 2;
            __nv_bfloat162 p0 = __floats2bfloat162_rn(sc[nt][0], sc[nt][1]);
            __nv_bfloat162 p1 = __floats2bfloat162_rn(sc[nt][2], sc[nt][3]);
            *(uint32_t*)(smb + AP_OFF + (qb + g) * AST + cp) = *(uint32_t*)&p0;
            *(uint32_t*)(smb + AP_OFF + (qb + g + 8) * AST + cp) = *(uint32_t*)&p1;
        }
        __syncwarp();

        // ---- O += P V ----
#pragma unroll
        for (int k = 0; k < 4; k++) {
            uint32_t a[4], bfr[8][2];
            {
                const uint32_t addr =
                    sb + ((AP_OFF + (qb + lrow) * AST) + k * 16 + lcol8) * 2;
                ldsm4(a[0], a[1], a[2], a[3], addr);
            }
#pragma unroll
            for (int np = 0; np < 4; np++) {
                const uint32_t addr =
                    sb + ((AV_OFF + (np * 16 + lrow) * AST) + k * 16 + lcol8) * 2;
                uint32_t b0, b1, b2, b3;
                ldsm4(b0, b1, b2, b3, addr);
                bfr[np * 2 + 0][0] = b0; bfr[np * 2 + 1][0] = b1;
                bfr[np * 2 + 0][1] = b2; bfr[np * 2 + 1][1] = b3;
            }
#pragma unroll
            for (int nt = 0; nt < 8; nt++)
                mma16(ob[nt], a, bfr[nt][0], bfr[nt][1]);
        }
    }

    // epilogue: O = ob / l (bf16 out)
#pragma unroll
    for (int hf = 0; hf < 2; hf++) {
        const float inv = 1.0f / lst[hf];
        const int row = q0 + qb + g + hf * 8;
#pragma unroll
        for (int nt = 0; nt < 8; nt++) {
            const int col = h * HD + nt * 8 + cc * 2;
            __nv_bfloat162 p = __floats2bfloat162_rn(ob[nt][hf * 2 + 0] * inv,
                                                     ob[nt][hf * 2 + 1] * inv);
            *(uint32_t*)(O + (size_t)(b * S + row) * D + col) = *(uint32_t*)&p;
        }
    }
}

// ---------------- LayerNorm over D, one block per row ------------------------
__global__ __launch_bounds__(256) void ln_kernel(
    const float* __restrict__ Y, const float* __restrict__ gamma,
    const float* __restrict__ beta, float* __restrict__ out)
{
    __shared__ float r1[256], r2[256];
    const int row = blockIdx.x;
    const int tid = threadIdx.x;
    const float* y = Y + (size_t)row * D;

    float s = 0.f, s2 = 0.f;
    for (int i = tid; i < D; i += 256) {
        const float v = y[i];
        s += v;
        s2 = fmaf(v, v, s2);
    }
    r1[tid] = s; r2[tid] = s2;
    __syncthreads();
    for (int o = 128; o > 0; o >>= 1) {
        if (tid < o) { r1[tid] += r1[tid + o]; r2[tid] += r2[tid + o]; }
        __syncthreads();
    }
    const float mu = r1[0] * (1.0f / D);
    const float var = r2[0] * (1.0f / D) - mu * mu;
    const float inv = rsqrtf(var + 1e-5f);

    float* o = out + (size_t)row * D;
    for (int i = tid; i < D; i += 256)
        o[i] = (y[i] - mu) * inv * gamma[i] + beta[i];
}

// ---------------- launch ------------------------------------------------------
extern "C" void kernel_launch(void* const* d_in, const int* in_sizes, int n_in,
                              void* d_out, int out_size)
{
    const float* x     = (const float*)d_in[0];
    const int*   mask  = (const int*)d_in[1];
    const float* Wq    = (const float*)d_in[2];
    const float* bq    = (const float*)d_in[3];
    const float* Wk    = (const float*)d_in[4];
    const float* bk    = (const float*)d_in[5];
    const float* Wv    = (const float*)d_in[6];
    const float* bv    = (const float*)d_in[7];
    const float* Wo    = (const float*)d_in[8];
    const float* bo    = (const float*)d_in[9];
    const float* gamma = (const float*)d_in[10];
    const float* beta  = (const float*)d_in[11];

    __nv_bfloat16 *Xb, *Wb, *Qb, *Kb, *Vb, *Cb;
    float* Yp;
    cudaGetSymbolAddress((void**)&Xb, g_Xb);
    cudaGetSymbolAddress((void**)&Wb, g_Wb);
    cudaGetSymbolAddress((void**)&Qb, g_Qb);
    cudaGetSymbolAddress((void**)&Kb, g_Kb);
    cudaGetSymbolAddress((void**)&Vb, g_Vb);
    cudaGetSymbolAddress((void**)&Cb, g_Cb);
    cudaGetSymbolAddress((void**)&Yp, g_Y);

    cudaFuncSetAttribute(gemm_bf<true>,
                         cudaFuncAttributeMaxDynamicSharedMemorySize, GEMM_SMEM);
    cudaFuncSetAttribute(gemm_bf<false>,
                         cudaFuncAttributeMaxDynamicSharedMemorySize, GEMM_SMEM);
    cudaFuncSetAttribute(attn_mma,
                         cudaFuncAttributeMaxDynamicSharedMemorySize, ATT_SMEM);

    const int nX4 = NR * D / 4, nW4 = D * D / 4;
    cvt_bf16<<<nX4 / 256, 256>>>(x, Xb, nX4);
    cvt_bf16<<<nW4 / 256, 256>>>(Wq, Wb + (size_t)0 * D * D, nW4);
    cvt_bf16<<<nW4 / 256, 256>>>(Wk, Wb + (size_t)1 * D * D, nW4);
    cvt_bf16<<<nW4 / 256, 256>>>(Wv, Wb + (size_t)2 * D * D, nW4);
    cvt_bf16<<<nW4 / 256, 256>>>(Wo, Wb + (size_t)3 * D * D, nW4);

    dim3 gg(D / 128, NR / 128);  // (8, 64)
    gemm_bf<true><<<gg, 256, GEMM_SMEM>>>(Xb, Wb + (size_t)0 * D * D, bq, nullptr, Qb);
    gemm_bf<true><<<gg, 256, GEMM_SMEM>>>(Xb, Wb + (size_t)1 * D * D, bk, nullptr, Kb);
    gemm_bf<true><<<gg, 256, GEMM_SMEM>>>(Xb, Wb + (size_t)2 * D * D, bv, nullptr, Vb);

    attn_mma<<<dim3(S / 256, H, B), 512, ATT_SMEM>>>(Qb, Kb, Vb, mask, Cb);

    gemm_bf<false><<<gg, 256, GEMM_SMEM>>>(Cb, Wb + (size_t)3 * D * D, bo, x, Yp);
    ln_kernel<<<NR, 256>>>(Yp, gamma, beta, (float*)d_out);
}

// round 6
// speedup vs baseline: 6.5617x; 1.1030x over previous
#include <cuda_runtime.h>
#include <cuda_bf16.h>
#include <cstdint>
#include <math.h>

constexpr int B = 4, S = 2048, D = 1024, H = 16, HD = 64;
constexpr int NR = B * S;  // 8192 rows

// ---------------- scratch (static device globals; no allocation) -------------
__device__ __nv_bfloat16 g_Xb[(size_t)NR * D];      // x bf16
__device__ __nv_bfloat16 g_Wb[(size_t)4 * D * D];   // Wq,Wk,Wv,Wo bf16
__device__ __nv_bfloat16 g_Qb[(size_t)NR * D];
__device__ __nv_bfloat16 g_Kb[(size_t)NR * D];
__device__ __nv_bfloat16 g_Vb[(size_t)NR * D];
__device__ __nv_bfloat16 g_Cb[(size_t)NR * D];      // attention out bf16
__device__ float         g_Y[(size_t)NR * D];

// ======================= helpers ============================================
__device__ __forceinline__ uint32_t smem_u32(const void* p) {
    uint32_t a;
    asm("{ .reg .u64 t; cvta.to.shared.u64 t, %1; cvt.u32.u64 %0, t; }"
        : "=r"(a) : "l"(p));
    return a;
}
__device__ __forceinline__ void ldsm4(uint32_t& r0, uint32_t& r1, uint32_t& r2,
                                      uint32_t& r3, uint32_t addr) {
    asm volatile("ldmatrix.sync.aligned.m8n8.x4.shared.b16 {%0,%1,%2,%3}, [%4];"
                 : "=r"(r0), "=r"(r1), "=r"(r2), "=r"(r3) : "r"(addr));
}
__device__ __forceinline__ void ldsm4t(uint32_t& r0, uint32_t& r1, uint32_t& r2,
                                       uint32_t& r3, uint32_t addr) {
    asm volatile("ldmatrix.sync.aligned.m8n8.x4.trans.shared.b16 {%0,%1,%2,%3}, [%4];"
                 : "=r"(r0), "=r"(r1), "=r"(r2), "=r"(r3) : "r"(addr));
}
__device__ __forceinline__ void mma16(float (&c)[4], const uint32_t (&a)[4],
                                      uint32_t b0, uint32_t b1) {
    asm volatile(
        "mma.sync.aligned.m16n8k16.row.col.f32.bf16.bf16.f32 "
        "{%0,%1,%2,%3}, {%4,%5,%6,%7}, {%8,%9}, {%0,%1,%2,%3};"
        : "+f"(c[0]), "+f"(c[1]), "+f"(c[2]), "+f"(c[3])
        : "r"(a[0]), "r"(a[1]), "r"(a[2]), "r"(a[3]), "r"(b0), "r"(b1));
}
__device__ __forceinline__ void cp_async16(uint32_t s, const void* g) {
    asm volatile("cp.async.cg.shared.global [%0], [%1], 16;" :: "r"(s), "l"(g));
}
__device__ __forceinline__ void cp_commit() {
    asm volatile("cp.async.commit_group;" ::: "memory");
}
template <int N>
__device__ __forceinline__ void cp_wait() {
    asm volatile("cp.async.wait_group %0;" :: "n"(N) : "memory");
}

// ======================= fp32 -> bf16 prep ===================================
__global__ __launch_bounds__(256) void cvt_bf16(const float* __restrict__ in,
                                                __nv_bfloat16* __restrict__ out,
                                                int n4)
{
    const int i = (blockIdx.x * 256 + threadIdx.x) * 4;
    if (i < n4 * 4) {
        float4 v = *(const float4*)(in + i);
        __nv_bfloat162 p0 = __floats2bfloat162_rn(v.x, v.y);
        __nv_bfloat162 p1 = __floats2bfloat162_rn(v.z, v.w);
        uint2 u;
        u.x = *(uint32_t*)&p0;
        u.y = *(uint32_t*)&p1;
        *(uint2*)(out + i) = u;
    }
}

// ======================= bf16 mma GEMM ======================================
// C[n, m] = sum_k A[n, k] * W[m, k] + bias[m] (+ R[n, m])
// Block tile 128(n) x 128(m), K chunks of 64 bf16. 8 warps, warp tile 64x32.
constexpr int GST = 72;                 // smem row stride (bf16 elems)
constexpr int G_STAGE = 256 * GST;      // bf16 elems per stage
constexpr int GEMM_SMEM = 2 * G_STAGE * 2;  // 73728 B

template <bool OUT_BF16>
__global__ __launch_bounds__(256, 2) void gemm_bf(
    const __nv_bfloat16* __restrict__ A, const __nv_bfloat16* __restrict__ W,
    const float* __restrict__ bias, const float* __restrict__ R,
    void* __restrict__ Cout)
{
    extern __shared__ __nv_bfloat16 gsm[];
    const int tid = threadIdx.x;
    const int lane = tid & 31, wid = tid >> 5;
    const int m0 = blockIdx.x * 128, n0 = blockIdx.y * 128;
    const int wr = wid >> 2, wc = wid & 3;
    const int lrow = lane & 15;
    const int lcol8 = (lane >> 4) * 8;
    const uint32_t sbase = smem_u32(gsm);

    float acc[4][4][4];
#pragma unroll
    for (int mt = 0; mt < 4; mt++)
#pragma unroll
        for (int nt = 0; nt < 4; nt++)
#pragma unroll
            for (int q = 0; q < 4; q++) acc[mt][nt][q] = 0.f;

    auto issue_chunk = [&](int c) {
        const int k0 = c * 64;
        const uint32_t stb = sbase + (c & 1) * G_STAGE * 2;
#pragma unroll
        for (int i = 0; i < 8; i++) {
            const int idx = tid + i * 256;
            const int t = idx & 1023;
            const int row = t >> 3, c8 = (t & 7) * 8;
            const __nv_bfloat16* g =
                (idx < 1024 ? A + (size_t)(n0 + row) * D
                            : W + (size_t)(m0 + row) * D) + k0 + c8;
            const int srow = row + (idx < 1024 ? 0 : 128);
            cp_async16(stb + (srow * GST + c8) * 2, g);
        }
        cp_commit();
    };

    issue_chunk(0);
    for (int c = 0; c < 16; c++) {
        if (c < 15) issue_chunk(c + 1);
        if (c < 15) cp_wait<1>(); else cp_wait<0>();
        __syncthreads();

        const uint32_t stb = sbase + (c & 1) * G_STAGE * 2;
#pragma unroll
        for (int k = 0; k < 4; k++) {
            uint32_t a[4][4];
            uint32_t bfr[4][2];
#pragma unroll
            for (int mt = 0; mt < 4; mt++) {
                const uint32_t addr =
                    stb + ((wr * 64 + mt * 16 + lrow) * GST + k * 16 + lcol8) * 2;
                ldsm4(a[mt][0], a[mt][1], a[mt][2], a[mt][3], addr);
            }
#pragma unroll
            for (int np = 0; np < 2; np++) {
                const uint32_t addr =
                    stb + ((128 + wc * 32 + np * 16 + lrow) * GST + k * 16 + lcol8) * 2;
                uint32_t b0, b1, b2, b3;
                ldsm4(b0, b1, b2, b3, addr);
                bfr[np * 2 + 0][0] = b0; bfr[np * 2 + 1][0] = b1;
                bfr[np * 2 + 0][1] = b2; bfr[np * 2 + 1][1] = b3;
            }
#pragma unroll
            for (int mt = 0; mt < 4; mt++)
#pragma unroll
                for (int nt = 0; nt < 4; nt++)
                    mma16(acc[mt][nt], a[mt], bfr[nt][0], bfr[nt][1]);
        }
        __syncthreads();
    }

    // epilogue
    const int g = lane >> 2, cc = lane & 3;
#pragma unroll
    for (int mt = 0; mt < 4; mt++) {
#pragma unroll
        for (int hf = 0; hf < 2; hf++) {
            const int row = n0 + wr * 64 + mt * 16 + g + hf * 8;
#pragma unroll
            for (int nt = 0; nt < 4; nt++) {
                const int col = m0 + wc * 32 + nt * 8 + cc * 2;
                float2 bv = *(const float2*)(bias + col);
                float ox = acc[mt][nt][hf * 2 + 0] + bv.x;
                float oy = acc[mt][nt][hf * 2 + 1] + bv.y;
                if (OUT_BF16) {
                    __nv_bfloat162 p = __floats2bfloat162_rn(ox, oy);
                    *(uint32_t*)((__nv_bfloat16*)Cout + (size_t)row * D + col) =
                        *(uint32_t*)&p;
                } else {
                    if (R) {
                        float2 rvv = *(const float2*)(R + (size_t)row * D + col);
                        ox += rvv.x; oy += rvv.y;
                    }
                    float2 o; o.x = ox; o.y = oy;
                    *(float2*)((float*)Cout + (size_t)row * D + col) = o;
                }
            }
        }
    }
}

// ======================= bf16 mma flash attention ===========================
// Block: 256 q rows, 16 warps x 16 rows. 64-key tiles, double-buffered cp.async.
constexpr int AST = 72;                       // bf16 elems per smem row
constexpr int AQ_E = 0;                       // Q: 256 x AST
constexpr int AK_E = 256 * AST;               // K: 2 stages x 64 x AST
constexpr int AV_E = AK_E + 2 * 64 * AST;     // V: 2 stages x 64 x AST (natural [tok][d])
constexpr int AP_E = AV_E + 2 * 64 * AST;     // P: 256 x AST
constexpr int AEND_E = AP_E + 256 * AST;
constexpr int AM_BYTE = AEND_E * 2;           // mask: 2 stages x 64 ints
constexpr int ATT_SMEM = AM_BYTE + 2 * 64 * 4;
constexpr int KSTG = 64 * AST;                // elems per K/V stage

__global__ __launch_bounds__(512) void attn_mma(
    const __nv_bfloat16* __restrict__ Q, const __nv_bfloat16* __restrict__ K,
    const __nv_bfloat16* __restrict__ V, const int* __restrict__ mask,
    __nv_bfloat16* __restrict__ O)
{
    extern __shared__ __nv_bfloat16 smb[];
    int* ms = (int*)((char*)smb + AM_BYTE);
    const int tid = threadIdx.x, lane = tid & 31, wid = tid >> 5;
    const int b = blockIdx.z, h = blockIdx.y, q0 = blockIdx.x * 256;
    const uint32_t sb = smem_u32(smb);
    const int lrow = lane & 15;
    const int lcol8 = (lane >> 4) * 8;
    const int lrow_t = (lane & 7) + ((lane >> 4) << 3);   // trans-ldsm source row
    const int dsel = ((lane >> 3) & 1) * 8;               // trans-ldsm source col
    const int g = lane >> 2, cc = lane & 3;
    const int qb = wid * 16;
    const float scale = 0.125f;  // 1/sqrt(64)

    // Q tile (256 x 64 bf16) via cp.async: 4 x 16B per thread
#pragma unroll
    for (int i = 0; i < 4; i++) {
        const int idx = tid + i * 512;
        const int row = idx >> 3, c8 = (idx & 7) * 8;
        cp_async16(sb + (AQ_E + row * AST + c8) * 2,
                   Q + (size_t)(b * S + q0 + row) * D + h * HD + c8);
    }
    cp_commit();

    auto issueKV = [&](int t) {
        const int k0 = t * 64;
        const int stage = t & 1;
        const int row = tid >> 3, c8 = (tid & 7) * 8;
        cp_async16(sb + ((AK_E + stage * KSTG) + row * AST + c8) * 2,
                   K + (size_t)(b * S + k0 + row) * D + h * HD + c8);
        cp_async16(sb + ((AV_E + stage * KSTG) + row * AST + c8) * 2,
                   V + (size_t)(b * S + k0 + row) * D + h * HD + c8);
        if (tid < 16)
            cp_async16(sb + AM_BYTE + stage * 256 + tid * 16,
                       mask + b * S + k0 + tid * 4);
        cp_commit();
    };

    issueKV(0);

    float ob[8][4];
#pragma unroll
    for (int nt = 0; nt < 8; nt++)
#pragma unroll
        for (int q = 0; q < 4; q++) ob[nt][q] = 0.f;
    float mst[2], lst[2];
    mst[0] = mst[1] = -1e30f;
    lst[0] = lst[1] = 0.f;

    constexpr int NT = S / 64;  // 32 tiles
    for (int t = 0; t < NT; t++) {
        const int stage = t & 1;
        if (t + 1 < NT) {
            issueKV(t + 1);
            cp_wait<1>();
        } else {
            cp_wait<0>();
        }
        __syncthreads();

        // ---- S = Q K^T ----
        float sc[8][4];
#pragma unroll
        for (int nt = 0; nt < 8; nt++)
#pragma unroll
            for (int q = 0; q < 4; q++) sc[nt][q] = 0.f;

#pragma unroll
        for (int k = 0; k < 4; k++) {
            uint32_t a[4], bfr[8][2];
            {
                const uint32_t addr =
                    sb + ((AQ_E + (qb + lrow) * AST) + k * 16 + lcol8) * 2;
                ldsm4(a[0], a[1], a[2], a[3], addr);
            }
#pragma unroll
            for (int np = 0; np < 4; np++) {
                const uint32_t addr =
                    sb + ((AK_E + stage * KSTG + (np * 16 + lrow) * AST) +
                          k * 16 + lcol8) * 2;
                uint32_t b0, b1, b2, b3;
                ldsm4(b0, b1, b2, b3, addr);
                bfr[np * 2 + 0][0] = b0; bfr[np * 2 + 1][0] = b1;
                bfr[np * 2 + 0][1] = b2; bfr[np * 2 + 1][1] = b3;
            }
#pragma unroll
            for (int nt = 0; nt < 8; nt++)
                mma16(sc[nt], a, bfr[nt][0], bfr[nt][1]);
        }

        // ---- online softmax (per row-half) ----
        const int* mstg = ms + stage * 64;
#pragma unroll
        for (int hf = 0; hf < 2; hf++) {
            float rm = -1e30f;
#pragma unroll
            for (int nt = 0; nt < 8; nt++) {
                const int c0 = nt * 8 + cc * 2;
                const float m0v = mstg[c0] ? 0.f : -1e9f;
                const float m1v = mstg[c0 + 1] ? 0.f : -1e9f;
                float v0 = fmaf(sc[nt][hf * 2 + 0], scale, m0v);
                float v1 = fmaf(sc[nt][hf * 2 + 1], scale, m1v);
                sc[nt][hf * 2 + 0] = v0;
                sc[nt][hf * 2 + 1] = v1;
                rm = fmaxf(rm, fmaxf(v0, v1));
            }
            rm = fmaxf(rm, __shfl_xor_sync(0xffffffffu, rm, 1));
            rm = fmaxf(rm, __shfl_xor_sync(0xffffffffu, rm, 2));
            const float mnew = fmaxf(mst[hf], rm);
            const float cf = __expf(mst[hf] - mnew);
            mst[hf] = mnew;
            float rs = 0.f;
#pragma unroll
            for (int nt = 0; nt < 8; nt++) {
                float p0 = __expf(sc[nt][hf * 2 + 0] - mnew);
                float p1 = __expf(sc[nt][hf * 2 + 1] - mnew);
                sc[nt][hf * 2 + 0] = p0;
                sc[nt][hf * 2 + 1] = p1;
                rs += p0 + p1;
            }
            rs += __shfl_xor_sync(0xffffffffu, rs, 1);
            rs += __shfl_xor_sync(0xffffffffu, rs, 2);
            lst[hf] = lst[hf] * cf + rs;
#pragma unroll
            for (int nt = 0; nt < 8; nt++) {
                ob[nt][hf * 2 + 0] *= cf;
                ob[nt][hf * 2 + 1] *= cf;
            }
        }

        // stage P (bf16) — warp-local rows
#pragma unroll
        for (int nt = 0; nt < 8; nt++) {
            const int cp = nt * 8 + cc * 2;
            __nv_bfloat162 p0 = __floats2bfloat162_rn(sc[nt][0], sc[nt][1]);
            __nv_bfloat162 p1 = __floats2bfloat162_rn(sc[nt][2], sc[nt][3]);
            *(uint32_t*)(smb + AP_E + (qb + g) * AST + cp) = *(uint32_t*)&p0;
            *(uint32_t*)(smb + AP_E + (qb + g + 8) * AST + cp) = *(uint32_t*)&p1;
        }
        __syncwarp();

        // ---- O += P V (V natural layout, trans ldmatrix) ----
#pragma unroll
        for (int k = 0; k < 4; k++) {
            uint32_t a[4], bfr[8][2];
            {
                const uint32_t addr =
                    sb + ((AP_E + (qb + lrow) * AST) + k * 16 + lcol8) * 2;
                ldsm4(a[0], a[1], a[2], a[3], addr);
            }
#pragma unroll
            for (int np = 0; np < 4; np++) {
                const uint32_t addr =
                    sb + ((AV_E + stage * KSTG + (k * 16 + lrow_t) * AST) +
                          np * 16 + dsel) * 2;
                uint32_t b0, b1, b2, b3;
                ldsm4t(b0, b1, b2, b3, addr);
                bfr[np * 2 + 0][0] = b0; bfr[np * 2 + 1][0] = b1;
                bfr[np * 2 + 0][1] = b2; bfr[np * 2 + 1][1] = b3;
            }
#pragma unroll
            for (int nt = 0; nt < 8; nt++)
                mma16(ob[nt], a, bfr[nt][0], bfr[nt][1]);
        }
        __syncthreads();  // stage t fully consumed before t+2 overwrites it
    }

    // epilogue: O = ob / l (bf16 out)
#pragma unroll
    for (int hf = 0; hf < 2; hf++) {
        const float inv = 1.0f / lst[hf];
        const int row = q0 + qb + g + hf * 8;
#pragma unroll
        for (int nt = 0; nt < 8; nt++) {
            const int col = h * HD + nt * 8 + cc * 2;
            __nv_bfloat162 p = __floats2bfloat162_rn(ob[nt][hf * 2 + 0] * inv,
                                                     ob[nt][hf * 2 + 1] * inv);
            *(uint32_t*)(O + (size_t)(b * S + row) * D + col) = *(uint32_t*)&p;
        }
    }
}

// ---------------- LayerNorm over D, one block per row ------------------------
__global__ __launch_bounds__(256) void ln_kernel(
    const float* __restrict__ Y, const float* __restrict__ gamma,
    const float* __restrict__ beta, float* __restrict__ out)
{
    __shared__ float r1[256], r2[256];
    const int row = blockIdx.x;
    const int tid = threadIdx.x;
    const float* y = Y + (size_t)row * D;

    float s = 0.f, s2 = 0.f;
    for (int i = tid; i < D; i += 256) {
        const float v = y[i];
        s += v;
        s2 = fmaf(v, v, s2);
    }
    r1[tid] = s; r2[tid] = s2;
    __syncthreads();
    for (int o = 128; o > 0; o >>= 1) {
        if (tid < o) { r1[tid] += r1[tid + o]; r2[tid] += r2[tid + o]; }
        __syncthreads();
    }
    const float mu = r1[0] * (1.0f / D);
    const float var = r2[0] * (1.0f / D) - mu * mu;
    const float inv = rsqrtf(var + 1e-5f);

    float* o = out + (size_t)row * D;
    for (int i = tid; i < D; i += 256)
        o[i] = (y[i] - mu) * inv * gamma[i] + beta[i];
}

// ---------------- launch ------------------------------------------------------
extern "C" void kernel_launch(void* const* d_in, const int* in_sizes, int n_in,
                              void* d_out, int out_size)
{
    const float* x     = (const float*)d_in[0];
    const int*   mask  = (const int*)d_in[1];
    const float* Wq    = (const float*)d_in[2];
    const float* bq    = (const float*)d_in[3];
    const float* Wk    = (const float*)d_in[4];
    const float* bk    = (const float*)d_in[5];
    const float* Wv    = (const float*)d_in[6];
    const float* bv    = (const float*)d_in[7];
    const float* Wo    = (const float*)d_in[8];
    const float* bo    = (const float*)d_in[9];
    const float* gamma = (const float*)d_in[10];
    const float* beta  = (const float*)d_in[11];

    __nv_bfloat16 *Xb, *Wb, *Qb, *Kb, *Vb, *Cb;
    float* Yp;
    cudaGetSymbolAddress((void**)&Xb, g_Xb);
    cudaGetSymbolAddress((void**)&Wb, g_Wb);
    cudaGetSymbolAddress((void**)&Qb, g_Qb);
    cudaGetSymbolAddress((void**)&Kb, g_Kb);
    cudaGetSymbolAddress((void**)&Vb, g_Vb);
    cudaGetSymbolAddress((void**)&Cb, g_Cb);
    cudaGetSymbolAddress((void**)&Yp, g_Y);

    cudaFuncSetAttribute(gemm_bf<true>,
                         cudaFuncAttributeMaxDynamicSharedMemorySize, GEMM_SMEM);
    cudaFuncSetAttribute(gemm_bf<false>,
                         cudaFuncAttributeMaxDynamicSharedMemorySize, GEMM_SMEM);
    cudaFuncSetAttribute(attn_mma,
                         cudaFuncAttributeMaxDynamicSharedMemorySize, ATT_SMEM);

    const int nX4 = NR * D / 4, nW4 = D * D / 4;
    cvt_bf16<<<nX4 / 256, 256>>>(x, Xb, nX4);
    cvt_bf16<<<nW4 / 256, 256>>>(Wq, Wb + (size_t)0 * D * D, nW4);
    cvt_bf16<<<nW4 / 256, 256>>>(Wk, Wb + (size_t)1 * D * D, nW4);
    cvt_bf16<<<nW4 / 256, 256>>>(Wv, Wb + (size_t)2 * D * D, nW4);
    cvt_bf16<<<nW4 / 256, 256>>>(Wo, Wb + (size_t)3 * D * D, nW4);

    dim3 gg(D / 128, NR / 128);  // (8, 64)
    gemm_bf<true><<<gg, 256, GEMM_SMEM>>>(Xb, Wb + (size_t)0 * D * D, bq, nullptr, Qb);
    gemm_bf<true><<<gg, 256, GEMM_SMEM>>>(Xb, Wb + (size_t)1 * D * D, bk, nullptr, Kb);
    gemm_bf<true><<<gg, 256, GEMM_SMEM>>>(Xb, Wb + (size_t)2 * D * D, bv, nullptr, Vb);

    attn_mma<<<dim3(S / 256, H, B), 512, ATT_SMEM>>>(Qb, Kb, Vb, mask, Cb);

    gemm_bf<false><<<gg, 256, GEMM_SMEM>>>(Cb, Wb + (size_t)3 * D * D, bo, x, Yp);
    ln_kernel<<<NR, 256>>>(Yp, gamma, beta, (float*)d_out);
}

// round 7
// speedup vs baseline: 6.9792x; 1.0636x over previous
#include <cuda_runtime.h>
#include <cuda_bf16.h>
#include <cstdint>
#include <math.h>

constexpr int B = 4, S = 2048, D = 1024, H = 16, HD = 64;
constexpr int NR = B * S;  // 8192 rows

// ---------------- scratch (static device globals; no allocation) -------------
__device__ __nv_bfloat16 g_Xb[(size_t)NR * D];      // x bf16
__device__ __nv_bfloat16 g_Wb[(size_t)4 * D * D];   // Wq,Wk,Wv,Wo bf16
__device__ __nv_bfloat16 g_Qb[(size_t)NR * D];
__device__ __nv_bfloat16 g_Kb[(size_t)NR * D];
__device__ __nv_bfloat16 g_Vb[(size_t)NR * D];
__device__ __nv_bfloat16 g_Cb[(size_t)NR * D];      // attention out bf16
__device__ float         g_Y[(size_t)NR * D];

// ======================= helpers ============================================
__device__ __forceinline__ uint32_t smem_u32(const void* p) {
    uint32_t a;
    asm("{ .reg .u64 t; cvta.to.shared.u64 t, %1; cvt.u32.u64 %0, t; }"
        : "=r"(a) : "l"(p));
    return a;
}
__device__ __forceinline__ void ldsm4(uint32_t& r0, uint32_t& r1, uint32_t& r2,
                                      uint32_t& r3, uint32_t addr) {
    asm volatile("ldmatrix.sync.aligned.m8n8.x4.shared.b16 {%0,%1,%2,%3}, [%4];"
                 : "=r"(r0), "=r"(r1), "=r"(r2), "=r"(r3) : "r"(addr));
}
__device__ __forceinline__ void ldsm4t(uint32_t& r0, uint32_t& r1, uint32_t& r2,
                                       uint32_t& r3, uint32_t addr) {
    asm volatile("ldmatrix.sync.aligned.m8n8.x4.trans.shared.b16 {%0,%1,%2,%3}, [%4];"
                 : "=r"(r0), "=r"(r1), "=r"(r2), "=r"(r3) : "r"(addr));
}
__device__ __forceinline__ void mma16(float (&c)[4], const uint32_t (&a)[4],
                                      uint32_t b0, uint32_t b1) {
    asm volatile(
        "mma.sync.aligned.m16n8k16.row.col.f32.bf16.bf16.f32 "
        "{%0,%1,%2,%3}, {%4,%5,%6,%7}, {%8,%9}, {%0,%1,%2,%3};"
        : "+f"(c[0]), "+f"(c[1]), "+f"(c[2]), "+f"(c[3])
        : "r"(a[0]), "r"(a[1]), "r"(a[2]), "r"(a[3]), "r"(b0), "r"(b1));
}
__device__ __forceinline__ void cp_async16(uint32_t s, const void* g) {
    asm volatile("cp.async.cg.shared.global [%0], [%1], 16;" :: "r"(s), "l"(g));
}
__device__ __forceinline__ void cp_commit() {
    asm volatile("cp.async.commit_group;" ::: "memory");
}
template <int N>
__device__ __forceinline__ void cp_wait() {
    asm volatile("cp.async.wait_group %0;" :: "n"(N) : "memory");
}
__device__ __forceinline__ uint32_t packbf(float x, float y) {
    __nv_bfloat162 p = __floats2bfloat162_rn(x, y);
    return *(uint32_t*)&p;
}

// ======================= fp32 -> bf16 prep ===================================
__global__ __launch_bounds__(256) void cvt_bf16(const float* __restrict__ in,
                                                __nv_bfloat16* __restrict__ out,
                                                int n4)
{
    const int i = (blockIdx.x * 256 + threadIdx.x) * 4;
    if (i < n4 * 4) {
        float4 v = *(const float4*)(in + i);
        uint2 u;
        u.x = packbf(v.x, v.y);
        u.y = packbf(v.z, v.w);
        *(uint2*)(out + i) = u;
    }
}

// ======================= bf16 mma GEMM core =================================
constexpr int GST = 72;                 // smem row stride (bf16 elems)
constexpr int G_STAGE = 256 * GST;      // bf16 elems per stage
constexpr int GEMM_SMEM = 2 * G_STAGE * 2;  // 73728 B

struct QKVOut {
    __nv_bfloat16* out[3];
    const float* bias[3];
};

// Shared GEMM mainloop: computes acc for a 128x128 tile of A(row n0) x W^T(row m0)
template <typename AccFn>
__device__ __forceinline__ void gemm_body(
    const __nv_bfloat16* __restrict__ A, const __nv_bfloat16* __restrict__ W,
    int n0, int m0, __nv_bfloat16* gsm, AccFn&& emit)
{
    const int tid = threadIdx.x;
    const int lane = tid & 31, wid = tid >> 5;
    const int wr = wid >> 2, wc = wid & 3;
    const int lrow = lane & 15;
    const int lcol8 = (lane >> 4) * 8;
    const uint32_t sbase = smem_u32(gsm);

    float acc[4][4][4];
#pragma unroll
    for (int mt = 0; mt < 4; mt++)
#pragma unroll
        for (int nt = 0; nt < 4; nt++)
#pragma unroll
            for (int q = 0; q < 4; q++) acc[mt][nt][q] = 0.f;

    auto issue_chunk = [&](int c) {
        const int k0 = c * 64;
        const uint32_t stb = sbase + (c & 1) * G_STAGE * 2;
#pragma unroll
        for (int i = 0; i < 8; i++) {
            const int idx = tid + i * 256;
            const int t = idx & 1023;
            const int row = t >> 3, c8 = (t & 7) * 8;
            const __nv_bfloat16* g =
                (idx < 1024 ? A + (size_t)(n0 + row) * D
                            : W + (size_t)(m0 + row) * D) + k0 + c8;
            const int srow = row + (idx < 1024 ? 0 : 128);
            cp_async16(stb + (srow * GST + c8) * 2, g);
        }
        cp_commit();
    };

    issue_chunk(0);
    for (int c = 0; c < 16; c++) {
        if (c < 15) issue_chunk(c + 1);
        if (c < 15) cp_wait<1>(); else cp_wait<0>();
        __syncthreads();

        const uint32_t stb = sbase + (c & 1) * G_STAGE * 2;
#pragma unroll
        for (int k = 0; k < 4; k++) {
            uint32_t a[4][4];
            uint32_t bfr[4][2];
#pragma unroll
            for (int mt = 0; mt < 4; mt++) {
                const uint32_t addr =
                    stb + ((wr * 64 + mt * 16 + lrow) * GST + k * 16 + lcol8) * 2;
                ldsm4(a[mt][0], a[mt][1], a[mt][2], a[mt][3], addr);
            }
#pragma unroll
            for (int np = 0; np < 2; np++) {
                const uint32_t addr =
                    stb + ((128 + wc * 32 + np * 16 + lrow) * GST + k * 16 + lcol8) * 2;
                uint32_t b0, b1, b2, b3;
                ldsm4(b0, b1, b2, b3, addr);
                bfr[np * 2 + 0][0] = b0; bfr[np * 2 + 1][0] = b1;
                bfr[np * 2 + 0][1] = b2; bfr[np * 2 + 1][1] = b3;
            }
#pragma unroll
            for (int mt = 0; mt < 4; mt++)
#pragma unroll
                for (int nt = 0; nt < 4; nt++)
                    mma16(acc[mt][nt], a[mt], bfr[nt][0], bfr[nt][1]);
        }
        __syncthreads();
    }

    // epilogue via callback
    const int g = lane >> 2, cc = lane & 3;
#pragma unroll
    for (int mt = 0; mt < 4; mt++)
#pragma unroll
        for (int hf = 0; hf < 2; hf++) {
            const int row = n0 + wr * 64 + mt * 16 + g + hf * 8;
#pragma unroll
            for (int nt = 0; nt < 4; nt++) {
                const int col = m0 + wc * 32 + nt * 8 + cc * 2;
                emit(row, col, acc[mt][nt][hf * 2 + 0], acc[mt][nt][hf * 2 + 1]);
            }
        }
}

// Fused QKV projection: grid.x in [0,24): sel = x>>3, m-block = x&7.
__global__ __launch_bounds__(256, 2) void qkv_gemm(
    const __nv_bfloat16* __restrict__ A, const __nv_bfloat16* __restrict__ Wall,
    QKVOut io)
{
    extern __shared__ __nv_bfloat16 gsm[];
    const int sel = blockIdx.x >> 3;
    const int m0 = (blockIdx.x & 7) * 128;
    const int n0 = blockIdx.y * 128;
    const __nv_bfloat16* W = Wall + (size_t)sel * D * D;
    __nv_bfloat16* out = io.out[sel];
    const float* bias = io.bias[sel];

    gemm_body(A, W, n0, m0, gsm,
              [&](int row, int col, float vx, float vy) {
                  float2 bv = *(const float2*)(bias + col);
                  *(uint32_t*)(out + (size_t)row * D + col) =
                      packbf(vx + bv.x, vy + bv.y);
              });
}

// Output projection with residual, fp32 out.
__global__ __launch_bounds__(256, 2) void out_gemm(
    const __nv_bfloat16* __restrict__ A, const __nv_bfloat16* __restrict__ W,
    const float* __restrict__ bias, const float* __restrict__ R,
    float* __restrict__ C)
{
    extern __shared__ __nv_bfloat16 gsm[];
    const int m0 = blockIdx.x * 128;
    const int n0 = blockIdx.y * 128;

    gemm_body(A, W, n0, m0, gsm,
              [&](int row, int col, float vx, float vy) {
                  float2 bv = *(const float2*)(bias + col);
                  float2 rv = *(const float2*)(R + (size_t)row * D + col);
                  float2 o;
                  o.x = vx + bv.x + rv.x;
                  o.y = vy + bv.y + rv.y;
                  *(float2*)(C + (size_t)row * D + col) = o;
              });
}

// ======================= bf16 mma flash attention ===========================
// Block: 256 q rows, 16 warps x 16 rows. 64-key tiles, 3-stage cp.async,
// P passed through registers (FA-2 style), V consumed via ldmatrix.trans.
constexpr int AST = 72;                       // bf16 elems per smem row
constexpr int AQ_E = 0;                       // Q: 256 x AST
constexpr int AK_E = 256 * AST;               // K: 3 stages x 64 x AST
constexpr int AV_E = AK_E + 3 * 64 * AST;     // V: 3 stages x 64 x AST
constexpr int AEND_E = AV_E + 3 * 64 * AST;
constexpr int AM_BYTE = AEND_E * 2;           // mask: 3 stages x 64 ints
constexpr int ATT_SMEM = AM_BYTE + 3 * 64 * 4;
constexpr int KSTG = 64 * AST;                // elems per K/V stage

__global__ __launch_bounds__(512) void attn_mma(
    const __nv_bfloat16* __restrict__ Q, const __nv_bfloat16* __restrict__ K,
    const __nv_bfloat16* __restrict__ V, const int* __restrict__ mask,
    __nv_bfloat16* __restrict__ O)
{
    extern __shared__ __nv_bfloat16 smb[];
    int* ms = (int*)((char*)smb + AM_BYTE);
    const int tid = threadIdx.x, lane = tid & 31, wid = tid >> 5;
    const int b = blockIdx.z, h = blockIdx.y, q0 = blockIdx.x * 256;
    const uint32_t sb = smem_u32(smb);
    const int lrow = lane & 15;
    const int lcol8 = (lane >> 4) * 8;
    const int lrow_t = (lane & 7) + ((lane >> 4) << 3);   // trans-ldsm source row
    const int dsel = ((lane >> 3) & 1) * 8;               // trans-ldsm source col
    const int g = lane >> 2, cc = lane & 3;
    const int qb = wid * 16;
    const float scale = 0.125f;  // 1/sqrt(64)

    // Q tile (256 x 64 bf16) via cp.async
#pragma unroll
    for (int i = 0; i < 4; i++) {
        const int idx = tid + i * 512;
        const int row = idx >> 3, c8 = (idx & 7) * 8;
        cp_async16(sb + (AQ_E + row * AST + c8) * 2,
                   Q + (size_t)(b * S + q0 + row) * D + h * HD + c8);
    }
    cp_commit();

    auto issueKV = [&](int t) {
        const int k0 = t * 64;
        const int stage = t % 3;
        const int row = tid >> 3, c8 = (tid & 7) * 8;
        cp_async16(sb + ((AK_E + stage * KSTG) + row * AST + c8) * 2,
                   K + (size_t)(b * S + k0 + row) * D + h * HD + c8);
        cp_async16(sb + ((AV_E + stage * KSTG) + row * AST + c8) * 2,
                   V + (size_t)(b * S + k0 + row) * D + h * HD + c8);
        if (tid < 16)
            cp_async16(sb + AM_BYTE + stage * 256 + tid * 16,
                       mask + b * S + k0 + tid * 4);
        cp_commit();
    };

    issueKV(0);
    issueKV(1);

    float ob[8][4];
#pragma unroll
    for (int nt = 0; nt < 8; nt++)
#pragma unroll
        for (int q = 0; q < 4; q++) ob[nt][q] = 0.f;
    float mst[2], lst[2];
    mst[0] = mst[1] = -1e30f;
    lst[0] = lst[1] = 0.f;

    constexpr int NT = S / 64;  // 32 tiles
    for (int t = 0; t < NT; t++) {
        const int stage = t % 3;
        if (t + 1 < NT) cp_wait<1>(); else cp_wait<0>();
        __syncthreads();               // tile t data visible; stage (t+2)%3 free
        if (t + 2 < NT) issueKV(t + 2);

        // ---- S = Q K^T ----
        float sc[8][4];
#pragma unroll
        for (int nt = 0; nt < 8; nt++)
#pragma unroll
            for (int q = 0; q < 4; q++) sc[nt][q] = 0.f;

#pragma unroll
        for (int k = 0; k < 4; k++) {
            uint32_t a[4], bfr[8][2];
            {
                const uint32_t addr =
                    sb + ((AQ_E + (qb + lrow) * AST) + k * 16 + lcol8) * 2;
                ldsm4(a[0], a[1], a[2], a[3], addr);
            }
#pragma unroll
            for (int np = 0; np < 4; np++) {
                const uint32_t addr =
                    sb + ((AK_E + stage * KSTG + (np * 16 + lrow) * AST) +
                          k * 16 + lcol8) * 2;
                uint32_t b0, b1, b2, b3;
                ldsm4(b0, b1, b2, b3, addr);
                bfr[np * 2 + 0][0] = b0; bfr[np * 2 + 1][0] = b1;
                bfr[np * 2 + 0][1] = b2; bfr[np * 2 + 1][1] = b3;
            }
#pragma unroll
            for (int nt = 0; nt < 8; nt++)
                mma16(sc[nt], a, bfr[nt][0], bfr[nt][1]);
        }

        // ---- online softmax (per row-half) ----
        const int* mstg = ms + stage * 64;
#pragma unroll
        for (int hf = 0; hf < 2; hf++) {
            float rm = -1e30f;
#pragma unroll
            for (int nt = 0; nt < 8; nt++) {
                const int c0 = nt * 8 + cc * 2;
                const float m0v = mstg[c0] ? 0.f : -1e9f;
                const float m1v = mstg[c0 + 1] ? 0.f : -1e9f;
                float v0 = fmaf(sc[nt][hf * 2 + 0], scale, m0v);
                float v1 = fmaf(sc[nt][hf * 2 + 1], scale, m1v);
                sc[nt][hf * 2 + 0] = v0;
                sc[nt][hf * 2 + 1] = v1;
                rm = fmaxf(rm, fmaxf(v0, v1));
            }
            rm = fmaxf(rm, __shfl_xor_sync(0xffffffffu, rm, 1));
            rm = fmaxf(rm, __shfl_xor_sync(0xffffffffu, rm, 2));
            const float mnew = fmaxf(mst[hf], rm);
            const float cf = __expf(mst[hf] - mnew);
            mst[hf] = mnew;
            float rs = 0.f;
#pragma unroll
            for (int nt = 0; nt < 8; nt++) {
                float p0 = __expf(sc[nt][hf * 2 + 0] - mnew);
                float p1 = __expf(sc[nt][hf * 2 + 1] - mnew);
                sc[nt][hf * 2 + 0] = p0;
                sc[nt][hf * 2 + 1] = p1;
                rs += p0 + p1;
            }
            rs += __shfl_xor_sync(0xffffffffu, rs, 1);
            rs += __shfl_xor_sync(0xffffffffu, rs, 2);
            lst[hf] = lst[hf] * cf + rs;
#pragma unroll
            for (int nt = 0; nt < 8; nt++) {
                ob[nt][hf * 2 + 0] *= cf;
                ob[nt][hf * 2 + 1] *= cf;
            }
        }

        // ---- O += P V, P direct from registers ----
#pragma unroll
        for (int kc = 0; kc < 4; kc++) {
            uint32_t a[4], bfr[8][2];
            a[0] = packbf(sc[2 * kc][0], sc[2 * kc][1]);
            a[1] = packbf(sc[2 * kc][2], sc[2 * kc][3]);
            a[2] = packbf(sc[2 * kc + 1][0], sc[2 * kc + 1][1]);
            a[3] = packbf(sc[2 * kc + 1][2], sc[2 * kc + 1][3]);
#pragma unroll
            for (int np = 0; np < 4; np++) {
                const uint32_t addr =
                    sb + ((AV_E + stage * KSTG + (kc * 16 + lrow_t) * AST) +
                          np * 16 + dsel) * 2;
                uint32_t b0, b1, b2, b3;
                ldsm4t(b0, b1, b2, b3, addr);
                bfr[np * 2 + 0][0] = b0; bfr[np * 2 + 1][0] = b1;
                bfr[np * 2 + 0][1] = b2; bfr[np * 2 + 1][1] = b3;
            }
#pragma unroll
            for (int nt = 0; nt < 8; nt++)
                mma16(ob[nt], a, bfr[nt][0], bfr[nt][1]);
        }
        // no trailing sync: top-of-loop sync at t+1 proves tile-t consumption
        // before stage (t+3)%3 == stage t reissue at loop t+1.
    }

    // epilogue: O = ob / l (bf16 out)
#pragma unroll
    for (int hf = 0; hf < 2; hf++) {
        const float inv = 1.0f / lst[hf];
        const int row = q0 + qb + g + hf * 8;
#pragma unroll
        for (int nt = 0; nt < 8; nt++) {
            const int col = h * HD + nt * 8 + cc * 2;
            *(uint32_t*)(O + (size_t)(b * S + row) * D + col) =
                packbf(ob[nt][hf * 2 + 0] * inv, ob[nt][hf * 2 + 1] * inv);
        }
    }
}

// ---------------- LayerNorm over D, one block per row ------------------------
__global__ __launch_bounds__(256) void ln_kernel(
    const float* __restrict__ Y, const float* __restrict__ gamma,
    const float* __restrict__ beta, float* __restrict__ out)
{
    __shared__ float r1[256], r2[256];
    const int row = blockIdx.x;
    const int tid = threadIdx.x;
    const float* y = Y + (size_t)row * D;

    float s = 0.f, s2 = 0.f;
    for (int i = tid; i < D; i += 256) {
        const float v = y[i];
        s += v;
        s2 = fmaf(v, v, s2);
    }
    r1[tid] = s; r2[tid] = s2;
    __syncthreads();
    for (int o = 128; o > 0; o >>= 1) {
        if (tid < o) { r1[tid] += r1[tid + o]; r2[tid] += r2[tid + o]; }
        __syncthreads();
    }
    const float mu = r1[0] * (1.0f / D);
    const float var = r2[0] * (1.0f / D) - mu * mu;
    const float inv = rsqrtf(var + 1e-5f);

    float* o = out + (size_t)row * D;
    for (int i = tid; i < D; i += 256)
        o[i] = (y[i] - mu) * inv * gamma[i] + beta[i];
}

// ---------------- launch ------------------------------------------------------
extern "C" void kernel_launch(void* const* d_in, const int* in_sizes, int n_in,
                              void* d_out, int out_size)
{
    const float* x     = (const float*)d_in[0];
    const int*   mask  = (const int*)d_in[1];
    const float* Wq    = (const float*)d_in[2];
    const float* bq    = (const float*)d_in[3];
    const float* Wk    = (const float*)d_in[4];
    const float* bk    = (const float*)d_in[5];
    const float* Wv    = (const float*)d_in[6];
    const float* bv    = (const float*)d_in[7];
    const float* Wo    = (const float*)d_in[8];
    const float* bo    = (const float*)d_in[9];
    const float* gamma = (const float*)d_in[10];
    const float* beta  = (const float*)d_in[11];

    __nv_bfloat16 *Xb, *Wb, *Qb, *Kb, *Vb, *Cb;
    float* Yp;
    cudaGetSymbolAddress((void**)&Xb, g_Xb);
    cudaGetSymbolAddress((void**)&Wb, g_Wb);
    cudaGetSymbolAddress((void**)&Qb, g_Qb);
    cudaGetSymbolAddress((void**)&Kb, g_Kb);
    cudaGetSymbolAddress((void**)&Vb, g_Vb);
    cudaGetSymbolAddress((void**)&Cb, g_Cb);
    cudaGetSymbolAddress((void**)&Yp, g_Y);

    cudaFuncSetAttribute(qkv_gemm,
                         cudaFuncAttributeMaxDynamicSharedMemorySize, GEMM_SMEM);
    cudaFuncSetAttribute(out_gemm,
                         cudaFuncAttributeMaxDynamicSharedMemorySize, GEMM_SMEM);
    cudaFuncSetAttribute(attn_mma,
                         cudaFuncAttributeMaxDynamicSharedMemorySize, ATT_SMEM);

    const int nX4 = NR * D / 4, nW4 = D * D / 4;
    cvt_bf16<<<nX4 / 256, 256>>>(x, Xb, nX4);
    cvt_bf16<<<nW4 / 256, 256>>>(Wq, Wb + (size_t)0 * D * D, nW4);
    cvt_bf16<<<nW4 / 256, 256>>>(Wk, Wb + (size_t)1 * D * D, nW4);
    cvt_bf16<<<nW4 / 256, 256>>>(Wv, Wb + (size_t)2 * D * D, nW4);
    cvt_bf16<<<nW4 / 256, 256>>>(Wo, Wb + (size_t)3 * D * D, nW4);

    QKVOut io;
    io.out[0] = Qb; io.out[1] = Kb; io.out[2] = Vb;
    io.bias[0] = bq; io.bias[1] = bk; io.bias[2] = bv;
    qkv_gemm<<<dim3(24, NR / 128), 256, GEMM_SMEM>>>(Xb, Wb, io);

    attn_mma<<<dim3(S / 256, H, B), 512, ATT_SMEM>>>(Qb, Kb, Vb, mask, Cb);

    out_gemm<<<dim3(8, NR / 128), 256, GEMM_SMEM>>>(
        Cb, Wb + (size_t)3 * D * D, bo, x, Yp);
    ln_kernel<<<NR, 256>>>(Yp, gamma, beta, (float*)d_out);
}

// round 8
// speedup vs baseline: 7.2880x; 1.0442x over previous
#include <cuda_runtime.h>
#include <cuda_bf16.h>
#include <cstdint>
#include <math.h>

constexpr int B = 4, S = 2048, D = 1024, H = 16, HD = 64;
constexpr int NR = B * S;  // 8192 rows

// ---------------- scratch (static device globals; no allocation) -------------
__device__ __nv_bfloat16 g_Xb[(size_t)NR * D];      // x bf16
__device__ __nv_bfloat16 g_Wb[(size_t)4 * D * D];   // Wq,Wk,Wv,Wo bf16
__device__ __nv_bfloat16 g_Qb[(size_t)NR * D];
__device__ __nv_bfloat16 g_Kb[(size_t)NR * D];
__device__ __nv_bfloat16 g_Vb[(size_t)NR * D];
__device__ __nv_bfloat16 g_Cb[(size_t)NR * D];      // attention out bf16
__device__ float         g_Y[(size_t)NR * D];

// ======================= helpers ============================================
__device__ __forceinline__ uint32_t smem_u32(const void* p) {
    uint32_t a;
    asm("{ .reg .u64 t; cvta.to.shared.u64 t, %1; cvt.u32.u64 %0, t; }"
        : "=r"(a) : "l"(p));
    return a;
}
__device__ __forceinline__ void ldsm4(uint32_t& r0, uint32_t& r1, uint32_t& r2,
                                      uint32_t& r3, uint32_t addr) {
    asm volatile("ldmatrix.sync.aligned.m8n8.x4.shared.b16 {%0,%1,%2,%3}, [%4];"
                 : "=r"(r0), "=r"(r1), "=r"(r2), "=r"(r3) : "r"(addr));
}
__device__ __forceinline__ void ldsm4t(uint32_t& r0, uint32_t& r1, uint32_t& r2,
                                       uint32_t& r3, uint32_t addr) {
    asm volatile("ldmatrix.sync.aligned.m8n8.x4.trans.shared.b16 {%0,%1,%2,%3}, [%4];"
                 : "=r"(r0), "=r"(r1), "=r"(r2), "=r"(r3) : "r"(addr));
}
__device__ __forceinline__ void mma16(float (&c)[4], const uint32_t (&a)[4],
                                      uint32_t b0, uint32_t b1) {
    asm volatile(
        "mma.sync.aligned.m16n8k16.row.col.f32.bf16.bf16.f32 "
        "{%0,%1,%2,%3}, {%4,%5,%6,%7}, {%8,%9}, {%0,%1,%2,%3};"
        : "+f"(c[0]), "+f"(c[1]), "+f"(c[2]), "+f"(c[3])
        : "r"(a[0]), "r"(a[1]), "r"(a[2]), "r"(a[3]), "r"(b0), "r"(b1));
}
__device__ __forceinline__ void cp_async16(uint32_t s, const void* g) {
    asm volatile("cp.async.cg.shared.global [%0], [%1], 16;" :: "r"(s), "l"(g));
}
__device__ __forceinline__ void cp_commit() {
    asm volatile("cp.async.commit_group;" ::: "memory");
}
template <int N>
__device__ __forceinline__ void cp_wait() {
    asm volatile("cp.async.wait_group %0;" :: "n"(N) : "memory");
}
__device__ __forceinline__ uint32_t packbf(float x, float y) {
    __nv_bfloat162 p = __floats2bfloat162_rn(x, y);
    return *(uint32_t*)&p;
}

// ======================= fp32 -> bf16 prep ===================================
__global__ __launch_bounds__(256) void cvt_bf16(const float* __restrict__ in,
                                                __nv_bfloat16* __restrict__ out,
                                                int n4)
{
    const int i = (blockIdx.x * 256 + threadIdx.x) * 4;
    if (i < n4 * 4) {
        float4 v = *(const float4*)(in + i);
        uint2 u;
        u.x = packbf(v.x, v.y);
        u.y = packbf(v.z, v.w);
        *(uint2*)(out + i) = u;
    }
}

struct WPtrs { const float* w[4]; };

__global__ __launch_bounds__(256) void cvt_w4(WPtrs ws,
                                              __nv_bfloat16* __restrict__ out)
{
    const int i = (blockIdx.x * 256 + threadIdx.x) * 4;
    const float* in = ws.w[blockIdx.y];
    __nv_bfloat16* o = out + (size_t)blockIdx.y * D * D;
    float4 v = *(const float4*)(in + i);
    uint2 u;
    u.x = packbf(v.x, v.y);
    u.y = packbf(v.z, v.w);
    *(uint2*)(o + i) = u;
}

// ======================= bf16 mma GEMM core =================================
// 128x128 block tile, 4 warps, warp tile 64x64. 2-stage cp.async, BK=64.
constexpr int GST = 72;                 // smem row stride (bf16 elems)
constexpr int G_STAGE = 256 * GST;      // bf16 elems per stage
constexpr int GEMM_SMEM = 2 * G_STAGE * 2;  // 73728 B

struct QKVOut {
    __nv_bfloat16* out[3];
    const float* bias[3];
};

template <typename AccFn>
__device__ __forceinline__ void gemm_body(
    const __nv_bfloat16* __restrict__ A, const __nv_bfloat16* __restrict__ W,
    int n0, int m0, __nv_bfloat16* gsm, AccFn&& emit)
{
    const int tid = threadIdx.x;
    const int lane = tid & 31, wid = tid >> 5;   // 4 warps
    const int wr = wid >> 1, wc = wid & 1;        // 2x2 warp grid, 64x64 each
    const int lrow = lane & 15;
    const int lcol8 = (lane >> 4) * 8;
    const uint32_t sbase = smem_u32(gsm);

    float acc[4][8][4];
#pragma unroll
    for (int mt = 0; mt < 4; mt++)
#pragma unroll
        for (int nt = 0; nt < 8; nt++)
#pragma unroll
            for (int q = 0; q < 4; q++) acc[mt][nt][q] = 0.f;

    auto issue_chunk = [&](int c) {
        const int k0 = c * 64;
        const uint32_t stb = sbase + (c & 1) * G_STAGE * 2;
#pragma unroll
        for (int i = 0; i < 16; i++) {
            const int idx = tid + i * 128;
            const int t = idx & 1023;
            const int row = t >> 3, c8 = (t & 7) * 8;
            const __nv_bfloat16* g =
                (idx < 1024 ? A + (size_t)(n0 + row) * D
                            : W + (size_t)(m0 + row) * D) + k0 + c8;
            const int srow = row + (idx < 1024 ? 0 : 128);
            cp_async16(stb + (srow * GST + c8) * 2, g);
        }
        cp_commit();
    };

    issue_chunk(0);
    for (int c = 0; c < 16; c++) {
        if (c < 15) issue_chunk(c + 1);
        if (c < 15) cp_wait<1>(); else cp_wait<0>();
        __syncthreads();

        const uint32_t stb = sbase + (c & 1) * G_STAGE * 2;
#pragma unroll
        for (int k = 0; k < 4; k++) {
            uint32_t a[4][4];
            uint32_t bfr[8][2];
#pragma unroll
            for (int mt = 0; mt < 4; mt++) {
                const uint32_t addr =
                    stb + ((wr * 64 + mt * 16 + lrow) * GST + k * 16 + lcol8) * 2;
                ldsm4(a[mt][0], a[mt][1], a[mt][2], a[mt][3], addr);
            }
#pragma unroll
            for (int np = 0; np < 4; np++) {
                const uint32_t addr =
                    stb + ((128 + wc * 64 + np * 16 + lrow) * GST + k * 16 + lcol8) * 2;
                uint32_t b0, b1, b2, b3;
                ldsm4(b0, b1, b2, b3, addr);
                bfr[np * 2 + 0][0] = b0; bfr[np * 2 + 1][0] = b1;
                bfr[np * 2 + 0][1] = b2; bfr[np * 2 + 1][1] = b3;
            }
#pragma unroll
            for (int mt = 0; mt < 4; mt++)
#pragma unroll
                for (int nt = 0; nt < 8; nt++)
                    mma16(acc[mt][nt], a[mt], bfr[nt][0], bfr[nt][1]);
        }
        __syncthreads();
    }

    const int g = lane >> 2, cc = lane & 3;
#pragma unroll
    for (int mt = 0; mt < 4; mt++)
#pragma unroll
        for (int hf = 0; hf < 2; hf++) {
            const int row = n0 + wr * 64 + mt * 16 + g + hf * 8;
#pragma unroll
            for (int nt = 0; nt < 8; nt++) {
                const int col = m0 + wc * 64 + nt * 8 + cc * 2;
                emit(row, col, acc[mt][nt][hf * 2 + 0], acc[mt][nt][hf * 2 + 1]);
            }
        }
}

// Fused QKV projection: grid.x in [0,24): sel = x>>3, m-block = x&7.
__global__ __launch_bounds__(128, 2) void qkv_gemm(
    const __nv_bfloat16* __restrict__ A, const __nv_bfloat16* __restrict__ Wall,
    QKVOut io)
{
    extern __shared__ __nv_bfloat16 gsm[];
    const int sel = blockIdx.x >> 3;
    const int m0 = (blockIdx.x & 7) * 128;
    const int n0 = blockIdx.y * 128;
    const __nv_bfloat16* W = Wall + (size_t)sel * D * D;
    __nv_bfloat16* out = io.out[sel];
    const float* bias = io.bias[sel];

    gemm_body(A, W, n0, m0, gsm,
              [&](int row, int col, float vx, float vy) {
                  float2 bv = *(const float2*)(bias + col);
                  *(uint32_t*)(out + (size_t)row * D + col) =
                      packbf(vx + bv.x, vy + bv.y);
              });
}

// Output projection with residual, fp32 out.
__global__ __launch_bounds__(128, 2) void out_gemm(
    const __nv_bfloat16* __restrict__ A, const __nv_bfloat16* __restrict__ W,
    const float* __restrict__ bias, const float* __restrict__ R,
    float* __restrict__ C)
{
    extern __shared__ __nv_bfloat16 gsm[];
    const int m0 = blockIdx.x * 128;
    const int n0 = blockIdx.y * 128;

    gemm_body(A, W, n0, m0, gsm,
              [&](int row, int col, float vx, float vy) {
                  float2 bv = *(const float2*)(bias + col);
                  float2 rv = *(const float2*)(R + (size_t)row * D + col);
                  float2 o;
                  o.x = vx + bv.x + rv.x;
                  o.y = vy + bv.y + rv.y;
                  *(float2*)(C + (size_t)row * D + col) = o;
              });
}

// ======================= bf16 mma flash attention ===========================
// Block: 256 q rows, 16 warps x 16 rows. 64-key tiles, 3-stage cp.async,
// P passed through registers, V via ldmatrix.trans, exp2-domain softmax.
constexpr int AST = 72;
constexpr int AQ_E = 0;
constexpr int AK_E = 256 * AST;
constexpr int AV_E = AK_E + 3 * 64 * AST;
constexpr int AEND_E = AV_E + 3 * 64 * AST;
constexpr int AM_BYTE = AEND_E * 2;
constexpr int ATT_SMEM = AM_BYTE + 3 * 64 * 4;
constexpr int KSTG = 64 * AST;

__global__ __launch_bounds__(512) void attn_mma(
    const __nv_bfloat16* __restrict__ Q, const __nv_bfloat16* __restrict__ K,
    const __nv_bfloat16* __restrict__ V, const int* __restrict__ mask,
    __nv_bfloat16* __restrict__ O)
{
    extern __shared__ __nv_bfloat16 smb[];
    int* ms = (int*)((char*)smb + AM_BYTE);
    const int tid = threadIdx.x, lane = tid & 31, wid = tid >> 5;
    const int b = blockIdx.z, h = blockIdx.y, q0 = blockIdx.x * 256;
    const uint32_t sb = smem_u32(smb);
    const int lrow = lane & 15;
    const int lcol8 = (lane >> 4) * 8;
    const int lrow_t = (lane & 7) + ((lane >> 4) << 3);
    const int dsel = ((lane >> 3) & 1) * 8;
    const int g = lane >> 2, cc = lane & 3;
    const int qb = wid * 16;
    // exp2-domain: scores scaled by (1/sqrt(64)) * log2(e)
    const float scale2 = 0.125f * 1.44269504f;
    const float mneg2 = -1.44269504e9f;   // -1e9 * log2(e)

    // Q tile (256 x 64 bf16) via cp.async
#pragma unroll
    for (int i = 0; i < 4; i++) {
        const int idx = tid + i * 512;
        const int row = idx >> 3, c8 = (idx & 7) * 8;
        cp_async16(sb + (AQ_E + row * AST + c8) * 2,
                   Q + (size_t)(b * S + q0 + row) * D + h * HD + c8);
    }
    cp_commit();

    auto issueKV = [&](int t) {
        const int k0 = t * 64;
        const int stage = t % 3;
        const int row = tid >> 3, c8 = (tid & 7) * 8;
        cp_async16(sb + ((AK_E + stage * KSTG) + row * AST + c8) * 2,
                   K + (size_t)(b * S + k0 + row) * D + h * HD + c8);
        cp_async16(sb + ((AV_E + stage * KSTG) + row * AST + c8) * 2,
                   V + (size_t)(b * S + k0 + row) * D + h * HD + c8);
        if (tid < 16)
            cp_async16(sb + AM_BYTE + stage * 256 + tid * 16,
                       mask + b * S + k0 + tid * 4);
        cp_commit();
    };

    issueKV(0);
    issueKV(1);

    float ob[8][4];
#pragma unroll
    for (int nt = 0; nt < 8; nt++)
#pragma unroll
        for (int q = 0; q < 4; q++) ob[nt][q] = 0.f;
    float mst[2], lst[2];
    mst[0] = mst[1] = -1e30f;
    lst[0] = lst[1] = 0.f;

    constexpr int NT = S / 64;
    for (int t = 0; t < NT; t++) {
        const int stage = t % 3;
        if (t + 1 < NT) cp_wait<1>(); else cp_wait<0>();
        __syncthreads();
        if (t + 2 < NT) issueKV(t + 2);

        // ---- S = Q K^T ----
        float sc[8][4];
#pragma unroll
        for (int nt = 0; nt < 8; nt++)
#pragma unroll
            for (int q = 0; q < 4; q++) sc[nt][q] = 0.f;

#pragma unroll
        for (int k = 0; k < 4; k++) {
            uint32_t a[4], bfr[8][2];
            {
                const uint32_t addr =
                    sb + ((AQ_E + (qb + lrow) * AST) + k * 16 + lcol8) * 2;
                ldsm4(a[0], a[1], a[2], a[3], addr);
            }
#pragma unroll
            for (int np = 0; np < 4; np++) {
                const uint32_t addr =
                    sb + ((AK_E + stage * KSTG + (np * 16 + lrow) * AST) +
                          k * 16 + lcol8) * 2;
                uint32_t b0, b1, b2, b3;
                ldsm4(b0, b1, b2, b3, addr);
                bfr[np * 2 + 0][0] = b0; bfr[np * 2 + 1][0] = b1;
                bfr[np * 2 + 0][1] = b2; bfr[np * 2 + 1][1] = b3;
            }
#pragma unroll
            for (int nt = 0; nt < 8; nt++)
                mma16(sc[nt], a, bfr[nt][0], bfr[nt][1]);
        }

        // ---- online softmax, log2 domain ----
        const int* mstg = ms + stage * 64;
#pragma unroll
        for (int hf = 0; hf < 2; hf++) {
            float rm = -1e30f;
#pragma unroll
            for (int nt = 0; nt < 8; nt++) {
                const int c0 = nt * 8 + cc * 2;
                const float m0v = mstg[c0] ? 0.f : mneg2;
                const float m1v = mstg[c0 + 1] ? 0.f : mneg2;
                float v0 = fmaf(sc[nt][hf * 2 + 0], scale2, m0v);
                float v1 = fmaf(sc[nt][hf * 2 + 1], scale2, m1v);
                sc[nt][hf * 2 + 0] = v0;
                sc[nt][hf * 2 + 1] = v1;
                rm = fmaxf(rm, fmaxf(v0, v1));
            }
            rm = fmaxf(rm, __shfl_xor_sync(0xffffffffu, rm, 1));
            rm = fmaxf(rm, __shfl_xor_sync(0xffffffffu, rm, 2));
            const float mnew = fmaxf(mst[hf], rm);
            const float cf = exp2f(mst[hf] - mnew);
            mst[hf] = mnew;
            float rs = 0.f;
#pragma unroll
            for (int nt = 0; nt < 8; nt++) {
                float p0 = exp2f(sc[nt][hf * 2 + 0] - mnew);
                float p1 = exp2f(sc[nt][hf * 2 + 1] - mnew);
                sc[nt][hf * 2 + 0] = p0;
                sc[nt][hf * 2 + 1] = p1;
                rs += p0 + p1;
            }
            rs += __shfl_xor_sync(0xffffffffu, rs, 1);
            rs += __shfl_xor_sync(0xffffffffu, rs, 2);
            lst[hf] = lst[hf] * cf + rs;
#pragma unroll
            for (int nt = 0; nt < 8; nt++) {
                ob[nt][hf * 2 + 0] *= cf;
                ob[nt][hf * 2 + 1] *= cf;
            }
        }

        // ---- O += P V, P direct from registers ----
#pragma unroll
        for (int kc = 0; kc < 4; kc++) {
            uint32_t a[4], bfr[8][2];
            a[0] = packbf(sc[2 * kc][0], sc[2 * kc][1]);
            a[1] = packbf(sc[2 * kc][2], sc[2 * kc][3]);
            a[2] = packbf(sc[2 * kc + 1][0], sc[2 * kc + 1][1]);
            a[3] = packbf(sc[2 * kc + 1][2], sc[2 * kc + 1][3]);
#pragma unroll
            for (int np = 0; np < 4; np++) {
                const uint32_t addr =
                    sb + ((AV_E + stage * KSTG + (kc * 16 + lrow_t) * AST) +
                          np * 16 + dsel) * 2;
                uint32_t b0, b1, b2, b3;
                ldsm4t(b0, b1, b2, b3, addr);
                bfr[np * 2 + 0][0] = b0; bfr[np * 2 + 1][0] = b1;
                bfr[np * 2 + 0][1] = b2; bfr[np * 2 + 1][1] = b3;
            }
#pragma unroll
            for (int nt = 0; nt < 8; nt++)
                mma16(ob[nt], a, bfr[nt][0], bfr[nt][1]);
        }
    }

    // epilogue
#pragma unroll
    for (int hf = 0; hf < 2; hf++) {
        const float inv = 1.0f / lst[hf];
        const int row = q0 + qb + g + hf * 8;
#pragma unroll
        for (int nt = 0; nt < 8; nt++) {
            const int col = h * HD + nt * 8 + cc * 2;
            *(uint32_t*)(O + (size_t)(b * S + row) * D + col) =
                packbf(ob[nt][hf * 2 + 0] * inv, ob[nt][hf * 2 + 1] * inv);
        }
    }
}

// ---------------- LayerNorm: warp per row, shuffle reduce --------------------
__global__ __launch_bounds__(256) void ln_kernel(
    const float* __restrict__ Y, const float* __restrict__ gamma,
    const float* __restrict__ beta, float* __restrict__ out)
{
    const int lane = threadIdx.x & 31, wid = threadIdx.x >> 5;
    const int row = blockIdx.x * 8 + wid;
    const float* y = Y + (size_t)row * D;

    float s = 0.f, s2 = 0.f;
    float4 v[8];
#pragma unroll
    for (int i = 0; i < 8; i++) {
        v[i] = *(const float4*)(y + lane * 4 + i * 128);
        s += v[i].x + v[i].y + v[i].z + v[i].w;
        s2 = fmaf(v[i].x, v[i].x, s2);
        s2 = fmaf(v[i].y, v[i].y, s2);
        s2 = fmaf(v[i].z, v[i].z, s2);
        s2 = fmaf(v[i].w, v[i].w, s2);
    }
#pragma unroll
    for (int o = 16; o > 0; o >>= 1) {
        s  += __shfl_xor_sync(0xffffffffu, s, o);
        s2 += __shfl_xor_sync(0xffffffffu, s2, o);
    }
    const float mu = s * (1.0f / D);
    const float var = s2 * (1.0f / D) - mu * mu;
    const float inv = rsqrtf(var + 1e-5f);

    float* o = out + (size_t)row * D;
#pragma unroll
    for (int i = 0; i < 8; i++) {
        const int c = lane * 4 + i * 128;
        float4 gv = *(const float4*)(gamma + c);
        float4 bv = *(const float4*)(beta + c);
        float4 r;
        r.x = (v[i].x - mu) * inv * gv.x + bv.x;
        r.y = (v[i].y - mu) * inv * gv.y + bv.y;
        r.z = (v[i].z - mu) * inv * gv.z + bv.z;
        r.w = (v[i].w - mu) * inv * gv.w + bv.w;
        *(float4*)(o + c) = r;
    }
}

// ---------------- launch ------------------------------------------------------
extern "C" void kernel_launch(void* const* d_in, const int* in_sizes, int n_in,
                              void* d_out, int out_size)
{
    const float* x     = (const float*)d_in[0];
    const int*   mask  = (const int*)d_in[1];
    const float* Wq    = (const float*)d_in[2];
    const float* bq    = (const float*)d_in[3];
    const float* Wk    = (const float*)d_in[4];
    const float* bk    = (const float*)d_in[5];
    const float* Wv    = (const float*)d_in[6];
    const float* bv    = (const float*)d_in[7];
    const float* Wo    = (const float*)d_in[8];
    const float* bo    = (const float*)d_in[9];
    const float* gamma = (const float*)d_in[10];
    const float* beta  = (const float*)d_in[11];

    __nv_bfloat16 *Xb, *Wb, *Qb, *Kb, *Vb, *Cb;
    float* Yp;
    cudaGetSymbolAddress((void**)&Xb, g_Xb);
    cudaGetSymbolAddress((void**)&Wb, g_Wb);
    cudaGetSymbolAddress((void**)&Qb, g_Qb);
    cudaGetSymbolAddress((void**)&Kb, g_Kb);
    cudaGetSymbolAddress((void**)&Vb, g_Vb);
    cudaGetSymbolAddress((void**)&Cb, g_Cb);
    cudaGetSymbolAddress((void**)&Yp, g_Y);

    cudaFuncSetAttribute(qkv_gemm,
                         cudaFuncAttributeMaxDynamicSharedMemorySize, GEMM_SMEM);
    cudaFuncSetAttribute(out_gemm,
                         cudaFuncAttributeMaxDynamicSharedMemorySize, GEMM_SMEM);
    cudaFuncSetAttribute(attn_mma,
                         cudaFuncAttributeMaxDynamicSharedMemorySize, ATT_SMEM);

    const int nX4 = NR * D / 4, nW4 = D * D / 4;
    cvt_bf16<<<nX4 / 256, 256>>>(x, Xb, nX4);
    WPtrs ws;
    ws.w[0] = Wq; ws.w[1] = Wk; ws.w[2] = Wv; ws.w[3] = Wo;
    cvt_w4<<<dim3(nW4 / 256, 4), 256>>>(ws, Wb);

    QKVOut io;
    io.out[0] = Qb; io.out[1] = Kb; io.out[2] = Vb;
    io.bias[0] = bq; io.bias[1] = bk; io.bias[2] = bv;
    qkv_gemm<<<dim3(24, NR / 128), 128, GEMM_SMEM>>>(Xb, Wb, io);

    attn_mma<<<dim3(S / 256, H, B), 512, ATT_SMEM>>>(Qb, Kb, Vb, mask, Cb);

    out_gemm<<<dim3(8, NR / 128), 128, GEMM_SMEM>>>(
        Cb, Wb + (size_t)3 * D * D, bo, x, Yp);
    ln_kernel<<<NR / 8, 256>>>(Yp, gamma, beta, (float*)d_out);
}

// round 9
// speedup vs baseline: 7.5541x; 1.0365x over previous
#include <cuda_runtime.h>
#include <cuda_bf16.h>
#include <cstdint>
#include <math.h>

constexpr int B = 4, S = 2048, D = 1024, H = 16, HD = 64;
constexpr int NR = B * S;  // 8192 rows

// ---------------- scratch (static device globals; no allocation) -------------
__device__ __nv_bfloat16 g_Xb[(size_t)NR * D];      // x bf16
__device__ __nv_bfloat16 g_Wb[(size_t)4 * D * D];   // Wq,Wk,Wv,Wo bf16
__device__ __nv_bfloat16 g_Qb[(size_t)NR * D];
__device__ __nv_bfloat16 g_Kb[(size_t)NR * D];
__device__ __nv_bfloat16 g_Vb[(size_t)NR * D];
__device__ __nv_bfloat16 g_Cb[(size_t)NR * D];      // attention out bf16
__device__ float         g_Y[(size_t)NR * D];

// ======================= helpers ============================================
__device__ __forceinline__ uint32_t smem_u32(const void* p) {
    uint32_t a;
    asm("{ .reg .u64 t; cvta.to.shared.u64 t, %1; cvt.u32.u64 %0, t; }"
        : "=r"(a) : "l"(p));
    return a;
}
__device__ __forceinline__ void ldsm4(uint32_t& r0, uint32_t& r1, uint32_t& r2,
                                      uint32_t& r3, uint32_t addr) {
    asm volatile("ldmatrix.sync.aligned.m8n8.x4.shared.b16 {%0,%1,%2,%3}, [%4];"
                 : "=r"(r0), "=r"(r1), "=r"(r2), "=r"(r3) : "r"(addr));
}
__device__ __forceinline__ void ldsm4t(uint32_t& r0, uint32_t& r1, uint32_t& r2,
                                       uint32_t& r3, uint32_t addr) {
    asm volatile("ldmatrix.sync.aligned.m8n8.x4.trans.shared.b16 {%0,%1,%2,%3}, [%4];"
                 : "=r"(r0), "=r"(r1), "=r"(r2), "=r"(r3) : "r"(addr));
}
__device__ __forceinline__ void mma16(float (&c)[4], const uint32_t (&a)[4],
                                      uint32_t b0, uint32_t b1) {
    asm volatile(
        "mma.sync.aligned.m16n8k16.row.col.f32.bf16.bf16.f32 "
        "{%0,%1,%2,%3}, {%4,%5,%6,%7}, {%8,%9}, {%0,%1,%2,%3};"
        : "+f"(c[0]), "+f"(c[1]), "+f"(c[2]), "+f"(c[3])
        : "r"(a[0]), "r"(a[1]), "r"(a[2]), "r"(a[3]), "r"(b0), "r"(b1));
}
__device__ __forceinline__ void cp_async16(uint32_t s, const void* g) {
    asm volatile("cp.async.cg.shared.global [%0], [%1], 16;" :: "r"(s), "l"(g));
}
__device__ __forceinline__ void cp_commit() {
    asm volatile("cp.async.commit_group;" ::: "memory");
}
template <int N>
__device__ __forceinline__ void cp_wait() {
    asm volatile("cp.async.wait_group %0;" :: "n"(N) : "memory");
}
__device__ __forceinline__ uint32_t packbf(float x, float y) {
    __nv_bfloat162 p = __floats2bfloat162_rn(x, y);
    return *(uint32_t*)&p;
}

// ======================= fp32 -> bf16 prep ===================================
__global__ __launch_bounds__(256) void cvt_bf16(const float* __restrict__ in,
                                                __nv_bfloat16* __restrict__ out,
                                                int n4)
{
    const int i = (blockIdx.x * 256 + threadIdx.x) * 4;
    if (i < n4 * 4) {
        float4 v = *(const float4*)(in + i);
        uint2 u;
        u.x = packbf(v.x, v.y);
        u.y = packbf(v.z, v.w);
        *(uint2*)(out + i) = u;
    }
}

struct WPtrs { const float* w[4]; };

__global__ __launch_bounds__(256) void cvt_w4(WPtrs ws,
                                              __nv_bfloat16* __restrict__ out)
{
    const int i = (blockIdx.x * 256 + threadIdx.x) * 4;
    const float* in = ws.w[blockIdx.y];
    __nv_bfloat16* o = out + (size_t)blockIdx.y * D * D;
    float4 v = *(const float4*)(in + i);
    uint2 u;
    u.x = packbf(v.x, v.y);
    u.y = packbf(v.z, v.w);
    *(uint2*)(o + i) = u;
}

// ======================= bf16 mma GEMM core =================================
// 128x128 block tile, 4 warps, warp tile 64x64. 2-stage cp.async, BK=64.
constexpr int GST = 72;                 // smem row stride (bf16 elems)
constexpr int G_STAGE = 256 * GST;      // bf16 elems per stage
constexpr int GEMM_SMEM = 2 * G_STAGE * 2;  // 73728 B

struct QKVOut {
    __nv_bfloat16* out[3];
    const float* bias[3];
};

template <typename AccFn>
__device__ __forceinline__ void gemm_body(
    const __nv_bfloat16* __restrict__ A, const __nv_bfloat16* __restrict__ W,
    int n0, int m0, __nv_bfloat16* gsm, AccFn&& emit)
{
    const int tid = threadIdx.x;
    const int lane = tid & 31, wid = tid >> 5;   // 4 warps
    const int wr = wid >> 1, wc = wid & 1;        // 2x2 warp grid, 64x64 each
    const int lrow = lane & 15;
    const int lcol8 = (lane >> 4) * 8;
    const uint32_t sbase = smem_u32(gsm);

    float acc[4][8][4];
#pragma unroll
    for (int mt = 0; mt < 4; mt++)
#pragma unroll
        for (int nt = 0; nt < 8; nt++)
#pragma unroll
            for (int q = 0; q < 4; q++) acc[mt][nt][q] = 0.f;

    auto issue_chunk = [&](int c) {
        const int k0 = c * 64;
        const uint32_t stb = sbase + (c & 1) * G_STAGE * 2;
#pragma unroll
        for (int i = 0; i < 16; i++) {
            const int idx = tid + i * 128;
            const int t = idx & 1023;
            const int row = t >> 3, c8 = (t & 7) * 8;
            const __nv_bfloat16* g =
                (idx < 1024 ? A + (size_t)(n0 + row) * D
                            : W + (size_t)(m0 + row) * D) + k0 + c8;
            const int srow = row + (idx < 1024 ? 0 : 128);
            cp_async16(stb + (srow * GST + c8) * 2, g);
        }
        cp_commit();
    };

    issue_chunk(0);
    for (int c = 0; c < 16; c++) {
        if (c < 15) issue_chunk(c + 1);
        if (c < 15) cp_wait<1>(); else cp_wait<0>();
        __syncthreads();

        const uint32_t stb = sbase + (c & 1) * G_STAGE * 2;
#pragma unroll
        for (int k = 0; k < 4; k++) {
            uint32_t a[4][4];
            uint32_t bfr[8][2];
#pragma unroll
            for (int mt = 0; mt < 4; mt++) {
                const uint32_t addr =
                    stb + ((wr * 64 + mt * 16 + lrow) * GST + k * 16 + lcol8) * 2;
                ldsm4(a[mt][0], a[mt][1], a[mt][2], a[mt][3], addr);
            }
#pragma unroll
            for (int np = 0; np < 4; np++) {
                const uint32_t addr =
                    stb + ((128 + wc * 64 + np * 16 + lrow) * GST + k * 16 + lcol8) * 2;
                uint32_t b0, b1, b2, b3;
                ldsm4(b0, b1, b2, b3, addr);
                bfr[np * 2 + 0][0] = b0; bfr[np * 2 + 1][0] = b1;
                bfr[np * 2 + 0][1] = b2; bfr[np * 2 + 1][1] = b3;
            }
#pragma unroll
            for (int mt = 0; mt < 4; mt++)
#pragma unroll
                for (int nt = 0; nt < 8; nt++)
                    mma16(acc[mt][nt], a[mt], bfr[nt][0], bfr[nt][1]);
        }
        __syncthreads();
    }

    const int g = lane >> 2, cc = lane & 3;
#pragma unroll
    for (int mt = 0; mt < 4; mt++)
#pragma unroll
        for (int hf = 0; hf < 2; hf++) {
            const int row = n0 + wr * 64 + mt * 16 + g + hf * 8;
#pragma unroll
            for (int nt = 0; nt < 8; nt++) {
                const int col = m0 + wc * 64 + nt * 8 + cc * 2;
                emit(row, col, acc[mt][nt][hf * 2 + 0], acc[mt][nt][hf * 2 + 1]);
            }
        }
}

// Fused QKV projection: grid.x in [0,24): sel = x>>3, m-block = x&7.
__global__ __launch_bounds__(128, 2) void qkv_gemm(
    const __nv_bfloat16* __restrict__ A, const __nv_bfloat16* __restrict__ Wall,
    QKVOut io)
{
    extern __shared__ __nv_bfloat16 gsm[];
    const int sel = blockIdx.x >> 3;
    const int m0 = (blockIdx.x & 7) * 128;
    const int n0 = blockIdx.y * 128;
    const __nv_bfloat16* W = Wall + (size_t)sel * D * D;
    __nv_bfloat16* out = io.out[sel];
    const float* bias = io.bias[sel];

    gemm_body(A, W, n0, m0, gsm,
              [&](int row, int col, float vx, float vy) {
                  float2 bv = *(const float2*)(bias + col);
                  *(uint32_t*)(out + (size_t)row * D + col) =
                      packbf(vx + bv.x, vy + bv.y);
              });
}

// Output projection with residual, fp32 out.
__global__ __launch_bounds__(128, 2) void out_gemm(
    const __nv_bfloat16* __restrict__ A, const __nv_bfloat16* __restrict__ W,
    const float* __restrict__ bias, const float* __restrict__ R,
    float* __restrict__ C)
{
    extern __shared__ __nv_bfloat16 gsm[];
    const int m0 = blockIdx.x * 128;
    const int n0 = blockIdx.y * 128;

    gemm_body(A, W, n0, m0, gsm,
              [&](int row, int col, float vx, float vy) {
                  float2 bv = *(const float2*)(bias + col);
                  float2 rv = *(const float2*)(R + (size_t)row * D + col);
                  float2 o;
                  o.x = vx + bv.x + rv.x;
                  o.y = vy + bv.y + rv.y;
                  *(float2*)(C + (size_t)row * D + col) = o;
              });
}

// ======================= bf16 mma flash attention ===========================
// Block: 256 q rows, 16 warps x 16 rows. 64-key tiles, 3-stage cp.async,
// Q fragments hoisted, rotating stage offsets, per-lane deferred row sums.
constexpr int AST = 72;
constexpr int AQ_E = 0;
constexpr int AK_E = 256 * AST;
constexpr int AV_E = AK_E + 3 * 64 * AST;
constexpr int AEND_E = AV_E + 3 * 64 * AST;
constexpr int AM_BYTE = AEND_E * 2;
constexpr int ATT_SMEM = AM_BYTE + 3 * 64 * 4;
constexpr int KSTG = 64 * AST;                // elems per K/V stage
constexpr uint32_t SROT = KSTG * 2;           // stage byte stride

__global__ __launch_bounds__(512) void attn_mma(
    const __nv_bfloat16* __restrict__ Q, const __nv_bfloat16* __restrict__ K,
    const __nv_bfloat16* __restrict__ V, const int* __restrict__ mask,
    __nv_bfloat16* __restrict__ O)
{
    extern __shared__ __nv_bfloat16 smb[];
    int* ms = (int*)((char*)smb + AM_BYTE);
    const int tid = threadIdx.x, lane = tid & 31, wid = tid >> 5;
    const int b = blockIdx.z, h = blockIdx.y, q0 = blockIdx.x * 256;
    const uint32_t sb = smem_u32(smb);
    const int lrow = lane & 15;
    const int lcol8 = (lane >> 4) * 8;
    const int lrow_t = (lane & 7) + ((lane >> 4) << 3);
    const int dsel = ((lane >> 3) & 1) * 8;
    const int g = lane >> 2, cc = lane & 3;
    const int qb = wid * 16;
    const float scale2 = 0.125f * 1.44269504f;   // log2-domain scale
    const float mneg2 = -1.44269504e9f;

    // Q tile (256 x 64 bf16) via cp.async — first commit group
#pragma unroll
    for (int i = 0; i < 4; i++) {
        const int idx = tid + i * 512;
        const int row = idx >> 3, c8 = (idx & 7) * 8;
        cp_async16(sb + (AQ_E + row * AST + c8) * 2,
                   Q + (size_t)(b * S + q0 + row) * D + h * HD + c8);
    }
    cp_commit();

    auto issueKV = [&](int k0, int stage) {
        const int row = tid >> 3, c8 = (tid & 7) * 8;
        cp_async16(sb + ((AK_E + stage * KSTG) + row * AST + c8) * 2,
                   K + (size_t)(b * S + k0 + row) * D + h * HD + c8);
        cp_async16(sb + ((AV_E + stage * KSTG) + row * AST + c8) * 2,
                   V + (size_t)(b * S + k0 + row) * D + h * HD + c8);
        if (tid < 16)
            cp_async16(sb + AM_BYTE + stage * 256 + tid * 16,
                       mask + b * S + k0 + tid * 4);
        cp_commit();
    };

    issueKV(0, 0);
    issueKV(64, 1);

    // Hoist Q fragments: wait for Q group (2 groups may stay outstanding)
    cp_wait<2>();
    __syncthreads();
    uint32_t aq[4][4];
#pragma unroll
    for (int k = 0; k < 4; k++) {
        const uint32_t addr =
            sb + ((AQ_E + (qb + lrow) * AST) + k * 16 + lcol8) * 2;
        ldsm4(aq[k][0], aq[k][1], aq[k][2], aq[k][3], addr);
    }

    float ob[8][4];
#pragma unroll
    for (int nt = 0; nt < 8; nt++)
#pragma unroll
        for (int q = 0; q < 4; q++) ob[nt][q] = 0.f;
    float mst[2], lst[2];
    mst[0] = mst[1] = -1e30f;
    lst[0] = lst[1] = 0.f;   // per-lane partial row sums

    // rotating stage state
    uint32_t kbase = sb + (AK_E + lrow * AST + lcol8) * 2;          // + soff
    uint32_t vbase = sb + (AV_E + lrow_t * AST + dsel) * 2;         // + soff
    uint32_t soff = 0;
    int sidx = 0;      // mask stage index
    int wstage = 2;    // stage that issueKV(t+2) writes

    constexpr int NT = S / 64;
    for (int t = 0; t < NT; t++) {
        if (t + 1 < NT) cp_wait<1>(); else cp_wait<0>();
        __syncthreads();
        if (t + 2 < NT) issueKV((t + 2) * 64, wstage);

        // ---- S = Q K^T (Q from registers) ----
        float sc[8][4];
#pragma unroll
        for (int nt = 0; nt < 8; nt++)
#pragma unroll
            for (int q = 0; q < 4; q++) sc[nt][q] = 0.f;

        const uint32_t kb = kbase + soff;
#pragma unroll
        for (int k = 0; k < 4; k++) {
            uint32_t bfr[8][2];
#pragma unroll
            for (int np = 0; np < 4; np++) {
                uint32_t b0, b1, b2, b3;
                ldsm4(b0, b1, b2, b3, kb + (np * 16 * AST + k * 16) * 2);
                bfr[np * 2 + 0][0] = b0; bfr[np * 2 + 1][0] = b1;
                bfr[np * 2 + 0][1] = b2; bfr[np * 2 + 1][1] = b3;
            }
#pragma unroll
            for (int nt = 0; nt < 8; nt++)
                mma16(sc[nt], aq[k], bfr[nt][0], bfr[nt][1]);
        }

        // ---- online softmax, log2 domain; lane-partial sums ----
        const int* mstg = ms + sidx * 64;
#pragma unroll
        for (int hf = 0; hf < 2; hf++) {
            float rm = -1e30f;
#pragma unroll
            for (int nt = 0; nt < 8; nt++) {
                const int c0 = nt * 8 + cc * 2;
                const float m0v = mstg[c0] ? 0.f : mneg2;
                const float m1v = mstg[c0 + 1] ? 0.f : mneg2;
                float v0 = fmaf(sc[nt][hf * 2 + 0], scale2, m0v);
                float v1 = fmaf(sc[nt][hf * 2 + 1], scale2, m1v);
                sc[nt][hf * 2 + 0] = v0;
                sc[nt][hf * 2 + 1] = v1;
                rm = fmaxf(rm, fmaxf(v0, v1));
            }
            rm = fmaxf(rm, __shfl_xor_sync(0xffffffffu, rm, 1));
            rm = fmaxf(rm, __shfl_xor_sync(0xffffffffu, rm, 2));
            const float mnew = fmaxf(mst[hf], rm);
            const float cf = exp2f(mst[hf] - mnew);
            mst[hf] = mnew;
            float rs = 0.f;
#pragma unroll
            for (int nt = 0; nt < 8; nt++) {
                float p0 = exp2f(sc[nt][hf * 2 + 0] - mnew);
                float p1 = exp2f(sc[nt][hf * 2 + 1] - mnew);
                sc[nt][hf * 2 + 0] = p0;
                sc[nt][hf * 2 + 1] = p1;
                rs += p0 + p1;
            }
            lst[hf] = lst[hf] * cf + rs;    // lane-partial; reduced in epilogue
#pragma unroll
            for (int nt = 0; nt < 8; nt++) {
                ob[nt][hf * 2 + 0] *= cf;
                ob[nt][hf * 2 + 1] *= cf;
            }
        }

        // ---- O += P V, P direct from registers ----
        const uint32_t vb = vbase + soff;
#pragma unroll
        for (int kc = 0; kc < 4; kc++) {
            uint32_t a[4], bfr[8][2];
            a[0] = packbf(sc[2 * kc][0], sc[2 * kc][1]);
            a[1] = packbf(sc[2 * kc][2], sc[2 * kc][3]);
            a[2] = packbf(sc[2 * kc + 1][0], sc[2 * kc + 1][1]);
            a[3] = packbf(sc[2 * kc + 1][2], sc[2 * kc + 1][3]);
#pragma unroll
            for (int np = 0; np < 4; np++) {
                uint32_t b0, b1, b2, b3;
                ldsm4t(b0, b1, b2, b3, vb + (kc * 16 * AST + np * 16) * 2);
                bfr[np * 2 + 0][0] = b0; bfr[np * 2 + 1][0] = b1;
                bfr[np * 2 + 0][1] = b2; bfr[np * 2 + 1][1] = b3;
            }
#pragma unroll
            for (int nt = 0; nt < 8; nt++)
                mma16(ob[nt], a, bfr[nt][0], bfr[nt][1]);
        }

        // rotate stage state
        soff += SROT; if (soff == 3 * SROT) soff = 0;
        sidx = (sidx == 2) ? 0 : sidx + 1;
        wstage = (wstage == 2) ? 0 : wstage + 1;
    }

    // epilogue: reduce lane-partial sums, then O = ob / l
#pragma unroll
    for (int hf = 0; hf < 2; hf++) {
        float lt = lst[hf];
        lt += __shfl_xor_sync(0xffffffffu, lt, 1);
        lt += __shfl_xor_sync(0xffffffffu, lt, 2);
        const float inv = 1.0f / lt;
        const int row = q0 + qb + g + hf * 8;
#pragma unroll
        for (int nt = 0; nt < 8; nt++) {
            const int col = h * HD + nt * 8 + cc * 2;
            *(uint32_t*)(O + (size_t)(b * S + row) * D + col) =
                packbf(ob[nt][hf * 2 + 0] * inv, ob[nt][hf * 2 + 1] * inv);
        }
    }
}

// ---------------- LayerNorm: warp per row, shuffle reduce --------------------
__global__ __launch_bounds__(256) void ln_kernel(
    const float* __restrict__ Y, const float* __restrict__ gamma,
    const float* __restrict__ beta, float* __restrict__ out)
{
    const int lane = threadIdx.x & 31, wid = threadIdx.x >> 5;
    const int row = blockIdx.x * 8 + wid;
    const float* y = Y + (size_t)row * D;

    float s = 0.f, s2 = 0.f;
    float4 v[8];
#pragma unroll
    for (int i = 0; i < 8; i++) {
        v[i] = *(const float4*)(y + lane * 4 + i * 128);
        s += v[i].x + v[i].y + v[i].z + v[i].w;
        s2 = fmaf(v[i].x, v[i].x, s2);
        s2 = fmaf(v[i].y, v[i].y, s2);
        s2 = fmaf(v[i].z, v[i].z, s2);
        s2 = fmaf(v[i].w, v[i].w, s2);
    }
#pragma unroll
    for (int o = 16; o > 0; o >>= 1) {
        s  += __shfl_xor_sync(0xffffffffu, s, o);
        s2 += __shfl_xor_sync(0xffffffffu, s2, o);
    }
    const float mu = s * (1.0f / D);
    const float var = s2 * (1.0f / D) - mu * mu;
    const float inv = rsqrtf(var + 1e-5f);

    float* o = out + (size_t)row * D;
#pragma unroll
    for (int i = 0; i < 8; i++) {
        const int c = lane * 4 + i * 128;
        float4 gv = *(const float4*)(gamma + c);
        float4 bv = *(const float4*)(beta + c);
        float4 r;
        r.x = (v[i].x - mu) * inv * gv.x + bv.x;
        r.y = (v[i].y - mu) * inv * gv.y + bv.y;
        r.z = (v[i].z - mu) * inv * gv.z + bv.z;
        r.w = (v[i].w - mu) * inv * gv.w + bv.w;
        *(float4*)(o + c) = r;
    }
}

// ---------------- launch ------------------------------------------------------
extern "C" void kernel_launch(void* const* d_in, const int* in_sizes, int n_in,
                              void* d_out, int out_size)
{
    const float* x     = (const float*)d_in[0];
    const int*   mask  = (const int*)d_in[1];
    const float* Wq    = (const float*)d_in[2];
    const float* bq    = (const float*)d_in[3];
    const float* Wk    = (const float*)d_in[4];
    const float* bk    = (const float*)d_in[5];
    const float* Wv    = (const float*)d_in[6];
    const float* bv    = (const float*)d_in[7];
    const float* Wo    = (const float*)d_in[8];
    const float* bo    = (const float*)d_in[9];
    const float* gamma = (const float*)d_in[10];
    const float* beta  = (const float*)d_in[11];

    __nv_bfloat16 *Xb, *Wb, *Qb, *Kb, *Vb, *Cb;
    float* Yp;
    cudaGetSymbolAddress((void**)&Xb, g_Xb);
    cudaGetSymbolAddress((void**)&Wb, g_Wb);
    cudaGetSymbolAddress((void**)&Qb, g_Qb);
    cudaGetSymbolAddress((void**)&Kb, g_Kb);
    cudaGetSymbolAddress((void**)&Vb, g_Vb);
    cudaGetSymbolAddress((void**)&Cb, g_Cb);
    cudaGetSymbolAddress((void**)&Yp, g_Y);

    cudaFuncSetAttribute(qkv_gemm,
                         cudaFuncAttributeMaxDynamicSharedMemorySize, GEMM_SMEM);
    cudaFuncSetAttribute(out_gemm,
                         cudaFuncAttributeMaxDynamicSharedMemorySize, GEMM_SMEM);
    cudaFuncSetAttribute(attn_mma,
                         cudaFuncAttributeMaxDynamicSharedMemorySize, ATT_SMEM);

    const int nX4 = NR * D / 4, nW4 = D * D / 4;
    cvt_bf16<<<nX4 / 256, 256>>>(x, Xb, nX4);
    WPtrs ws;
    ws.w[0] = Wq; ws.w[1] = Wk; ws.w[2] = Wv; ws.w[3] = Wo;
    cvt_w4<<<dim3(nW4 / 256, 4), 256>>>(ws, Wb);

    QKVOut io;
    io.out[0] = Qb; io.out[1] = Kb; io.out[2] = Vb;
    io.bias[0] = bq; io.bias[1] = bk; io.bias[2] = bv;
    qkv_gemm<<<dim3(24, NR / 128), 128, GEMM_SMEM>>>(Xb, Wb, io);

    attn_mma<<<dim3(S / 256, H, B), 512, ATT_SMEM>>>(Qb, Kb, Vb, mask, Cb);

    out_gemm<<<dim3(8, NR / 128), 128, GEMM_SMEM>>>(
        Cb, Wb + (size_t)3 * D * D, bo, x, Yp);
    ln_kernel<<<NR / 8, 256>>>(Yp, gamma, beta, (float*)d_out);
}

// round 10
// speedup vs baseline: 8.0609x; 1.0671x over previous
#include <cuda_runtime.h>
#include <cuda_bf16.h>
#include <cstdint>
#include <math.h>

constexpr int B = 4, S = 2048, D = 1024, H = 16, HD = 64;
constexpr int NR = B * S;  // 8192 rows

// ---------------- scratch (static device globals; no allocation) -------------
__device__ __nv_bfloat16 g_Xb[(size_t)NR * D];      // x bf16
__device__ __nv_bfloat16 g_Wb[(size_t)4 * D * D];   // Wq,Wk,Wv,Wo bf16
__device__ __nv_bfloat16 g_Qb[(size_t)NR * D];
__device__ __nv_bfloat16 g_Kb[(size_t)NR * D];
__device__ __nv_bfloat16 g_Vb[(size_t)NR * D];
__device__ __nv_bfloat16 g_Cb[(size_t)NR * D];      // attention out bf16
__device__ float         g_Y[(size_t)NR * D];

// ======================= helpers ============================================
__device__ __forceinline__ uint32_t smem_u32(const void* p) {
    uint32_t a;
    asm("{ .reg .u64 t; cvta.to.shared.u64 t, %1; cvt.u32.u64 %0, t; }"
        : "=r"(a) : "l"(p));
    return a;
}
__device__ __forceinline__ void ldsm4(uint32_t& r0, uint32_t& r1, uint32_t& r2,
                                      uint32_t& r3, uint32_t addr) {
    asm volatile("ldmatrix.sync.aligned.m8n8.x4.shared.b16 {%0,%1,%2,%3}, [%4];"
                 : "=r"(r0), "=r"(r1), "=r"(r2), "=r"(r3) : "r"(addr));
}
__device__ __forceinline__ void ldsm4t(uint32_t& r0, uint32_t& r1, uint32_t& r2,
                                       uint32_t& r3, uint32_t addr) {
    asm volatile("ldmatrix.sync.aligned.m8n8.x4.trans.shared.b16 {%0,%1,%2,%3}, [%4];"
                 : "=r"(r0), "=r"(r1), "=r"(r2), "=r"(r3) : "r"(addr));
}
__device__ __forceinline__ void mma16(float (&c)[4], const uint32_t (&a)[4],
                                      uint32_t b0, uint32_t b1) {
    asm volatile(
        "mma.sync.aligned.m16n8k16.row.col.f32.bf16.bf16.f32 "
        "{%0,%1,%2,%3}, {%4,%5,%6,%7}, {%8,%9}, {%0,%1,%2,%3};"
        : "+f"(c[0]), "+f"(c[1]), "+f"(c[2]), "+f"(c[3])
        : "r"(a[0]), "r"(a[1]), "r"(a[2]), "r"(a[3]), "r"(b0), "r"(b1));
}
__device__ __forceinline__ void cp_async16(uint32_t s, const void* g) {
    asm volatile("cp.async.cg.shared.global [%0], [%1], 16;" :: "r"(s), "l"(g));
}
__device__ __forceinline__ void cp_commit() {
    asm volatile("cp.async.commit_group;" ::: "memory");
}
template <int N>
__device__ __forceinline__ void cp_wait() {
    asm volatile("cp.async.wait_group %0;" :: "n"(N) : "memory");
}
__device__ __forceinline__ uint32_t packbf(float x, float y) {
    __nv_bfloat162 p = __floats2bfloat162_rn(x, y);
    return *(uint32_t*)&p;
}

// ======================= fp32 -> bf16 prep ===================================
__global__ __launch_bounds__(256) void cvt_bf16(const float* __restrict__ in,
                                                __nv_bfloat16* __restrict__ out,
                                                int n4)
{
    const int i = (blockIdx.x * 256 + threadIdx.x) * 4;
    if (i < n4 * 4) {
        float4 v = *(const float4*)(in + i);
        uint2 u;
        u.x = packbf(v.x, v.y);
        u.y = packbf(v.z, v.w);
        *(uint2*)(out + i) = u;
    }
}

struct WPtrs { const float* w[4]; };

__global__ __launch_bounds__(256) void cvt_w4(WPtrs ws,
                                              __nv_bfloat16* __restrict__ out)
{
    const int i = (blockIdx.x * 256 + threadIdx.x) * 4;
    const float* in = ws.w[blockIdx.y];
    __nv_bfloat16* o = out + (size_t)blockIdx.y * D * D;
    float4 v = *(const float4*)(in + i);
    uint2 u;
    u.x = packbf(v.x, v.y);
    u.y = packbf(v.z, v.w);
    *(uint2*)(o + i) = u;
}

// ======================= bf16 mma GEMM core =================================
// 128x128 block tile, 4 warps, warp tile 64x64. 2-stage cp.async, BK=64.
constexpr int GST = 72;                 // smem row stride (bf16 elems)
constexpr int G_STAGE = 256 * GST;      // bf16 elems per stage
constexpr int GEMM_SMEM = 2 * G_STAGE * 2;  // 73728 B

struct QKVOut {
    __nv_bfloat16* out[3];
    const float* bias[3];
};

template <typename AccFn>
__device__ __forceinline__ void gemm_body(
    const __nv_bfloat16* __restrict__ A, const __nv_bfloat16* __restrict__ W,
    int n0, int m0, __nv_bfloat16* gsm, AccFn&& emit)
{
    const int tid = threadIdx.x;
    const int lane = tid & 31, wid = tid >> 5;   // 4 warps
    const int wr = wid >> 1, wc = wid & 1;        // 2x2 warp grid, 64x64 each
    const int lrow = lane & 15;
    const int lcol8 = (lane >> 4) * 8;
    const uint32_t sbase = smem_u32(gsm);

    float acc[4][8][4];
#pragma unroll
    for (int mt = 0; mt < 4; mt++)
#pragma unroll
        for (int nt = 0; nt < 8; nt++)
#pragma unroll
            for (int q = 0; q < 4; q++) acc[mt][nt][q] = 0.f;

    auto issue_chunk = [&](int c) {
        const int k0 = c * 64;
        const uint32_t stb = sbase + (c & 1) * G_STAGE * 2;
#pragma unroll
        for (int i = 0; i < 16; i++) {
            const int idx = tid + i * 128;
            const int t = idx & 1023;
            const int row = t >> 3, c8 = (t & 7) * 8;
            const __nv_bfloat16* g =
                (idx < 1024 ? A + (size_t)(n0 + row) * D
                            : W + (size_t)(m0 + row) * D) + k0 + c8;
            const int srow = row + (idx < 1024 ? 0 : 128);
            cp_async16(stb + (srow * GST + c8) * 2, g);
        }
        cp_commit();
    };

    issue_chunk(0);
    for (int c = 0; c < 16; c++) {
        if (c < 15) issue_chunk(c + 1);
        if (c < 15) cp_wait<1>(); else cp_wait<0>();
        __syncthreads();

        const uint32_t stb = sbase + (c & 1) * G_STAGE * 2;
#pragma unroll
        for (int k = 0; k < 4; k++) {
            uint32_t a[4][4];
            uint32_t bfr[8][2];
#pragma unroll
            for (int mt = 0; mt < 4; mt++) {
                const uint32_t addr =
                    stb + ((wr * 64 + mt * 16 + lrow) * GST + k * 16 + lcol8) * 2;
                ldsm4(a[mt][0], a[mt][1], a[mt][2], a[mt][3], addr);
            }
#pragma unroll
            for (int np = 0; np < 4; np++) {
                const uint32_t addr =
                    stb + ((128 + wc * 64 + np * 16 + lrow) * GST + k * 16 + lcol8) * 2;
                uint32_t b0, b1, b2, b3;
                ldsm4(b0, b1, b2, b3, addr);
                bfr[np * 2 + 0][0] = b0; bfr[np * 2 + 1][0] = b1;
                bfr[np * 2 + 0][1] = b2; bfr[np * 2 + 1][1] = b3;
            }
#pragma unroll
            for (int mt = 0; mt < 4; mt++)
#pragma unroll
                for (int nt = 0; nt < 8; nt++)
                    mma16(acc[mt][nt], a[mt], bfr[nt][0], bfr[nt][1]);
        }
        __syncthreads();
    }

    const int g = lane >> 2, cc = lane & 3;
#pragma unroll
    for (int mt = 0; mt < 4; mt++)
#pragma unroll
        for (int hf = 0; hf < 2; hf++) {
            const int row = n0 + wr * 64 + mt * 16 + g + hf * 8;
#pragma unroll
            for (int nt = 0; nt < 8; nt++) {
                const int col = m0 + wc * 64 + nt * 8 + cc * 2;
                emit(row, col, acc[mt][nt][hf * 2 + 0], acc[mt][nt][hf * 2 + 1]);
            }
        }
}

// Fused QKV projection: grid.x in [0,24): sel = x>>3, m-block = x&7.
__global__ __launch_bounds__(128, 2) void qkv_gemm(
    const __nv_bfloat16* __restrict__ A, const __nv_bfloat16* __restrict__ Wall,
    QKVOut io)
{
    extern __shared__ __nv_bfloat16 gsm[];
    const int sel = blockIdx.x >> 3;
    const int m0 = (blockIdx.x & 7) * 128;
    const int n0 = blockIdx.y * 128;
    const __nv_bfloat16* W = Wall + (size_t)sel * D * D;
    __nv_bfloat16* out = io.out[sel];
    const float* bias = io.bias[sel];

    gemm_body(A, W, n0, m0, gsm,
              [&](int row, int col, float vx, float vy) {
                  float2 bv = *(const float2*)(bias + col);
                  *(uint32_t*)(out + (size_t)row * D + col) =
                      packbf(vx + bv.x, vy + bv.y);
              });
}

// Output projection with residual, fp32 out.
__global__ __launch_bounds__(128, 2) void out_gemm(
    const __nv_bfloat16* __restrict__ A, const __nv_bfloat16* __restrict__ W,
    const float* __restrict__ bias, const float* __restrict__ R,
    float* __restrict__ C)
{
    extern __shared__ __nv_bfloat16 gsm[];
    const int m0 = blockIdx.x * 128;
    const int n0 = blockIdx.y * 128;

    gemm_body(A, W, n0, m0, gsm,
              [&](int row, int col, float vx, float vy) {
                  float2 bv = *(const float2*)(bias + col);
                  float2 rv = *(const float2*)(R + (size_t)row * D + col);
                  float2 o;
                  o.x = vx + bv.x + rv.x;
                  o.y = vy + bv.y + rv.y;
                  *(float2*)(C + (size_t)row * D + col) = o;
              });
}

// ======================= bf16 mma flash attention ===========================
// Block: 128 q rows, 8 warps x 16 rows, 256 threads, 2 CTAs/SM.
// 64-key tiles, 3-stage cp.async, Q fragments hoisted, rotating stage offsets,
// per-lane deferred row sums, mask addends hoisted per tile.
constexpr int AST = 72;
constexpr int AQ_E = 0;
constexpr int AK_E = 128 * AST;                 // after 128-row Q tile
constexpr int AV_E = AK_E + 3 * 64 * AST;
constexpr int AEND_E = AV_E + 3 * 64 * AST;
constexpr int AM_BYTE = AEND_E * 2;
constexpr int ATT_SMEM = AM_BYTE + 3 * 64 * 4;  // ~74.5 KB
constexpr int KSTG = 64 * AST;
constexpr uint32_t SROT = KSTG * 2;

__global__ __launch_bounds__(256, 2) void attn_mma(
    const __nv_bfloat16* __restrict__ Q, const __nv_bfloat16* __restrict__ K,
    const __nv_bfloat16* __restrict__ V, const int* __restrict__ mask,
    __nv_bfloat16* __restrict__ O)
{
    extern __shared__ __nv_bfloat16 smb[];
    int* ms = (int*)((char*)smb + AM_BYTE);
    const int tid = threadIdx.x, lane = tid & 31, wid = tid >> 5;
    const int b = blockIdx.z, h = blockIdx.y, q0 = blockIdx.x * 128;
    const uint32_t sb = smem_u32(smb);
    const int lrow = lane & 15;
    const int lcol8 = (lane >> 4) * 8;
    const int lrow_t = (lane & 7) + ((lane >> 4) << 3);
    const int dsel = ((lane >> 3) & 1) * 8;
    const int g = lane >> 2, cc = lane & 3;
    const int qb = wid * 16;
    const float scale2 = 0.125f * 1.44269504f;   // log2-domain scale
    const float mneg2 = -1.44269504e9f;

    // Q tile (128 x 64 bf16) via cp.async — first commit group
#pragma unroll
    for (int i = 0; i < 4; i++) {
        const int idx = tid + i * 256;
        const int row = idx >> 3, c8 = (idx & 7) * 8;
        cp_async16(sb + (AQ_E + row * AST + c8) * 2,
                   Q + (size_t)(b * S + q0 + row) * D + h * HD + c8);
    }
    cp_commit();

    auto issueKV = [&](int k0, int stage) {
#pragma unroll
        for (int j = 0; j < 2; j++) {
            const int idx = tid + j * 256;
            const int row = idx >> 3, c8 = (idx & 7) * 8;
            cp_async16(sb + ((AK_E + stage * KSTG) + row * AST + c8) * 2,
                       K + (size_t)(b * S + k0 + row) * D + h * HD + c8);
            cp_async16(sb + ((AV_E + stage * KSTG) + row * AST + c8) * 2,
                       V + (size_t)(b * S + k0 + row) * D + h * HD + c8);
        }
        if (tid < 16)
            cp_async16(sb + AM_BYTE + stage * 256 + tid * 16,
                       mask + b * S + k0 + tid * 4);
        cp_commit();
    };

    issueKV(0, 0);
    issueKV(64, 1);

    // Hoist Q fragments
    cp_wait<2>();
    __syncthreads();
    uint32_t aq[4][4];
#pragma unroll
    for (int k = 0; k < 4; k++) {
        const uint32_t addr =
            sb + ((AQ_E + (qb + lrow) * AST) + k * 16 + lcol8) * 2;
        ldsm4(aq[k][0], aq[k][1], aq[k][2], aq[k][3], addr);
    }

    float ob[8][4];
#pragma unroll
    for (int nt = 0; nt < 8; nt++)
#pragma unroll
        for (int q = 0; q < 4; q++) ob[nt][q] = 0.f;
    float mst[2], lst[2];
    mst[0] = mst[1] = -1e30f;
    lst[0] = lst[1] = 0.f;   // per-lane partial row sums

    uint32_t kbase = sb + (AK_E + lrow * AST + lcol8) * 2;
    uint32_t vbase = sb + (AV_E + lrow_t * AST + dsel) * 2;
    uint32_t soff = 0;
    int sidx = 0;
    int wstage = 2;

    constexpr int NT = S / 64;
    for (int t = 0; t < NT; t++) {
        if (t + 1 < NT) cp_wait<1>(); else cp_wait<0>();
        __syncthreads();
        if (t + 2 < NT) issueKV((t + 2) * 64, wstage);

        // ---- S = Q K^T (Q from registers) ----
        float sc[8][4];
#pragma unroll
        for (int nt = 0; nt < 8; nt++)
#pragma unroll
            for (int q = 0; q < 4; q++) sc[nt][q] = 0.f;

        const uint32_t kb = kbase + soff;
#pragma unroll
        for (int k = 0; k < 4; k++) {
            uint32_t bfr[8][2];
#pragma unroll
            for (int np = 0; np < 4; np++) {
                uint32_t b0, b1, b2, b3;
                ldsm4(b0, b1, b2, b3, kb + (np * 16 * AST + k * 16) * 2);
                bfr[np * 2 + 0][0] = b0; bfr[np * 2 + 1][0] = b1;
                bfr[np * 2 + 0][1] = b2; bfr[np * 2 + 1][1] = b3;
            }
#pragma unroll
            for (int nt = 0; nt < 8; nt++)
                mma16(sc[nt], aq[k], bfr[nt][0], bfr[nt][1]);
        }

        // ---- mask addends, hoisted once per tile ----
        const int* mstg = ms + sidx * 64;
        float madd[8][2];
#pragma unroll
        for (int nt = 0; nt < 8; nt++) {
            const int c0 = nt * 8 + cc * 2;
            madd[nt][0] = mstg[c0] ? 0.f : mneg2;
            madd[nt][1] = mstg[c0 + 1] ? 0.f : mneg2;
        }

        // ---- online softmax, log2 domain; lane-partial sums ----
#pragma unroll
        for (int hf = 0; hf < 2; hf++) {
            float rm = -1e30f;
#pragma unroll
            for (int nt = 0; nt < 8; nt++) {
                float v0 = fmaf(sc[nt][hf * 2 + 0], scale2, madd[nt][0]);
                float v1 = fmaf(sc[nt][hf * 2 + 1], scale2, madd[nt][1]);
                sc[nt][hf * 2 + 0] = v0;
                sc[nt][hf * 2 + 1] = v1;
                rm = fmaxf(rm, fmaxf(v0, v1));
            }
            rm = fmaxf(rm, __shfl_xor_sync(0xffffffffu, rm, 1));
            rm = fmaxf(rm, __shfl_xor_sync(0xffffffffu, rm, 2));
            const float mnew = fmaxf(mst[hf], rm);
            const float cf = exp2f(mst[hf] - mnew);
            mst[hf] = mnew;
            float rs = 0.f;
#pragma unroll
            for (int nt = 0; nt < 8; nt++) {
                float p0 = exp2f(sc[nt][hf * 2 + 0] - mnew);
                float p1 = exp2f(sc[nt][hf * 2 + 1] - mnew);
                sc[nt][hf * 2 + 0] = p0;
                sc[nt][hf * 2 + 1] = p1;
                rs += p0 + p1;
            }
            lst[hf] = lst[hf] * cf + rs;
#pragma unroll
            for (int nt = 0; nt < 8; nt++) {
                ob[nt][hf * 2 + 0] *= cf;
                ob[nt][hf * 2 + 1] *= cf;
            }
        }

        // ---- O += P V, P direct from registers ----
        const uint32_t vb = vbase + soff;
#pragma unroll
        for (int kc = 0; kc < 4; kc++) {
            uint32_t a[4], bfr[8][2];
            a[0] = packbf(sc[2 * kc][0], sc[2 * kc][1]);
            a[1] = packbf(sc[2 * kc][2], sc[2 * kc][3]);
            a[2] = packbf(sc[2 * kc + 1][0], sc[2 * kc + 1][1]);
            a[3] = packbf(sc[2 * kc + 1][2], sc[2 * kc + 1][3]);
#pragma unroll
            for (int np = 0; np < 4; np++) {
                uint32_t b0, b1, b2, b3;
                ldsm4t(b0, b1, b2, b3, vb + (kc * 16 * AST + np * 16) * 2);
                bfr[np * 2 + 0][0] = b0; bfr[np * 2 + 1][0] = b1;
                bfr[np * 2 + 0][1] = b2; bfr[np * 2 + 1][1] = b3;
            }
#pragma unroll
            for (int nt = 0; nt < 8; nt++)
                mma16(ob[nt], a, bfr[nt][0], bfr[nt][1]);
        }

        soff += SROT; if (soff == 3 * SROT) soff = 0;
        sidx = (sidx == 2) ? 0 : sidx + 1;
        wstage = (wstage == 2) ? 0 : wstage + 1;
    }

    // epilogue: reduce lane-partial sums, then O = ob / l
#pragma unroll
    for (int hf = 0; hf < 2; hf++) {
        float lt = lst[hf];
        lt += __shfl_xor_sync(0xffffffffu, lt, 1);
        lt += __shfl_xor_sync(0xffffffffu, lt, 2);
        const float inv = 1.0f / lt;
        const int row = q0 + qb + g + hf * 8;
#pragma unroll
        for (int nt = 0; nt < 8; nt++) {
            const int col = h * HD + nt * 8 + cc * 2;
            *(uint32_t*)(O + (size_t)(b * S + row) * D + col) =
                packbf(ob[nt][hf * 2 + 0] * inv, ob[nt][hf * 2 + 1] * inv);
        }
    }
}

// ---------------- LayerNorm: warp per row, shuffle reduce --------------------
__global__ __launch_bounds__(256) void ln_kernel(
    const float* __restrict__ Y, const float* __restrict__ gamma,
    const float* __restrict__ beta, float* __restrict__ out)
{
    const int lane = threadIdx.x & 31, wid = threadIdx.x >> 5;
    const int row = blockIdx.x * 8 + wid;
    const float* y = Y + (size_t)row * D;

    float s = 0.f, s2 = 0.f;
    float4 v[8];
#pragma unroll
    for (int i = 0; i < 8; i++) {
        v[i] = *(const float4*)(y + lane * 4 + i * 128);
        s += v[i].x + v[i].y + v[i].z + v[i].w;
        s2 = fmaf(v[i].x, v[i].x, s2);
        s2 = fmaf(v[i].y, v[i].y, s2);
        s2 = fmaf(v[i].z, v[i].z, s2);
        s2 = fmaf(v[i].w, v[i].w, s2);
    }
#pragma unroll
    for (int o = 16; o > 0; o >>= 1) {
        s  += __shfl_xor_sync(0xffffffffu, s, o);
        s2 += __shfl_xor_sync(0xffffffffu, s2, o);
    }
    const float mu = s * (1.0f / D);
    const float var = s2 * (1.0f / D) - mu * mu;
    const float inv = rsqrtf(var + 1e-5f);

    float* o = out + (size_t)row * D;
#pragma unroll
    for (int i = 0; i < 8; i++) {
        const int c = lane * 4 + i * 128;
        float4 gv = *(const float4*)(gamma + c);
        float4 bv = *(const float4*)(beta + c);
        float4 r;
        r.x = (v[i].x - mu) * inv * gv.x + bv.x;
        r.y = (v[i].y - mu) * inv * gv.y + bv.y;
        r.z = (v[i].z - mu) * inv * gv.z + bv.z;
        r.w = (v[i].w - mu) * inv * gv.w + bv.w;
        *(float4*)(o + c) = r;
    }
}

// ---------------- launch ------------------------------------------------------
extern "C" void kernel_launch(void* const* d_in, const int* in_sizes, int n_in,
                              void* d_out, int out_size)
{
    const float* x     = (const float*)d_in[0];
    const int*   mask  = (const int*)d_in[1];
    const float* Wq    = (const float*)d_in[2];
    const float* bq    = (const float*)d_in[3];
    const float* Wk    = (const float*)d_in[4];
    const float* bk    = (const float*)d_in[5];
    const float* Wv    = (const float*)d_in[6];
    const float* bv    = (const float*)d_in[7];
    const float* Wo    = (const float*)d_in[8];
    const float* bo    = (const float*)d_in[9];
    const float* gamma = (const float*)d_in[10];
    const float* beta  = (const float*)d_in[11];

    __nv_bfloat16 *Xb, *Wb, *Qb, *Kb, *Vb, *Cb;
    float* Yp;
    cudaGetSymbolAddress((void**)&Xb, g_Xb);
    cudaGetSymbolAddress((void**)&Wb, g_Wb);
    cudaGetSymbolAddress((void**)&Qb, g_Qb);
    cudaGetSymbolAddress((void**)&Kb, g_Kb);
    cudaGetSymbolAddress((void**)&Vb, g_Vb);
    cudaGetSymbolAddress((void**)&Cb, g_Cb);
    cudaGetSymbolAddress((void**)&Yp, g_Y);

    cudaFuncSetAttribute(qkv_gemm,
                         cudaFuncAttributeMaxDynamicSharedMemorySize, GEMM_SMEM);
    cudaFuncSetAttribute(out_gemm,
                         cudaFuncAttributeMaxDynamicSharedMemorySize, GEMM_SMEM);
    cudaFuncSetAttribute(attn_mma,
                         cudaFuncAttributeMaxDynamicSharedMemorySize, ATT_SMEM);

    const int nX4 = NR * D / 4, nW4 = D * D / 4;
    cvt_bf16<<<nX4 / 256, 256>>>(x, Xb, nX4);
    WPtrs ws;
    ws.w[0] = Wq; ws.w[1] = Wk; ws.w[2] = Wv; ws.w[3] = Wo;
    cvt_w4<<<dim3(nW4 / 256, 4), 256>>>(ws, Wb);

    QKVOut io;
    io.out[0] = Qb; io.out[1] = Kb; io.out[2] = Vb;
    io.bias[0] = bq; io.bias[1] = bk; io.bias[2] = bv;
    qkv_gemm<<<dim3(24, NR / 128), 128, GEMM_SMEM>>>(Xb, Wb, io);

    attn_mma<<<dim3(S / 128, H, B), 256, ATT_SMEM>>>(Qb, Kb, Vb, mask, Cb);

    out_gemm<<<dim3(8, NR / 128), 128, GEMM_SMEM>>>(
        Cb, Wb + (size_t)3 * D * D, bo, x, Yp);
    ln_kernel<<<NR / 8, 256>>>(Yp, gamma, beta, (float*)d_out);
}

// round 11
// speedup vs baseline: 8.1002x; 1.0049x over previous
#include <cuda_runtime.h>
#include <cuda_bf16.h>
#include <cstdint>
#include <math.h>

constexpr int B = 4, S = 2048, D = 1024, H = 16, HD = 64;
constexpr int NR = B * S;  // 8192 rows

// ---------------- scratch (static device globals; no allocation) -------------
__device__ __nv_bfloat16 g_Xb[(size_t)NR * D];      // x bf16
__device__ __nv_bfloat16 g_Wb[(size_t)4 * D * D];   // Wq,Wk,Wv,Wo bf16
__device__ __nv_bfloat16 g_Qb[(size_t)NR * D];      // pre-scaled by 0.125*log2e
__device__ __nv_bfloat16 g_Kb[(size_t)NR * D];
__device__ __nv_bfloat16 g_Vb[(size_t)NR * D];
__device__ __nv_bfloat16 g_Cb[(size_t)NR * D];      // attention out bf16
__device__ float         g_Y[(size_t)NR * D];

// ======================= helpers ============================================
__device__ __forceinline__ uint32_t smem_u32(const void* p) {
    uint32_t a;
    asm("{ .reg .u64 t; cvta.to.shared.u64 t, %1; cvt.u32.u64 %0, t; }"
        : "=r"(a) : "l"(p));
    return a;
}
__device__ __forceinline__ void ldsm4(uint32_t& r0, uint32_t& r1, uint32_t& r2,
                                      uint32_t& r3, uint32_t addr) {
    asm volatile("ldmatrix.sync.aligned.m8n8.x4.shared.b16 {%0,%1,%2,%3}, [%4];"
                 : "=r"(r0), "=r"(r1), "=r"(r2), "=r"(r3) : "r"(addr));
}
__device__ __forceinline__ void ldsm4t(uint32_t& r0, uint32_t& r1, uint32_t& r2,
                                       uint32_t& r3, uint32_t addr) {
    asm volatile("ldmatrix.sync.aligned.m8n8.x4.trans.shared.b16 {%0,%1,%2,%3}, [%4];"
                 : "=r"(r0), "=r"(r1), "=r"(r2), "=r"(r3) : "r"(addr));
}
__device__ __forceinline__ void mma16(float (&c)[4], const uint32_t (&a)[4],
                                      uint32_t b0, uint32_t b1) {
    asm volatile(
        "mma.sync.aligned.m16n8k16.row.col.f32.bf16.bf16.f32 "
        "{%0,%1,%2,%3}, {%4,%5,%6,%7}, {%8,%9}, {%0,%1,%2,%3};"
        : "+f"(c[0]), "+f"(c[1]), "+f"(c[2]), "+f"(c[3])
        : "r"(a[0]), "r"(a[1]), "r"(a[2]), "r"(a[3]), "r"(b0), "r"(b1));
}
__device__ __forceinline__ void cp_async16(uint32_t s, const void* g) {
    asm volatile("cp.async.cg.shared.global [%0], [%1], 16;" :: "r"(s), "l"(g));
}
__device__ __forceinline__ void cp_commit() {
    asm volatile("cp.async.commit_group;" ::: "memory");
}
template <int N>
__device__ __forceinline__ void cp_wait() {
    asm volatile("cp.async.wait_group %0;" :: "n"(N) : "memory");
}
__device__ __forceinline__ uint32_t packbf(float x, float y) {
    __nv_bfloat162 p = __floats2bfloat162_rn(x, y);
    return *(uint32_t*)&p;
}

// ======================= fp32 -> bf16 prep ===================================
__global__ __launch_bounds__(256) void cvt_bf16(const float* __restrict__ in,
                                                __nv_bfloat16* __restrict__ out,
                                                int n4)
{
    const int i = (blockIdx.x * 256 + threadIdx.x) * 4;
    if (i < n4 * 4) {
        float4 v = *(const float4*)(in + i);
        uint2 u;
        u.x = packbf(v.x, v.y);
        u.y = packbf(v.z, v.w);
        *(uint2*)(out + i) = u;
    }
}

struct WPtrs { const float* w[4]; };

__global__ __launch_bounds__(256) void cvt_w4(WPtrs ws,
                                              __nv_bfloat16* __restrict__ out)
{
    const int i = (blockIdx.x * 256 + threadIdx.x) * 4;
    const float* in = ws.w[blockIdx.y];
    __nv_bfloat16* o = out + (size_t)blockIdx.y * D * D;
    float4 v = *(const float4*)(in + i);
    uint2 u;
    u.x = packbf(v.x, v.y);
    u.y = packbf(v.z, v.w);
    *(uint2*)(o + i) = u;
}

// ======================= bf16 mma GEMM core =================================
// 128x128 block tile, 4 warps, warp tile 64x64. 2-stage cp.async, BK=64.
constexpr int GST = 72;                 // smem row stride (bf16 elems)
constexpr int G_STAGE = 256 * GST;      // bf16 elems per stage
constexpr int GEMM_SMEM = 2 * G_STAGE * 2;  // 73728 B

struct QKVOut {
    __nv_bfloat16* out[3];
    const float* bias[3];
    float oscale[3];
};

template <typename AccFn>
__device__ __forceinline__ void gemm_body(
    const __nv_bfloat16* __restrict__ A, const __nv_bfloat16* __restrict__ W,
    int n0, int m0, __nv_bfloat16* gsm, AccFn&& emit)
{
    const int tid = threadIdx.x;
    const int lane = tid & 31, wid = tid >> 5;   // 4 warps
    const int wr = wid >> 1, wc = wid & 1;        // 2x2 warp grid, 64x64 each
    const int lrow = lane & 15;
    const int lcol8 = (lane >> 4) * 8;
    const uint32_t sbase = smem_u32(gsm);

    float acc[4][8][4];
#pragma unroll
    for (int mt = 0; mt < 4; mt++)
#pragma unroll
        for (int nt = 0; nt < 8; nt++)
#pragma unroll
            for (int q = 0; q < 4; q++) acc[mt][nt][q] = 0.f;

    auto issue_chunk = [&](int c) {
        const int k0 = c * 64;
        const uint32_t stb = sbase + (c & 1) * G_STAGE * 2;
#pragma unroll
        for (int i = 0; i < 16; i++) {
            const int idx = tid + i * 128;
            const int t = idx & 1023;
            const int row = t >> 3, c8 = (t & 7) * 8;
            const __nv_bfloat16* g =
                (idx < 1024 ? A + (size_t)(n0 + row) * D
                            : W + (size_t)(m0 + row) * D) + k0 + c8;
            const int srow = row + (idx < 1024 ? 0 : 128);
            cp_async16(stb + (srow * GST + c8) * 2, g);
        }
        cp_commit();
    };

    issue_chunk(0);
    for (int c = 0; c < 16; c++) {
        if (c < 15) issue_chunk(c + 1);
        if (c < 15) cp_wait<1>(); else cp_wait<0>();
        __syncthreads();

        const uint32_t stb = sbase + (c & 1) * G_STAGE * 2;
#pragma unroll
        for (int k = 0; k < 4; k++) {
            uint32_t a[4][4];
            uint32_t bfr[8][2];
#pragma unroll
            for (int mt = 0; mt < 4; mt++) {
                const uint32_t addr =
                    stb + ((wr * 64 + mt * 16 + lrow) * GST + k * 16 + lcol8) * 2;
                ldsm4(a[mt][0], a[mt][1], a[mt][2], a[mt][3], addr);
            }
#pragma unroll
            for (int np = 0; np < 4; np++) {
                const uint32_t addr =
                    stb + ((128 + wc * 64 + np * 16 + lrow) * GST + k * 16 + lcol8) * 2;
                uint32_t b0, b1, b2, b3;
                ldsm4(b0, b1, b2, b3, addr);
                bfr[np * 2 + 0][0] = b0; bfr[np * 2 + 1][0] = b1;
                bfr[np * 2 + 0][1] = b2; bfr[np * 2 + 1][1] = b3;
            }
#pragma unroll
            for (int mt = 0; mt < 4; mt++)
#pragma unroll
                for (int nt = 0; nt < 8; nt++)
                    mma16(acc[mt][nt], a[mt], bfr[nt][0], bfr[nt][1]);
        }
        __syncthreads();
    }

    const int g = lane >> 2, cc = lane & 3;
#pragma unroll
    for (int mt = 0; mt < 4; mt++)
#pragma unroll
        for (int hf = 0; hf < 2; hf++) {
            const int row = n0 + wr * 64 + mt * 16 + g + hf * 8;
#pragma unroll
            for (int nt = 0; nt < 8; nt++) {
                const int col = m0 + wc * 64 + nt * 8 + cc * 2;
                emit(row, col, acc[mt][nt][hf * 2 + 0], acc[mt][nt][hf * 2 + 1]);
            }
        }
}

// Fused QKV projection: grid.x in [0,24): sel = x>>3, m-block = x&7.
// Q output is pre-scaled by 0.125*log2(e) (softmax log2-domain fold).
__global__ __launch_bounds__(128, 2) void qkv_gemm(
    const __nv_bfloat16* __restrict__ A, const __nv_bfloat16* __restrict__ Wall,
    QKVOut io)
{
    extern __shared__ __nv_bfloat16 gsm[];
    const int sel = blockIdx.x >> 3;
    const int m0 = (blockIdx.x & 7) * 128;
    const int n0 = blockIdx.y * 128;
    const __nv_bfloat16* W = Wall + (size_t)sel * D * D;
    __nv_bfloat16* out = io.out[sel];
    const float* bias = io.bias[sel];
    const float os = io.oscale[sel];

    gemm_body(A, W, n0, m0, gsm,
              [&](int row, int col, float vx, float vy) {
                  float2 bv = *(const float2*)(bias + col);
                  *(uint32_t*)(out + (size_t)row * D + col) =
                      packbf((vx + bv.x) * os, (vy + bv.y) * os);
              });
}

// Output projection with residual, fp32 out.
__global__ __launch_bounds__(128, 2) void out_gemm(
    const __nv_bfloat16* __restrict__ A, const __nv_bfloat16* __restrict__ W,
    const float* __restrict__ bias, const float* __restrict__ R,
    float* __restrict__ C)
{
    extern __shared__ __nv_bfloat16 gsm[];
    const int m0 = blockIdx.x * 128;
    const int n0 = blockIdx.y * 128;

    gemm_body(A, W, n0, m0, gsm,
              [&](int row, int col, float vx, float vy) {
                  float2 bv = *(const float2*)(bias + col);
                  float2 rv = *(const float2*)(R + (size_t)row * D + col);
                  float2 o;
                  o.x = vx + bv.x + rv.x;
                  o.y = vy + bv.y + rv.y;
                  *(float2*)(C + (size_t)row * D + col) = o;
              });
}

// ======================= bf16 mma flash attention ===========================
// Block: 128 q rows, 8 warps x 16 rows, 256 threads, 2 CTAs/SM.
// Q pre-scaled to log2 domain; all-ones-mask fast path; no-max-update vote.
constexpr int AST = 72;
constexpr int AQ_E = 0;
constexpr int AK_E = 128 * AST;
constexpr int AV_E = AK_E + 3 * 64 * AST;
constexpr int AEND_E = AV_E + 3 * 64 * AST;
constexpr int AM_BYTE = AEND_E * 2;
constexpr int ATT_SMEM = AM_BYTE + 3 * 64 * 4;  // ~74.5 KB
constexpr int KSTG = 64 * AST;
constexpr uint32_t SROT = KSTG * 2;

__global__ __launch_bounds__(256, 2) void attn_mma(
    const __nv_bfloat16* __restrict__ Q, const __nv_bfloat16* __restrict__ K,
    const __nv_bfloat16* __restrict__ V, const int* __restrict__ mask,
    __nv_bfloat16* __restrict__ O)
{
    extern __shared__ __nv_bfloat16 smb[];
    int* ms = (int*)((char*)smb + AM_BYTE);
    const int tid = threadIdx.x, lane = tid & 31, wid = tid >> 5;
    const int b = blockIdx.z, h = blockIdx.y, q0 = blockIdx.x * 128;
    const uint32_t sb = smem_u32(smb);
    const int lrow = lane & 15;
    const int lcol8 = (lane >> 4) * 8;
    const int lrow_t = (lane & 7) + ((lane >> 4) << 3);
    const int dsel = ((lane >> 3) & 1) * 8;
    const int g = lane >> 2, cc = lane & 3;
    const int qb = wid * 16;
    const float mneg2 = -1.44269504e9f;   // -1e9 * log2(e)

    // Q tile (128 x 64 bf16) via cp.async — first commit group
#pragma unroll
    for (int i = 0; i < 4; i++) {
        const int idx = tid + i * 256;
        const int row = idx >> 3, c8 = (idx & 7) * 8;
        cp_async16(sb + (AQ_E + row * AST + c8) * 2,
                   Q + (size_t)(b * S + q0 + row) * D + h * HD + c8);
    }
    cp_commit();

    auto issueKV = [&](int k0, int stage) {
#pragma unroll
        for (int j = 0; j < 2; j++) {
            const int idx = tid + j * 256;
            const int row = idx >> 3, c8 = (idx & 7) * 8;
            cp_async16(sb + ((AK_E + stage * KSTG) + row * AST + c8) * 2,
                       K + (size_t)(b * S + k0 + row) * D + h * HD + c8);
            cp_async16(sb + ((AV_E + stage * KSTG) + row * AST + c8) * 2,
                       V + (size_t)(b * S + k0 + row) * D + h * HD + c8);
        }
        if (tid < 16)
            cp_async16(sb + AM_BYTE + stage * 256 + tid * 16,
                       mask + b * S + k0 + tid * 4);
        cp_commit();
    };

    issueKV(0, 0);
    issueKV(64, 1);

    // Hoist Q fragments
    cp_wait<2>();
    __syncthreads();
    uint32_t aq[4][4];
#pragma unroll
    for (int k = 0; k < 4; k++) {
        const uint32_t addr =
            sb + ((AQ_E + (qb + lrow) * AST) + k * 16 + lcol8) * 2;
        ldsm4(aq[k][0], aq[k][1], aq[k][2], aq[k][3], addr);
    }

    float ob[8][4];
#pragma unroll
    for (int nt = 0; nt < 8; nt++)
#pragma unroll
        for (int q = 0; q < 4; q++) ob[nt][q] = 0.f;
    float mst[2], lst[2];
    mst[0] = mst[1] = -1e30f;
    lst[0] = lst[1] = 0.f;   // per-lane partial row sums

    uint32_t kbase = sb + (AK_E + lrow * AST + lcol8) * 2;
    uint32_t vbase = sb + (AV_E + lrow_t * AST + dsel) * 2;
    uint32_t soff = 0;
    int sidx = 0;
    int wstage = 2;

    constexpr int NT = S / 64;
    for (int t = 0; t < NT; t++) {
        if (t + 1 < NT) cp_wait<1>(); else cp_wait<0>();
        __syncthreads();
        if (t + 2 < NT) issueKV((t + 2) * 64, wstage);

        // ---- S = Q K^T (already log2-domain: Q pre-scaled) ----
        float sc[8][4];
#pragma unroll
        for (int nt = 0; nt < 8; nt++)
#pragma unroll
            for (int q = 0; q < 4; q++) sc[nt][q] = 0.f;

        const uint32_t kb = kbase + soff;
#pragma unroll
        for (int k = 0; k < 4; k++) {
            uint32_t bfr[8][2];
#pragma unroll
            for (int np = 0; np < 4; np++) {
                uint32_t b0, b1, b2, b3;
                ldsm4(b0, b1, b2, b3, kb + (np * 16 * AST + k * 16) * 2);
                bfr[np * 2 + 0][0] = b0; bfr[np * 2 + 1][0] = b1;
                bfr[np * 2 + 0][1] = b2; bfr[np * 2 + 1][1] = b3;
            }
#pragma unroll
            for (int nt = 0; nt < 8; nt++)
                mma16(sc[nt], aq[k], bfr[nt][0], bfr[nt][1]);
        }

        // ---- mask: warp-uniform all-ones fast path ----
        const int* mstg = ms + sidx * 64;
        const int okk = mstg[lane * 2] & mstg[lane * 2 + 1];
        if (!__all_sync(0xffffffffu, okk != 0)) {
#pragma unroll
            for (int nt = 0; nt < 8; nt++) {
                const int c0 = nt * 8 + cc * 2;
                const float m0v = mstg[c0] ? 0.f : mneg2;
                const float m1v = mstg[c0 + 1] ? 0.f : mneg2;
                sc[nt][0] += m0v; sc[nt][2] += m0v;
                sc[nt][1] += m1v; sc[nt][3] += m1v;
            }
        }

        // ---- online softmax (log2 domain), lane-partial sums ----
#pragma unroll
        for (int hf = 0; hf < 2; hf++) {
            float rm = -1e30f;
#pragma unroll
            for (int nt = 0; nt < 8; nt++)
                rm = fmaxf(rm, fmaxf(sc[nt][hf * 2 + 0], sc[nt][hf * 2 + 1]));
            rm = fmaxf(rm, __shfl_xor_sync(0xffffffffu, rm, 1));
            rm = fmaxf(rm, __shfl_xor_sync(0xffffffffu, rm, 2));
            const float mnew = fmaxf(mst[hf], rm);
            float rs = 0.f;
#pragma unroll
            for (int nt = 0; nt < 8; nt++) {
                float p0 = exp2f(sc[nt][hf * 2 + 0] - mnew);
                float p1 = exp2f(sc[nt][hf * 2 + 1] - mnew);
                sc[nt][hf * 2 + 0] = p0;
                sc[nt][hf * 2 + 1] = p1;
                rs += p0 + p1;
            }
            const bool noup = (mnew == mst[hf]);
            if (__all_sync(0xffffffffu, noup)) {
                lst[hf] += rs;               // cf == 1 warp-wide: skip rescale
            } else {
                const float cf = exp2f(mst[hf] - mnew);
                mst[hf] = mnew;
                lst[hf] = lst[hf] * cf + rs;
#pragma unroll
                for (int nt = 0; nt < 8; nt++) {
                    ob[nt][hf * 2 + 0] *= cf;
                    ob[nt][hf * 2 + 1] *= cf;
                }
            }
        }

        // ---- O += P V, P direct from registers ----
        const uint32_t vb = vbase + soff;
#pragma unroll
        for (int kc = 0; kc < 4; kc++) {
            uint32_t a[4], bfr[8][2];
            a[0] = packbf(sc[2 * kc][0], sc[2 * kc][1]);
            a[1] = packbf(sc[2 * kc][2], sc[2 * kc][3]);
            a[2] = packbf(sc[2 * kc + 1][0], sc[2 * kc + 1][1]);
            a[3] = packbf(sc[2 * kc + 1][2], sc[2 * kc + 1][3]);
#pragma unroll
            for (int np = 0; np < 4; np++) {
                uint32_t b0, b1, b2, b3;
                ldsm4t(b0, b1, b2, b3, vb + (kc * 16 * AST + np * 16) * 2);
                bfr[np * 2 + 0][0] = b0; bfr[np * 2 + 1][0] = b1;
                bfr[np * 2 + 0][1] = b2; bfr[np * 2 + 1][1] = b3;
            }
#pragma unroll
            for (int nt = 0; nt < 8; nt++)
                mma16(ob[nt], a, bfr[nt][0], bfr[nt][1]);
        }

        soff += SROT; if (soff == 3 * SROT) soff = 0;
        sidx = (sidx == 2) ? 0 : sidx + 1;
        wstage = (wstage == 2) ? 0 : wstage + 1;
    }

    // epilogue: reduce lane-partial sums, then O = ob / l
#pragma unroll
    for (int hf = 0; hf < 2; hf++) {
        float lt = lst[hf];
        lt += __shfl_xor_sync(0xffffffffu, lt, 1);
        lt += __shfl_xor_sync(0xffffffffu, lt, 2);
        const float inv = 1.0f / lt;
        const int row = q0 + qb + g + hf * 8;
#pragma unroll
        for (int nt = 0; nt < 8; nt++) {
            const int col = h * HD + nt * 8 + cc * 2;
            *(uint32_t*)(O + (size_t)(b * S + row) * D + col) =
                packbf(ob[nt][hf * 2 + 0] * inv, ob[nt][hf * 2 + 1] * inv);
        }
    }
}

// ---------------- LayerNorm: warp per row, shuffle reduce --------------------
__global__ __launch_bounds__(256) void ln_kernel(
    const float* __restrict__ Y, const float* __restrict__ gamma,
    const float* __restrict__ beta, float* __restrict__ out)
{
    const int lane = threadIdx.x & 31, wid = threadIdx.x >> 5;
    const int row = blockIdx.x * 8 + wid;
    const float* y = Y + (size_t)row * D;

    float s = 0.f, s2 = 0.f;
    float4 v[8];
#pragma unroll
    for (int i = 0; i < 8; i++) {
        v[i] = *(const float4*)(y + lane * 4 + i * 128);
        s += v[i].x + v[i].y + v[i].z + v[i].w;
        s2 = fmaf(v[i].x, v[i].x, s2);
        s2 = fmaf(v[i].y, v[i].y, s2);
        s2 = fmaf(v[i].z, v[i].z, s2);
        s2 = fmaf(v[i].w, v[i].w, s2);
    }
#pragma unroll
    for (int o = 16; o > 0; o >>= 1) {
        s  += __shfl_xor_sync(0xffffffffu, s, o);
        s2 += __shfl_xor_sync(0xffffffffu, s2, o);
    }
    const float mu = s * (1.0f / D);
    const float var = s2 * (1.0f / D) - mu * mu;
    const float inv = rsqrtf(var + 1e-5f);

    float* o = out + (size_t)row * D;
#pragma unroll
    for (int i = 0; i < 8; i++) {
        const int c = lane * 4 + i * 128;
        float4 gv = *(const float4*)(gamma + c);
        float4 bv = *(const float4*)(beta + c);
        float4 r;
        r.x = (v[i].x - mu) * inv * gv.x + bv.x;
        r.y = (v[i].y - mu) * inv * gv.y + bv.y;
        r.z = (v[i].z - mu) * inv * gv.z + bv.z;
        r.w = (v[i].w - mu) * inv * gv.w + bv.w;
        *(float4*)(o + c) = r;
    }
}

// ---------------- launch ------------------------------------------------------
extern "C" void kernel_launch(void* const* d_in, const int* in_sizes, int n_in,
                              void* d_out, int out_size)
{
    const float* x     = (const float*)d_in[0];
    const int*   mask  = (const int*)d_in[1];
    const float* Wq    = (const float*)d_in[2];
    const float* bq    = (const float*)d_in[3];
    const float* Wk    = (const float*)d_in[4];
    const float* bk    = (const float*)d_in[5];
    const float* Wv    = (const float*)d_in[6];
    const float* bv    = (const float*)d_in[7];
    const float* Wo    = (const float*)d_in[8];
    const float* bo    = (const float*)d_in[9];
    const float* gamma = (const float*)d_in[10];
    const float* beta  = (const float*)d_in[11];

    __nv_bfloat16 *Xb, *Wb, *Qb, *Kb, *Vb, *Cb;
    float* Yp;
    cudaGetSymbolAddress((void**)&Xb, g_Xb);
    cudaGetSymbolAddress((void**)&Wb, g_Wb);
    cudaGetSymbolAddress((void**)&Qb, g_Qb);
    cudaGetSymbolAddress((void**)&Kb, g_Kb);
    cudaGetSymbolAddress((void**)&Vb, g_Vb);
    cudaGetSymbolAddress((void**)&Cb, g_Cb);
    cudaGetSymbolAddress((void**)&Yp, g_Y);

    cudaFuncSetAttribute(qkv_gemm,
                         cudaFuncAttributeMaxDynamicSharedMemorySize, GEMM_SMEM);
    cudaFuncSetAttribute(out_gemm,
                         cudaFuncAttributeMaxDynamicSharedMemorySize, GEMM_SMEM);
    cudaFuncSetAttribute(attn_mma,
                         cudaFuncAttributeMaxDynamicSharedMemorySize, ATT_SMEM);

    const int nX4 = NR * D / 4, nW4 = D * D / 4;
    cvt_bf16<<<nX4 / 256, 256>>>(x, Xb, nX4);
    WPtrs ws;
    ws.w[0] = Wq; ws.w[1] = Wk; ws.w[2] = Wv; ws.w[3] = Wo;
    cvt_w4<<<dim3(nW4 / 256, 4), 256>>>(ws, Wb);

    QKVOut io;
    io.out[0] = Qb; io.out[1] = Kb; io.out[2] = Vb;
    io.bias[0] = bq; io.bias[1] = bk; io.bias[2] = bv;
    io.oscale[0] = 0.125f * 1.44269504f;   // fold softmax scale+log2e into Q
    io.oscale[1] = 1.0f;
    io.oscale[2] = 1.0f;
    qkv_gemm<<<dim3(24, NR / 128), 128, GEMM_SMEM>>>(Xb, Wb, io);

    attn_mma<<<dim3(S / 128, H, B), 256, ATT_SMEM>>>(Qb, Kb, Vb, mask, Cb);

    out_gemm<<<dim3(8, NR / 128), 128, GEMM_SMEM>>>(
        Cb, Wb + (size_t)3 * D * D, bo, x, Yp);
    ln_kernel<<<NR / 8, 256>>>(Yp, gamma, beta, (float*)d_out);
}